// round 2
// baseline (speedup 1.0000x reference)
#include <cuda_runtime.h>
#include <math_constants.h>

// Problem constants
#define D_MODEL 1024
#define NHEAD   16
#define DK      64
#define BSZ     8
#define SEQL    1024
#define MROWS   (BSZ * SEQL)   // 8192

// ---------------------------------------------------------------------------
// Scratch (allocation-free: __device__ globals)
// qh/kh/vh: [B, H, S, DK] ; cc: [B, S, D_MODEL] (concat of heads)
// ---------------------------------------------------------------------------
__device__ float g_qh[(size_t)BSZ * NHEAD * SEQL * DK];
__device__ float g_kh[(size_t)BSZ * NHEAD * SEQL * DK];
__device__ float g_vh[(size_t)BSZ * NHEAD * SEQL * DK];
__device__ float g_cc[(size_t)MROWS * D_MODEL];

// ---------------------------------------------------------------------------
// SGEMM: C[M=8192, N=1024] = X[8192,1024] * W[1024,1024] + bias
// 128x128 block tile, K-panel 8, 256 threads, 8x8 per thread (2x2 of 4x4).
// Double-buffered smem: one __syncthreads per K-panel.
// scatter==1: write to head-split layout [B,H,S,DK]; else row-major [M,N].
// ---------------------------------------------------------------------------
__global__ __launch_bounds__(256, 2) void sgemm_bias_kernel(
    const float* __restrict__ X, const float* __restrict__ W,
    const float* __restrict__ bias, float* __restrict__ out, int scatter)
{
    __shared__ float As[2][8][132];  // As[buf][k][m]
    __shared__ float Bs[2][8][132];  // Bs[buf][k][n]

    const int tid = threadIdx.x;
    const int tx  = tid & 15;
    const int ty  = tid >> 4;
    const int mBase = blockIdx.y * 128;
    const int nBase = blockIdx.x * 128;

    const int aRow = tid >> 1;        // 0..127
    const int aCol = (tid & 1) << 2;  // 0 or 4
    const int bRow = tid >> 5;        // 0..7
    const int bCol = (tid & 31) << 2; // 0..124

    const float* Ap = X + (size_t)(mBase + aRow) * D_MODEL + aCol;
    const float* Bp = W + (size_t)bRow * D_MODEL + nBase + bCol;

    float acc[8][8];
#pragma unroll
    for (int i = 0; i < 8; i++)
#pragma unroll
        for (int j = 0; j < 8; j++) acc[i][j] = 0.0f;

    // prologue: panel 0 -> buffer 0
    {
        float4 a = *(const float4*)(Ap);
        float4 b = *(const float4*)(Bp);
        As[0][aCol + 0][aRow] = a.x;
        As[0][aCol + 1][aRow] = a.y;
        As[0][aCol + 2][aRow] = a.z;
        As[0][aCol + 3][aRow] = a.w;
        *(float4*)&Bs[0][bRow][bCol] = b;
    }
    __syncthreads();

    for (int k0 = 0; k0 < D_MODEL; k0 += 8) {
        const int cur = (k0 >> 3) & 1;
        const int nxt = cur ^ 1;
        const bool more = (k0 + 8) < D_MODEL;

        float4 a, b;
        if (more) {
            a = *(const float4*)(Ap + (k0 + 8));
            b = *(const float4*)(Bp + (size_t)(k0 + 8) * D_MODEL);
        }

#pragma unroll
        for (int kk = 0; kk < 8; kk++) {
            float ar[8], br[8];
            *(float4*)&ar[0] = *(float4*)&As[cur][kk][ty * 4];
            *(float4*)&ar[4] = *(float4*)&As[cur][kk][64 + ty * 4];
            *(float4*)&br[0] = *(float4*)&Bs[cur][kk][tx * 4];
            *(float4*)&br[4] = *(float4*)&Bs[cur][kk][64 + tx * 4];
#pragma unroll
            for (int i = 0; i < 8; i++)
#pragma unroll
                for (int j = 0; j < 8; j++)
                    acc[i][j] = fmaf(ar[i], br[j], acc[i][j]);
        }

        if (more) {
            // buffer `nxt` was last READ in iteration k0-8; the __syncthreads
            // at the end of that iteration makes these stores safe.
            As[nxt][aCol + 0][aRow] = a.x;
            As[nxt][aCol + 1][aRow] = a.y;
            As[nxt][aCol + 2][aRow] = a.z;
            As[nxt][aCol + 3][aRow] = a.w;
            *(float4*)&Bs[nxt][bRow][bCol] = b;
            __syncthreads();
        }
    }

    float bcol[8];
    *(float4*)&bcol[0] = *(const float4*)&bias[nBase + tx * 4];
    *(float4*)&bcol[4] = *(const float4*)&bias[nBase + 64 + tx * 4];

#pragma unroll
    for (int ih = 0; ih < 2; ih++) {
#pragma unroll
        for (int i = 0; i < 4; i++) {
            const int m = mBase + ih * 64 + ty * 4 + i;
#pragma unroll
            for (int jh = 0; jh < 2; jh++) {
                const int n = nBase + jh * 64 + tx * 4;
                float4 o;
                o.x = acc[ih * 4 + i][jh * 4 + 0] + bcol[jh * 4 + 0];
                o.y = acc[ih * 4 + i][jh * 4 + 1] + bcol[jh * 4 + 1];
                o.z = acc[ih * 4 + i][jh * 4 + 2] + bcol[jh * 4 + 2];
                o.w = acc[ih * 4 + i][jh * 4 + 3] + bcol[jh * 4 + 3];
                if (scatter) {
                    const int bb = m >> 10;        // batch
                    const int s  = m & 1023;       // seq pos
                    const int h  = n >> 6;         // head
                    const int d  = n & 63;         // dk offset (mult of 4)
                    *(float4*)&out[(((size_t)(bb * NHEAD + h) * SEQL + s) * DK) + d] = o;
                } else {
                    *(float4*)&out[(size_t)m * D_MODEL + n] = o;
                }
            }
        }
    }
}

// ---------------------------------------------------------------------------
// Flash attention: one CTA per (b, h, 64-row q tile). 256 threads as 16x16.
// Thread (ty,tx) owns S/acc micro-tile rows ty*4..+3, cols tx*4..+3.
// Smem: Qs[d][r], Ks[d][c], Vs[k][d], Ps[k][r], each [64][68] floats.
// ---------------------------------------------------------------------------
#define SPAD 68

__global__ __launch_bounds__(256, 2) void attn_kernel(const int* __restrict__ mask)
{
    extern __shared__ float sm[];
    float* Qs = sm;                  // [64][SPAD]  Q transposed: Qs[d*SPAD + r]
    float* Ks = Qs + 64 * SPAD;      // [64][SPAD]  K transposed: Ks[d*SPAD + c]
    float* Vs = Ks + 64 * SPAD;      // [64][SPAD]  V natural:    Vs[k*SPAD + d]
    float* Ps = Vs + 64 * SPAD;      // [64][SPAD]  P transposed: Ps[k*SPAD + r]

    const int tid = threadIdx.x;
    const int tx  = tid & 15;
    const int ty  = tid >> 4;
    const int qt  = blockIdx.x;  // q tile 0..15
    const int h   = blockIdx.y;  // head 0..15
    const int b   = blockIdx.z;  // batch 0..7

    const size_t headOff = (size_t)(b * NHEAD + h) * SEQL * DK;
    const float* Qg = g_qh + headOff + (size_t)qt * 64 * DK;
    const float* Kg = g_kh + headOff;
    const float* Vg = g_vh + headOff;

    // load Q tile transposed (once)
    {
        const int r  = tid >> 2;          // 0..63
        const int d0 = (tid & 3) << 4;    // 0,16,32,48
        const float* src = Qg + (size_t)r * DK + d0;
#pragma unroll
        for (int i = 0; i < 4; i++) {
            float4 a = *(const float4*)(src + i * 4);
            const int d = d0 + i * 4;
            Qs[(d + 0) * SPAD + r] = a.x;
            Qs[(d + 1) * SPAD + r] = a.y;
            Qs[(d + 2) * SPAD + r] = a.z;
            Qs[(d + 3) * SPAD + r] = a.w;
        }
    }

    float m_i[4], l_i[4], acc[4][4];
#pragma unroll
    for (int i = 0; i < 4; i++) {
        m_i[i] = -CUDART_INF_F;
        l_i[i] = 0.0f;
#pragma unroll
        for (int j = 0; j < 4; j++) acc[i][j] = 0.0f;
    }

    const int qRow0 = qt * 64 + ty * 4;
    const int* mbase = mask + ((size_t)b * SEQL) * SEQL + tx * 4;

    for (int kt = 0; kt < SEQL; kt += 64) {
        __syncthreads();  // protect Ks/Vs/Ps from previous iteration's readers
        // load K (transposed) and V tiles
        {
            const int r  = tid >> 2;
            const int d0 = (tid & 3) << 4;
            const float* ksrc = Kg + (size_t)(kt + r) * DK + d0;
            const float* vsrc = Vg + (size_t)(kt + r) * DK + d0;
#pragma unroll
            for (int i = 0; i < 4; i++) {
                float4 a = *(const float4*)(ksrc + i * 4);
                const int d = d0 + i * 4;
                Ks[(d + 0) * SPAD + r] = a.x;
                Ks[(d + 1) * SPAD + r] = a.y;
                Ks[(d + 2) * SPAD + r] = a.z;
                Ks[(d + 3) * SPAD + r] = a.w;
                float4 vv = *(const float4*)(vsrc + i * 4);
                *(float4*)&Vs[r * SPAD + d] = vv;
            }
        }
        __syncthreads();

        // S = Q K^T for this thread's 4x4
        float s[4][4];
#pragma unroll
        for (int i = 0; i < 4; i++)
#pragma unroll
            for (int j = 0; j < 4; j++) s[i][j] = 0.0f;

#pragma unroll 8
        for (int d = 0; d < 64; d++) {
            float4 qa = *(float4*)&Qs[d * SPAD + ty * 4];
            float4 kb = *(float4*)&Ks[d * SPAD + tx * 4];
            float qr[4] = {qa.x, qa.y, qa.z, qa.w};
            float kr[4] = {kb.x, kb.y, kb.z, kb.w};
#pragma unroll
            for (int i = 0; i < 4; i++)
#pragma unroll
                for (int j = 0; j < 4; j++)
                    s[i][j] = fmaf(qr[i], kr[j], s[i][j]);
        }

        // mask + scale + online softmax update
#pragma unroll
        for (int i = 0; i < 4; i++) {
            int4 mk = *(const int4*)(mbase + (size_t)(qRow0 + i) * SEQL + kt);
            s[i][0] = mk.x ? s[i][0] * 0.125f : -1e9f;
            s[i][1] = mk.y ? s[i][1] * 0.125f : -1e9f;
            s[i][2] = mk.z ? s[i][2] * 0.125f : -1e9f;
            s[i][3] = mk.w ? s[i][3] * 0.125f : -1e9f;

            float mx = fmaxf(fmaxf(s[i][0], s[i][1]), fmaxf(s[i][2], s[i][3]));
            mx = fmaxf(mx, __shfl_xor_sync(0xffffffffu, mx, 1));
            mx = fmaxf(mx, __shfl_xor_sync(0xffffffffu, mx, 2));
            mx = fmaxf(mx, __shfl_xor_sync(0xffffffffu, mx, 4));
            mx = fmaxf(mx, __shfl_xor_sync(0xffffffffu, mx, 8));

            const float mnew = fmaxf(m_i[i], mx);
            const float corr = __expf(m_i[i] - mnew);
            m_i[i] = mnew;

            float p0 = __expf(s[i][0] - mnew);
            float p1 = __expf(s[i][1] - mnew);
            float p2 = __expf(s[i][2] - mnew);
            float p3 = __expf(s[i][3] - mnew);

            float rs = p0 + p1 + p2 + p3;
            rs += __shfl_xor_sync(0xffffffffu, rs, 1);
            rs += __shfl_xor_sync(0xffffffffu, rs, 2);
            rs += __shfl_xor_sync(0xffffffffu, rs, 4);
            rs += __shfl_xor_sync(0xffffffffu, rs, 8);

            l_i[i] = l_i[i] * corr + rs;
#pragma unroll
            for (int j = 0; j < 4; j++) acc[i][j] *= corr;

            const int r = ty * 4 + i;
            Ps[(tx * 4 + 0) * SPAD + r] = p0;
            Ps[(tx * 4 + 1) * SPAD + r] = p1;
            Ps[(tx * 4 + 2) * SPAD + r] = p2;
            Ps[(tx * 4 + 3) * SPAD + r] = p3;
        }
        __syncthreads();

        // acc += P V
#pragma unroll 8
        for (int k = 0; k < 64; k++) {
            float4 pr = *(float4*)&Ps[k * SPAD + ty * 4];
            float4 vv = *(float4*)&Vs[k * SPAD + tx * 4];
            float pa[4] = {pr.x, pr.y, pr.z, pr.w};
            float vb[4] = {vv.x, vv.y, vv.z, vv.w};
#pragma unroll
            for (int i = 0; i < 4; i++)
#pragma unroll
                for (int j = 0; j < 4; j++)
                    acc[i][j] = fmaf(pa[i], vb[j], acc[i][j]);
        }
    }

    // epilogue: normalize and write into concat layout [B, S, H*DK]
#pragma unroll
    for (int i = 0; i < 4; i++) {
        const float inv = 1.0f / l_i[i];
        float4 o;
        o.x = acc[i][0] * inv;
        o.y = acc[i][1] * inv;
        o.z = acc[i][2] * inv;
        o.w = acc[i][3] * inv;
        const int row = qt * 64 + ty * 4 + i;
        *(float4*)&g_cc[((size_t)b * SEQL + row) * D_MODEL + h * 64 + tx * 4] = o;
    }
}

// ---------------------------------------------------------------------------
// Host launcher
// ---------------------------------------------------------------------------
extern "C" void kernel_launch(void* const* d_in, const int* in_sizes, int n_in,
                              void* d_out, int out_size)
{
    (void)in_sizes; (void)n_in; (void)out_size;

    const float* q    = (const float*)d_in[0];
    const float* k    = (const float*)d_in[1];
    const float* v    = (const float*)d_in[2];
    const int*   mask = (const int*)  d_in[3];
    const float* Wq   = (const float*)d_in[4];
    const float* bq   = (const float*)d_in[5];
    const float* Wk   = (const float*)d_in[6];
    const float* bk   = (const float*)d_in[7];
    const float* Wv   = (const float*)d_in[8];
    const float* bv   = (const float*)d_in[9];
    const float* Wo   = (const float*)d_in[10];
    const float* bo   = (const float*)d_in[11];
    float* out = (float*)d_out;

    void* p;
    cudaGetSymbolAddress(&p, g_qh); float* qh = (float*)p;
    cudaGetSymbolAddress(&p, g_kh); float* kh = (float*)p;
    cudaGetSymbolAddress(&p, g_vh); float* vh = (float*)p;
    cudaGetSymbolAddress(&p, g_cc); float* cc = (float*)p;

    const dim3 gg(D_MODEL / 128, MROWS / 128);

    sgemm_bias_kernel<<<gg, 256>>>(q, Wq, bq, qh, 1);
    sgemm_bias_kernel<<<gg, 256>>>(k, Wk, bk, kh, 1);
    sgemm_bias_kernel<<<gg, 256>>>(v, Wv, bv, vh, 1);

    const int smem_bytes = 4 * 64 * SPAD * (int)sizeof(float);  // 69632
    cudaFuncSetAttribute(attn_kernel, cudaFuncAttributeMaxDynamicSharedMemorySize,
                         smem_bytes);
    attn_kernel<<<dim3(16, 16, 8), 256, smem_bytes>>>(mask);

    sgemm_bias_kernel<<<gg, 256>>>(cc, Wo, bo, out, 0);
}

// round 4
// speedup vs baseline: 1.3477x; 1.3477x over previous
#include <cuda_runtime.h>
#include <cuda_bf16.h>
#include <math_constants.h>
#include <cstdint>

// Problem constants
#define D_MODEL 1024
#define NHEAD   16
#define DK      64
#define BSZ     8
#define SEQL    1024
#define MROWS   (BSZ * SEQL)   // 8192

// ---------------------------------------------------------------------------
// Scratch (allocation-free: __device__ globals)
// ---------------------------------------------------------------------------
__device__ float g_qh[(size_t)BSZ * NHEAD * SEQL * DK];
__device__ float g_kh[(size_t)BSZ * NHEAD * SEQL * DK];
__device__ float g_vh[(size_t)BSZ * NHEAD * SEQL * DK];
__device__ float g_cc[(size_t)MROWS * D_MODEL];
__device__ __nv_bfloat16 g_xhi[(size_t)MROWS * D_MODEL];
__device__ __nv_bfloat16 g_xlo[(size_t)MROWS * D_MODEL];
__device__ __nv_bfloat16 g_whi[(size_t)D_MODEL * D_MODEL];  // transposed [N,K]
__device__ __nv_bfloat16 g_wlo[(size_t)D_MODEL * D_MODEL];  // transposed [N,K]

// ---------------------------------------------------------------------------
// PTX helpers (standard PTX only — no tcgen05: ptxas target is plain sm_103)
// ---------------------------------------------------------------------------
__device__ __forceinline__ uint32_t smem_u32(const void* p) {
    uint32_t a;
    asm("{ .reg .u64 t; cvta.to.shared.u64 t, %1; cvt.u32.u64 %0, t; }"
        : "=r"(a) : "l"(p));
    return a;
}

#define LDSM_X4(r0, r1, r2, r3, addr) \
    asm volatile("ldmatrix.sync.aligned.m8n8.x4.shared.b16 {%0,%1,%2,%3}, [%4];" \
                 : "=r"(r0), "=r"(r1), "=r"(r2), "=r"(r3) : "r"(addr))

#define MMA_BF16(d, a, b) \
    asm volatile("mma.sync.aligned.m16n8k16.row.col.f32.bf16.bf16.f32 " \
                 "{%0,%1,%2,%3}, {%4,%5,%6,%7}, {%8,%9}, {%0,%1,%2,%3};" \
                 : "+f"((d)[0]), "+f"((d)[1]), "+f"((d)[2]), "+f"((d)[3]) \
                 : "r"((a)[0]), "r"((a)[1]), "r"((a)[2]), "r"((a)[3]), \
                   "r"((b)[0]), "r"((b)[1]))

#define STS128(addr, v) \
    asm volatile("st.shared.v4.b32 [%0], {%1,%2,%3,%4};" \
                 :: "r"(addr), "r"((v).x), "r"((v).y), "r"((v).z), "r"((v).w) \
                 : "memory")

// Swizzled smem byte offset for (row, 16B-chunk c) in a 64B-per-row tile.
// Conflict-free for both st.128 fills and ldmatrix 8x8 reads.
__device__ __forceinline__ uint32_t swz(int row, int c) {
    return (uint32_t)((row << 6) + (((c ^ (row >> 1)) & 3) << 4));
}

// ---------------------------------------------------------------------------
// fp32 -> (hi,lo) bf16 split, elementwise (row-major preserved)
// ---------------------------------------------------------------------------
__global__ void split_hilo_kernel(const float* __restrict__ x,
                                  __nv_bfloat16* __restrict__ hi,
                                  __nv_bfloat16* __restrict__ lo, int n4)
{
    int i = blockIdx.x * blockDim.x + threadIdx.x;
    if (i >= n4) return;
    float4 v = ((const float4*)x)[i];
    __nv_bfloat16 h[4], l[4];
    float f[4] = {v.x, v.y, v.z, v.w};
#pragma unroll
    for (int j = 0; j < 4; j++) {
        h[j] = __float2bfloat16_rn(f[j]);
        l[j] = __float2bfloat16_rn(f[j] - __bfloat162float(h[j]));
    }
    ((uint2*)hi)[i] = *(uint2*)h;
    ((uint2*)lo)[i] = *(uint2*)l;
}

// ---------------------------------------------------------------------------
// W [K,N] fp32 -> Wt hi/lo [N,K] bf16 (transpose + split)
// ---------------------------------------------------------------------------
__global__ void split_transpose_kernel(const float* __restrict__ W,
                                       __nv_bfloat16* __restrict__ hi,
                                       __nv_bfloat16* __restrict__ lo)
{
    __shared__ float t[32][33];
    const int kb = blockIdx.y * 32;
    const int nb = blockIdx.x * 32;
    const int tx = threadIdx.x & 31;
    const int ty = threadIdx.x >> 5;  // 0..7
#pragma unroll
    for (int j = 0; j < 4; j++)
        t[ty + 8 * j][tx] = W[(size_t)(kb + ty + 8 * j) * D_MODEL + nb + tx];
    __syncthreads();
#pragma unroll
    for (int j = 0; j < 4; j++) {
        float v = t[tx][ty + 8 * j];
        __nv_bfloat16 h = __float2bfloat16_rn(v);
        __nv_bfloat16 l = __float2bfloat16_rn(v - __bfloat162float(h));
        size_t o = (size_t)(nb + ty + 8 * j) * D_MODEL + kb + tx;
        hi[o] = h;
        lo[o] = l;
    }
}

// ---------------------------------------------------------------------------
// bf16x3-split GEMM via mma.sync (HMMA): C[8192,1024] = X*W + bias, fp32 acc.
// A = Xsplit [M,K] bf16 K-major; B = Wtsplit [N,K] bf16 K-major.
// CTA 128x128, 8 warps (4 over M x 2 over N), warp tile 32x64.
// K-chunk 32 bf16, double-buffered smem (2 x (8KB A + 8KB B) = 32KB).
// 3 passes: hi*hi + lo*hi + hi*lo.
// scatter==1: write head-split [B,H,S,DK]; else row-major [M,N].
// ---------------------------------------------------------------------------
__global__ __launch_bounds__(256, 2)
void gemm_bf16x3_kernel(const __nv_bfloat16* __restrict__ Ahi,
                        const __nv_bfloat16* __restrict__ Alo,
                        const __nv_bfloat16* __restrict__ Bhi,
                        const __nv_bfloat16* __restrict__ Blo,
                        const float* __restrict__ bias,
                        float* __restrict__ out, int scatter)
{
    __shared__ __align__(1024) char smem[32768];
    const uint32_t smem_base = smem_u32(smem);

    const int tid   = threadIdx.x;
    const int wid   = tid >> 5;
    const int lane  = tid & 31;
    const int warpM = wid & 3;   // 0..3 -> m offset *32
    const int warpN = wid >> 2;  // 0..1 -> n offset *64
    const int mBase = blockIdx.y * 128;
    const int nBase = blockIdx.x * 128;

    // ldmatrix per-thread address components
    const int j8 = lane >> 3;  // which 8x8 matrix this thread addresses
    const int r8 = lane & 7;   // row within that matrix
    const int aR = warpM * 32 + r8 + (j8 & 1) * 8;   // + mf*16
    const int aC = (j8 >> 1);                        // + 2*kk
    const int bR = warpN * 64 + r8 + (j8 >> 1) * 8;  // + nf2*16
    const int bC = (j8 & 1);                         // + 2*kk

    // global-load assignment: 2 x 16B for A, 2 x 16B for B per chunk
    const int gRow0 = tid >> 2;          // 0..63
    const int gC    = tid & 3;           // 16B chunk in 64B row

    const __nv_bfloat16* APASS[3] = {Ahi, Alo, Ahi};
    const __nv_bfloat16* BPASS[3] = {Bhi, Bhi, Blo};

    float acc[2][8][4];
#pragma unroll
    for (int mf = 0; mf < 2; mf++)
#pragma unroll
        for (int nf = 0; nf < 8; nf++)
#pragma unroll
            for (int e = 0; e < 4; e++) acc[mf][nf][e] = 0.0f;

    const int NCHUNK = 3 * (D_MODEL / 32);  // 96

    // prologue: chunk 0 -> buffer 0
    {
        const __nv_bfloat16* Ap = APASS[0];
        const __nv_bfloat16* Bp = BPASS[0];
#pragma unroll
        for (int i = 0; i < 2; i++) {
            const int row = gRow0 + i * 64;
            uint4 va = *(const uint4*)(Ap + (size_t)(mBase + row) * D_MODEL + gC * 8);
            STS128(smem_base + swz(row, gC), va);
            uint4 vb = *(const uint4*)(Bp + (size_t)(nBase + row) * D_MODEL + gC * 8);
            STS128(smem_base + 8192 + swz(row, gC), vb);
        }
    }
    __syncthreads();

    for (int it = 0; it < NCHUNK; it++) {
        const int cur = it & 1;
        const int nxt = cur ^ 1;
        const bool more = (it + 1) < NCHUNK;

        uint4 na[2], nb[2];
        if (more) {
            const int nit  = it + 1;
            const int pass = nit >> 5;
            const int k0   = (nit & 31) * 32;
            const __nv_bfloat16* Ap = APASS[pass];
            const __nv_bfloat16* Bp = BPASS[pass];
#pragma unroll
            for (int i = 0; i < 2; i++) {
                const int row = gRow0 + i * 64;
                na[i] = *(const uint4*)(Ap + (size_t)(mBase + row) * D_MODEL + k0 + gC * 8);
                nb[i] = *(const uint4*)(Bp + (size_t)(nBase + row) * D_MODEL + k0 + gC * 8);
            }
        }

        const uint32_t aBuf = smem_base + cur * 16384;
        const uint32_t bBuf = aBuf + 8192;

#pragma unroll
        for (int kk = 0; kk < 2; kk++) {
            uint32_t af[2][4];
#pragma unroll
            for (int mf = 0; mf < 2; mf++) {
                const int row = aR + mf * 16;
                LDSM_X4(af[mf][0], af[mf][1], af[mf][2], af[mf][3],
                        aBuf + swz(row, aC + 2 * kk));
            }
            uint32_t bfr[8][2];
#pragma unroll
            for (int nf2 = 0; nf2 < 4; nf2++) {
                const int row = bR + nf2 * 16;
                uint32_t r0, r1, r2, r3;
                LDSM_X4(r0, r1, r2, r3, bBuf + swz(row, bC + 2 * kk));
                bfr[2 * nf2][0] = r0; bfr[2 * nf2][1] = r1;
                bfr[2 * nf2 + 1][0] = r2; bfr[2 * nf2 + 1][1] = r3;
            }
#pragma unroll
            for (int mf = 0; mf < 2; mf++)
#pragma unroll
                for (int nf = 0; nf < 8; nf++)
                    MMA_BF16(acc[mf][nf], af[mf], bfr[nf]);
        }

        if (more) {
            const uint32_t aB2 = smem_base + nxt * 16384;
#pragma unroll
            for (int i = 0; i < 2; i++) {
                const int row = gRow0 + i * 64;
                STS128(aB2 + swz(row, gC), na[i]);
                STS128(aB2 + 8192 + swz(row, gC), nb[i]);
            }
            __syncthreads();
        }
    }

    // epilogue: bias add + store (float2 per fragment row)
#pragma unroll
    for (int mf = 0; mf < 2; mf++) {
#pragma unroll
        for (int nf = 0; nf < 8; nf++) {
            const int col = nBase + warpN * 64 + nf * 8 + (lane & 3) * 2;
            const float b0 = bias[col];
            const float b1 = bias[col + 1];
#pragma unroll
            for (int half = 0; half < 2; half++) {
                const int m = mBase + warpM * 32 + mf * 16 + (lane >> 2) + half * 8;
                float2 o;
                o.x = acc[mf][nf][half * 2 + 0] + b0;
                o.y = acc[mf][nf][half * 2 + 1] + b1;
                if (scatter) {
                    const int bb = m >> 10;
                    const int s  = m & 1023;
                    const int h  = col >> 6;
                    const int d  = col & 63;
                    *(float2*)&out[(((size_t)(bb * NHEAD + h) * SEQL + s) * DK) + d] = o;
                } else {
                    *(float2*)&out[(size_t)m * D_MODEL + col] = o;
                }
            }
        }
    }
}

// ---------------------------------------------------------------------------
// Flash attention: one CTA per (b, h, 64-row q tile). 256 threads as 16x16.
// (unchanged from R2 passing baseline; next optimization target)
// ---------------------------------------------------------------------------
#define SPAD 68

__global__ __launch_bounds__(256, 2) void attn_kernel(const int* __restrict__ mask)
{
    extern __shared__ float sm[];
    float* Qs = sm;
    float* Ks = Qs + 64 * SPAD;
    float* Vs = Ks + 64 * SPAD;
    float* Ps = Vs + 64 * SPAD;

    const int tid = threadIdx.x;
    const int tx  = tid & 15;
    const int ty  = tid >> 4;
    const int qt  = blockIdx.x;
    const int h   = blockIdx.y;
    const int b   = blockIdx.z;

    const size_t headOff = (size_t)(b * NHEAD + h) * SEQL * DK;
    const float* Qg = g_qh + headOff + (size_t)qt * 64 * DK;
    const float* Kg = g_kh + headOff;
    const float* Vg = g_vh + headOff;

    {
        const int r  = tid >> 2;
        const int d0 = (tid & 3) << 4;
        const float* src = Qg + (size_t)r * DK + d0;
#pragma unroll
        for (int i = 0; i < 4; i++) {
            float4 a = *(const float4*)(src + i * 4);
            const int d = d0 + i * 4;
            Qs[(d + 0) * SPAD + r] = a.x;
            Qs[(d + 1) * SPAD + r] = a.y;
            Qs[(d + 2) * SPAD + r] = a.z;
            Qs[(d + 3) * SPAD + r] = a.w;
        }
    }

    float m_i[4], l_i[4], acc[4][4];
#pragma unroll
    for (int i = 0; i < 4; i++) {
        m_i[i] = -CUDART_INF_F;
        l_i[i] = 0.0f;
#pragma unroll
        for (int j = 0; j < 4; j++) acc[i][j] = 0.0f;
    }

    const int qRow0 = qt * 64 + ty * 4;
    const int* mbase = mask + ((size_t)b * SEQL) * SEQL + tx * 4;

    for (int kt = 0; kt < SEQL; kt += 64) {
        __syncthreads();
        {
            const int r  = tid >> 2;
            const int d0 = (tid & 3) << 4;
            const float* ksrc = Kg + (size_t)(kt + r) * DK + d0;
            const float* vsrc = Vg + (size_t)(kt + r) * DK + d0;
#pragma unroll
            for (int i = 0; i < 4; i++) {
                float4 a = *(const float4*)(ksrc + i * 4);
                const int d = d0 + i * 4;
                Ks[(d + 0) * SPAD + r] = a.x;
                Ks[(d + 1) * SPAD + r] = a.y;
                Ks[(d + 2) * SPAD + r] = a.z;
                Ks[(d + 3) * SPAD + r] = a.w;
                float4 vv = *(const float4*)(vsrc + i * 4);
                *(float4*)&Vs[r * SPAD + d] = vv;
            }
        }
        __syncthreads();

        float s[4][4];
#pragma unroll
        for (int i = 0; i < 4; i++)
#pragma unroll
            for (int j = 0; j < 4; j++) s[i][j] = 0.0f;

#pragma unroll 8
        for (int d = 0; d < 64; d++) {
            float4 qa = *(float4*)&Qs[d * SPAD + ty * 4];
            float4 kb = *(float4*)&Ks[d * SPAD + tx * 4];
            float qr[4] = {qa.x, qa.y, qa.z, qa.w};
            float kr[4] = {kb.x, kb.y, kb.z, kb.w};
#pragma unroll
            for (int i = 0; i < 4; i++)
#pragma unroll
                for (int j = 0; j < 4; j++)
                    s[i][j] = fmaf(qr[i], kr[j], s[i][j]);
        }

#pragma unroll
        for (int i = 0; i < 4; i++) {
            int4 mk = *(const int4*)(mbase + (size_t)(qRow0 + i) * SEQL + kt);
            s[i][0] = mk.x ? s[i][0] * 0.125f : -1e9f;
            s[i][1] = mk.y ? s[i][1] * 0.125f : -1e9f;
            s[i][2] = mk.z ? s[i][2] * 0.125f : -1e9f;
            s[i][3] = mk.w ? s[i][3] * 0.125f : -1e9f;

            float mx = fmaxf(fmaxf(s[i][0], s[i][1]), fmaxf(s[i][2], s[i][3]));
            mx = fmaxf(mx, __shfl_xor_sync(0xffffffffu, mx, 1));
            mx = fmaxf(mx, __shfl_xor_sync(0xffffffffu, mx, 2));
            mx = fmaxf(mx, __shfl_xor_sync(0xffffffffu, mx, 4));
            mx = fmaxf(mx, __shfl_xor_sync(0xffffffffu, mx, 8));

            const float mnew = fmaxf(m_i[i], mx);
            const float corr = __expf(m_i[i] - mnew);
            m_i[i] = mnew;

            float p0 = __expf(s[i][0] - mnew);
            float p1 = __expf(s[i][1] - mnew);
            float p2 = __expf(s[i][2] - mnew);
            float p3 = __expf(s[i][3] - mnew);

            float rs = p0 + p1 + p2 + p3;
            rs += __shfl_xor_sync(0xffffffffu, rs, 1);
            rs += __shfl_xor_sync(0xffffffffu, rs, 2);
            rs += __shfl_xor_sync(0xffffffffu, rs, 4);
            rs += __shfl_xor_sync(0xffffffffu, rs, 8);

            l_i[i] = l_i[i] * corr + rs;
#pragma unroll
            for (int j = 0; j < 4; j++) acc[i][j] *= corr;

            const int r = ty * 4 + i;
            Ps[(tx * 4 + 0) * SPAD + r] = p0;
            Ps[(tx * 4 + 1) * SPAD + r] = p1;
            Ps[(tx * 4 + 2) * SPAD + r] = p2;
            Ps[(tx * 4 + 3) * SPAD + r] = p3;
        }
        __syncthreads();

#pragma unroll 8
        for (int k = 0; k < 64; k++) {
            float4 pr = *(float4*)&Ps[k * SPAD + ty * 4];
            float4 vv = *(float4*)&Vs[k * SPAD + tx * 4];
            float pa[4] = {pr.x, pr.y, pr.z, pr.w};
            float vb[4] = {vv.x, vv.y, vv.z, vv.w};
#pragma unroll
            for (int i = 0; i < 4; i++)
#pragma unroll
                for (int j = 0; j < 4; j++)
                    acc[i][j] = fmaf(pa[i], vb[j], acc[i][j]);
        }
    }

#pragma unroll
    for (int i = 0; i < 4; i++) {
        const float inv = 1.0f / l_i[i];
        float4 o;
        o.x = acc[i][0] * inv;
        o.y = acc[i][1] * inv;
        o.z = acc[i][2] * inv;
        o.w = acc[i][3] * inv;
        const int row = qt * 64 + ty * 4 + i;
        *(float4*)&g_cc[((size_t)b * SEQL + row) * D_MODEL + h * 64 + tx * 4] = o;
    }
}

// ---------------------------------------------------------------------------
// Host launcher
// ---------------------------------------------------------------------------
extern "C" void kernel_launch(void* const* d_in, const int* in_sizes, int n_in,
                              void* d_out, int out_size)
{
    (void)in_sizes; (void)n_in; (void)out_size;

    const float* q    = (const float*)d_in[0];
    const float* k    = (const float*)d_in[1];
    const float* v    = (const float*)d_in[2];
    const int*   mask = (const int*)  d_in[3];
    const float* Wq   = (const float*)d_in[4];
    const float* bq   = (const float*)d_in[5];
    const float* Wk   = (const float*)d_in[6];
    const float* bk   = (const float*)d_in[7];
    const float* Wv   = (const float*)d_in[8];
    const float* bv   = (const float*)d_in[9];
    const float* Wo   = (const float*)d_in[10];
    const float* bo   = (const float*)d_in[11];
    float* out = (float*)d_out;

    void* p;
    cudaGetSymbolAddress(&p, g_qh);  float* qh = (float*)p;
    cudaGetSymbolAddress(&p, g_kh);  float* kh = (float*)p;
    cudaGetSymbolAddress(&p, g_vh);  float* vh = (float*)p;
    cudaGetSymbolAddress(&p, g_cc);  float* cc = (float*)p;
    cudaGetSymbolAddress(&p, g_xhi); __nv_bfloat16* xhi = (__nv_bfloat16*)p;
    cudaGetSymbolAddress(&p, g_xlo); __nv_bfloat16* xlo = (__nv_bfloat16*)p;
    cudaGetSymbolAddress(&p, g_whi); __nv_bfloat16* whi = (__nv_bfloat16*)p;
    cudaGetSymbolAddress(&p, g_wlo); __nv_bfloat16* wlo = (__nv_bfloat16*)p;

    const int attn_smem = 4 * 64 * SPAD * (int)sizeof(float);
    cudaFuncSetAttribute(attn_kernel,
                         cudaFuncAttributeMaxDynamicSharedMemorySize, attn_smem);

    const int n4 = MROWS * D_MODEL / 4;
    const dim3 ggemm(D_MODEL / 128, MROWS / 128);   // (8, 64)
    const dim3 gtr(D_MODEL / 32, D_MODEL / 32);     // (32, 32)

    // Q projection
    split_hilo_kernel<<<(n4 + 255) / 256, 256>>>(q, xhi, xlo, n4);
    split_transpose_kernel<<<gtr, 256>>>(Wq, whi, wlo);
    gemm_bf16x3_kernel<<<ggemm, 256>>>(xhi, xlo, whi, wlo, bq, qh, 1);
    // K projection
    split_hilo_kernel<<<(n4 + 255) / 256, 256>>>(k, xhi, xlo, n4);
    split_transpose_kernel<<<gtr, 256>>>(Wk, whi, wlo);
    gemm_bf16x3_kernel<<<ggemm, 256>>>(xhi, xlo, whi, wlo, bk, kh, 1);
    // V projection
    split_hilo_kernel<<<(n4 + 255) / 256, 256>>>(v, xhi, xlo, n4);
    split_transpose_kernel<<<gtr, 256>>>(Wv, whi, wlo);
    gemm_bf16x3_kernel<<<ggemm, 256>>>(xhi, xlo, whi, wlo, bv, vh, 1);

    // Attention
    attn_kernel<<<dim3(16, 16, 8), 256, attn_smem>>>(mask);

    // Output projection
    split_hilo_kernel<<<(n4 + 255) / 256, 256>>>(cc, xhi, xlo, n4);
    split_transpose_kernel<<<gtr, 256>>>(Wo, whi, wlo);
    gemm_bf16x3_kernel<<<ggemm, 256>>>(xhi, xlo, whi, wlo, bo, out, 0);
}

// round 6
// speedup vs baseline: 2.2718x; 1.6857x over previous
#include <cuda_runtime.h>
#include <cuda_bf16.h>
#include <math_constants.h>
#include <cstdint>

// Problem constants
#define D_MODEL 1024
#define NHEAD   16
#define DK      64
#define BSZ     8
#define SEQL    1024
#define MROWS   (BSZ * SEQL)   // 8192

// ---------------------------------------------------------------------------
// Scratch (allocation-free: __device__ globals)
// ---------------------------------------------------------------------------
__device__ __align__(16) __nv_bfloat16 g_qhi[(size_t)BSZ * NHEAD * SEQL * DK];
__device__ __align__(16) __nv_bfloat16 g_qlo[(size_t)BSZ * NHEAD * SEQL * DK];
__device__ __align__(16) __nv_bfloat16 g_khi[(size_t)BSZ * NHEAD * SEQL * DK];
__device__ __align__(16) __nv_bfloat16 g_klo[(size_t)BSZ * NHEAD * SEQL * DK];
__device__ __align__(16) __nv_bfloat16 g_vhi[(size_t)BSZ * NHEAD * SEQL * DK];
__device__ __align__(16) __nv_bfloat16 g_vlo[(size_t)BSZ * NHEAD * SEQL * DK];
__device__ __align__(16) __nv_bfloat16 g_xhi[(size_t)MROWS * D_MODEL];
__device__ __align__(16) __nv_bfloat16 g_xlo[(size_t)MROWS * D_MODEL];
__device__ __align__(16) __nv_bfloat16 g_whi[(size_t)D_MODEL * D_MODEL];  // [N,K]
__device__ __align__(16) __nv_bfloat16 g_wlo[(size_t)D_MODEL * D_MODEL];  // [N,K]
__device__ __align__(16) uint32_t g_pk[(size_t)BSZ * SEQL * (SEQL / 32)]; // packed mask

// ---------------------------------------------------------------------------
// PTX helpers (standard PTX only — tcgen05 is rejected by the sm_103 target)
// ---------------------------------------------------------------------------
__device__ __forceinline__ uint32_t smem_u32(const void* p) {
    uint32_t a;
    asm("{ .reg .u64 t; cvta.to.shared.u64 t, %1; cvt.u32.u64 %0, t; }"
        : "=r"(a) : "l"(p));
    return a;
}

#define LDSM_X4(r0, r1, r2, r3, addr) \
    asm volatile("ldmatrix.sync.aligned.m8n8.x4.shared.b16 {%0,%1,%2,%3}, [%4];" \
                 : "=r"(r0), "=r"(r1), "=r"(r2), "=r"(r3) : "r"(addr))

#define LDSM_X4T(r0, r1, r2, r3, addr) \
    asm volatile("ldmatrix.sync.aligned.m8n8.x4.trans.shared.b16 {%0,%1,%2,%3}, [%4];" \
                 : "=r"(r0), "=r"(r1), "=r"(r2), "=r"(r3) : "r"(addr))

#define MMA_BF16(d, a, b) \
    asm volatile("mma.sync.aligned.m16n8k16.row.col.f32.bf16.bf16.f32 " \
                 "{%0,%1,%2,%3}, {%4,%5,%6,%7}, {%8,%9}, {%0,%1,%2,%3};" \
                 : "+f"((d)[0]), "+f"((d)[1]), "+f"((d)[2]), "+f"((d)[3]) \
                 : "r"((a)[0]), "r"((a)[1]), "r"((a)[2]), "r"((a)[3]), \
                   "r"((b)[0]), "r"((b)[1]))

#define STS128(addr, v) \
    asm volatile("st.shared.v4.b32 [%0], {%1,%2,%3,%4};" \
                 :: "r"(addr), "r"((v).x), "r"((v).y), "r"((v).z), "r"((v).w) \
                 : "memory")

#define CP16(smem_addr, gptr) \
    asm volatile("cp.async.cg.shared.global [%0], [%1], 16;" \
                 :: "r"(smem_addr), "l"(gptr) : "memory")
#define CP_COMMIT() asm volatile("cp.async.commit_group;" ::: "memory")

// 64B-row swizzle (GEMM tiles)
__device__ __forceinline__ uint32_t swz(int row, int c) {
    return (uint32_t)((row << 6) + (((c ^ (row >> 1)) & 3) << 4));
}
// SW128 swizzle for 128B rows (attention tiles)
__device__ __forceinline__ uint32_t sw128(uint32_t off) {
    return off ^ ((off >> 3) & 0x70);
}

__device__ __forceinline__ uint32_t pack_bf16x2(__nv_bfloat16 lo16, __nv_bfloat16 hi16) {
    return ((uint32_t)*(const uint16_t*)&hi16 << 16) | *(const uint16_t*)&lo16;
}

// split fp32 pair into bf16 hi / lo pairs and store as packed u32
__device__ __forceinline__ void store_hilo2(__nv_bfloat16* hi, __nv_bfloat16* lo,
                                            float a, float b) {
    __nv_bfloat16 ha = __float2bfloat16_rn(a), hb = __float2bfloat16_rn(b);
    *(uint32_t*)hi = pack_bf16x2(ha, hb);
    __nv_bfloat16 la = __float2bfloat16_rn(a - __bfloat162float(ha));
    __nv_bfloat16 lb = __float2bfloat16_rn(b - __bfloat162float(hb));
    *(uint32_t*)lo = pack_bf16x2(la, lb);
}

// ---------------------------------------------------------------------------
// fp32 -> (hi,lo) bf16 split, elementwise
// ---------------------------------------------------------------------------
__global__ void split_hilo_kernel(const float* __restrict__ x,
                                  __nv_bfloat16* __restrict__ hi,
                                  __nv_bfloat16* __restrict__ lo, int n4)
{
    int i = blockIdx.x * blockDim.x + threadIdx.x;
    if (i >= n4) return;
    float4 v = ((const float4*)x)[i];
    __nv_bfloat16 h[4], l[4];
    float f[4] = {v.x, v.y, v.z, v.w};
#pragma unroll
    for (int j = 0; j < 4; j++) {
        h[j] = __float2bfloat16_rn(f[j]);
        l[j] = __float2bfloat16_rn(f[j] - __bfloat162float(h[j]));
    }
    ((uint2*)hi)[i] = *(uint2*)h;
    ((uint2*)lo)[i] = *(uint2*)l;
}

// ---------------------------------------------------------------------------
// W [K,N] fp32 -> Wt hi/lo [N,K] bf16 (transpose + split)
// ---------------------------------------------------------------------------
__global__ void split_transpose_kernel(const float* __restrict__ W,
                                       __nv_bfloat16* __restrict__ hi,
                                       __nv_bfloat16* __restrict__ lo)
{
    __shared__ float t[32][33];
    const int kb = blockIdx.y * 32;
    const int nb = blockIdx.x * 32;
    const int tx = threadIdx.x & 31;
    const int ty = threadIdx.x >> 5;
#pragma unroll
    for (int j = 0; j < 4; j++)
        t[ty + 8 * j][tx] = W[(size_t)(kb + ty + 8 * j) * D_MODEL + nb + tx];
    __syncthreads();
#pragma unroll
    for (int j = 0; j < 4; j++) {
        float v = t[tx][ty + 8 * j];
        __nv_bfloat16 h = __float2bfloat16_rn(v);
        __nv_bfloat16 l = __float2bfloat16_rn(v - __bfloat162float(h));
        size_t o = (size_t)(nb + ty + 8 * j) * D_MODEL + kb + tx;
        hi[o] = h;
        lo[o] = l;
    }
}

// ---------------------------------------------------------------------------
// Pack mask [B,S,S] int32 -> bitmask [B,S,S/32]
// ---------------------------------------------------------------------------
__global__ void pack_mask_kernel(const int* __restrict__ mask)
{
    const int warp = (blockIdx.x * blockDim.x + threadIdx.x) >> 5;  // 0..8191
    const int lane = threadIdx.x & 31;
    const int* src = mask + (size_t)warp * SEQL;
    uint32_t* dst = g_pk + (size_t)warp * (SEQL / 32);
#pragma unroll 4
    for (int w = 0; w < 32; w++) {
        int v = src[w * 32 + lane];
        uint32_t bits = __ballot_sync(0xffffffffu, v != 0);
        if (lane == 0) dst[w] = bits;
    }
}

// ---------------------------------------------------------------------------
// bf16x3-split GEMM via mma.sync: C[8192,1024] = X*W + bias, fp32 acc.
// mode 0: fp32 row-major to outf.   mode 1: bf16 hi/lo head-split scatter.
// ---------------------------------------------------------------------------
__global__ __launch_bounds__(256, 2)
void gemm_bf16x3_kernel(const __nv_bfloat16* __restrict__ Ahi,
                        const __nv_bfloat16* __restrict__ Alo,
                        const __nv_bfloat16* __restrict__ Bhi,
                        const __nv_bfloat16* __restrict__ Blo,
                        const float* __restrict__ bias,
                        float* __restrict__ outf,
                        __nv_bfloat16* __restrict__ ohi,
                        __nv_bfloat16* __restrict__ olo, int mode)
{
    __shared__ __align__(1024) char smem[32768];
    const uint32_t smem_base = smem_u32(smem);

    const int tid   = threadIdx.x;
    const int wid   = tid >> 5;
    const int lane  = tid & 31;
    const int warpM = wid & 3;
    const int warpN = wid >> 2;
    const int mBase = blockIdx.y * 128;
    const int nBase = blockIdx.x * 128;

    const int j8 = lane >> 3;
    const int r8 = lane & 7;
    const int aR = warpM * 32 + r8 + (j8 & 1) * 8;
    const int aC = (j8 >> 1);
    const int bR = warpN * 64 + r8 + (j8 >> 1) * 8;
    const int bC = (j8 & 1);

    const int gRow0 = tid >> 2;
    const int gC    = tid & 3;

    const __nv_bfloat16* APASS[3] = {Ahi, Alo, Ahi};
    const __nv_bfloat16* BPASS[3] = {Bhi, Bhi, Blo};

    float acc[2][8][4];
#pragma unroll
    for (int mf = 0; mf < 2; mf++)
#pragma unroll
        for (int nf = 0; nf < 8; nf++)
#pragma unroll
            for (int e = 0; e < 4; e++) acc[mf][nf][e] = 0.0f;

    const int NCHUNK = 3 * (D_MODEL / 32);  // 96

    {
        const __nv_bfloat16* Ap = APASS[0];
        const __nv_bfloat16* Bp = BPASS[0];
#pragma unroll
        for (int i = 0; i < 2; i++) {
            const int row = gRow0 + i * 64;
            uint4 va = *(const uint4*)(Ap + (size_t)(mBase + row) * D_MODEL + gC * 8);
            STS128(smem_base + swz(row, gC), va);
            uint4 vb = *(const uint4*)(Bp + (size_t)(nBase + row) * D_MODEL + gC * 8);
            STS128(smem_base + 8192 + swz(row, gC), vb);
        }
    }
    __syncthreads();

    for (int it = 0; it < NCHUNK; it++) {
        const int cur = it & 1;
        const int nxt = cur ^ 1;
        const bool more = (it + 1) < NCHUNK;

        uint4 na[2], nb[2];
        if (more) {
            const int nit  = it + 1;
            const int pass = nit >> 5;
            const int k0   = (nit & 31) * 32;
            const __nv_bfloat16* Ap = APASS[pass];
            const __nv_bfloat16* Bp = BPASS[pass];
#pragma unroll
            for (int i = 0; i < 2; i++) {
                const int row = gRow0 + i * 64;
                na[i] = *(const uint4*)(Ap + (size_t)(mBase + row) * D_MODEL + k0 + gC * 8);
                nb[i] = *(const uint4*)(Bp + (size_t)(nBase + row) * D_MODEL + k0 + gC * 8);
            }
        }

        const uint32_t aBuf = smem_base + cur * 16384;
        const uint32_t bBuf = aBuf + 8192;

#pragma unroll
        for (int kk = 0; kk < 2; kk++) {
            uint32_t af[2][4];
#pragma unroll
            for (int mf = 0; mf < 2; mf++) {
                const int row = aR + mf * 16;
                LDSM_X4(af[mf][0], af[mf][1], af[mf][2], af[mf][3],
                        aBuf + swz(row, aC + 2 * kk));
            }
            uint32_t bfr[8][2];
#pragma unroll
            for (int nf2 = 0; nf2 < 4; nf2++) {
                const int row = bR + nf2 * 16;
                uint32_t r0, r1, r2, r3;
                LDSM_X4(r0, r1, r2, r3, bBuf + swz(row, bC + 2 * kk));
                bfr[2 * nf2][0] = r0; bfr[2 * nf2][1] = r1;
                bfr[2 * nf2 + 1][0] = r2; bfr[2 * nf2 + 1][1] = r3;
            }
#pragma unroll
            for (int mf = 0; mf < 2; mf++)
#pragma unroll
                for (int nf = 0; nf < 8; nf++)
                    MMA_BF16(acc[mf][nf], af[mf], bfr[nf]);
        }

        if (more) {
            const uint32_t aB2 = smem_base + nxt * 16384;
#pragma unroll
            for (int i = 0; i < 2; i++) {
                const int row = gRow0 + i * 64;
                STS128(aB2 + swz(row, gC), na[i]);
                STS128(aB2 + 8192 + swz(row, gC), nb[i]);
            }
            __syncthreads();
        }
    }

#pragma unroll
    for (int mf = 0; mf < 2; mf++) {
#pragma unroll
        for (int nf = 0; nf < 8; nf++) {
            const int col = nBase + warpN * 64 + nf * 8 + (lane & 3) * 2;
            const float b0 = bias[col];
            const float b1 = bias[col + 1];
#pragma unroll
            for (int half = 0; half < 2; half++) {
                const int m = mBase + warpM * 32 + mf * 16 + (lane >> 2) + half * 8;
                const float vx = acc[mf][nf][half * 2 + 0] + b0;
                const float vy = acc[mf][nf][half * 2 + 1] + b1;
                if (mode) {
                    const int bb = m >> 10;
                    const int s  = m & 1023;
                    const int h  = col >> 6;
                    const int d  = col & 63;
                    const size_t idx = (((size_t)(bb * NHEAD + h) * SEQL + s) * DK) + d;
                    store_hilo2(&ohi[idx], &olo[idx], vx, vy);
                } else {
                    float2 o2; o2.x = vx; o2.y = vy;
                    *(float2*)&outf[(size_t)m * D_MODEL + col] = o2;
                }
            }
        }
    }
}

// ---------------------------------------------------------------------------
// Tensor-core flash attention.
// CTA = (q-tile of 128 rows, head, batch), 256 threads = 8 warps.
// Warp w owns rows w*16..+15 and the full 128-key / 64-d width.
// S = Qhi*Khi + Qlo*Khi + Qhi*Klo ; O += Phi*Vhi + Plo*Vhi + Phi*Vlo.
// Smem: Qhi/Qlo 2x16KB + double-buffered K/V hi/lo 2x64KB = 160KB.
// ---------------------------------------------------------------------------
#define AT_QHI  0
#define AT_QLO  16384
#define AT_BUF  32768
#define AT_TILE 16384
#define AT_BUFSZ 65536
#define AT_SMEM (AT_BUF + 2 * AT_BUFSZ)  // 163840

__device__ __forceinline__ void attn_load_kv(
    uint32_t dstBase,
    const __nv_bfloat16* __restrict__ khi, const __nv_bfloat16* __restrict__ klo,
    const __nv_bfloat16* __restrict__ vhi, const __nv_bfloat16* __restrict__ vlo,
    int kt, int tid)
{
#pragma unroll
    for (int i = 0; i < 4; i++) {
        const int u = tid + i * 256;
        const int row = u >> 3;
        const int c = u & 7;
        const uint32_t so = sw128((uint32_t)(row * 128 + c * 16));
        const size_t go = (size_t)(kt + row) * DK + c * 8;
        CP16(dstBase + 0 * AT_TILE + so, khi + go);
        CP16(dstBase + 1 * AT_TILE + so, klo + go);
        CP16(dstBase + 2 * AT_TILE + so, vhi + go);
        CP16(dstBase + 3 * AT_TILE + so, vlo + go);
    }
}

__global__ __launch_bounds__(256, 1) void attn_mma_kernel()
{
    extern __shared__ char sm[];
    const uint32_t sb = smem_u32(sm);
    const int tid  = threadIdx.x;
    const int wid  = tid >> 5;
    const int lane = tid & 31;
    const int qt = blockIdx.x;   // 0..7 (128-row q tiles)
    const int h  = blockIdx.y;
    const int b  = blockIdx.z;

    const size_t headOff = (size_t)(b * NHEAD + h) * SEQL * DK;
    const __nv_bfloat16* qhig = g_qhi + headOff + (size_t)qt * 128 * DK;
    const __nv_bfloat16* qlog = g_qlo + headOff + (size_t)qt * 128 * DK;
    const __nv_bfloat16* khig = g_khi + headOff;
    const __nv_bfloat16* klog = g_klo + headOff;
    const __nv_bfloat16* vhig = g_vhi + headOff;
    const __nv_bfloat16* vlog = g_vlo + headOff;

    // Q tiles -> smem (plain), KV buf0 -> cp.async
    {
#pragma unroll
        for (int i = 0; i < 4; i++) {
            const int u = tid + i * 256;
            const int row = u >> 3;
            const int c = u & 7;
            const uint32_t so = sw128((uint32_t)(row * 128 + c * 16));
            const size_t go = (size_t)row * DK + c * 8;
            uint4 vh = *(const uint4*)(qhig + go);
            STS128(sb + AT_QHI + so, vh);
            uint4 vl = *(const uint4*)(qlog + go);
            STS128(sb + AT_QLO + so, vl);
        }
    }
    attn_load_kv(sb + AT_BUF, khig, klog, vhig, vlog, 0, tid);
    CP_COMMIT();
    __syncthreads();

    // extract Q fragments (A-operand, 4 ksteps over d=64)
    const int r8 = lane & 7;
    const int j8 = lane >> 3;
    const int aRow = wid * 16 + r8 + (j8 & 1) * 8;
    const int aC0  = j8 >> 1;
    uint32_t qh[4][4], ql[4][4];
#pragma unroll
    for (int kk = 0; kk < 4; kk++) {
        const uint32_t so = sw128((uint32_t)(aRow * 128 + (aC0 + 2 * kk) * 16));
        LDSM_X4(qh[kk][0], qh[kk][1], qh[kk][2], qh[kk][3], sb + AT_QHI + so);
        LDSM_X4(ql[kk][0], ql[kk][1], ql[kk][2], ql[kk][3], sb + AT_QLO + so);
    }

    float o[8][4];
#pragma unroll
    for (int nf = 0; nf < 8; nf++)
#pragma unroll
        for (int e = 0; e < 4; e++) o[nf][e] = 0.0f;
    float mrow1 = -CUDART_INF_F, mrow2 = -CUDART_INF_F;
    float lrow1 = 0.0f, lrow2 = 0.0f;

    const int qrow1 = qt * 128 + wid * 16 + (lane >> 2);
    const uint32_t* pk1 = g_pk + ((size_t)b * SEQL + qrow1) * (SEQL / 32);
    const uint32_t* pk2 = pk1 + 8 * (SEQL / 32);

    const int bRow = r8 + (j8 >> 1) * 8;   // key row within 16-block
    const int bC   = j8 & 1;               // +2*kk chunk
    const int vRow = lane & 15;            // within k16 block (trans ldsm)
    const int vCh  = lane >> 4;            // 0/1 d-chunk half

    for (int it = 0; it < 8; it++) {
        const int cur = it & 1;
        if (it < 7) {
            attn_load_kv(sb + AT_BUF + (cur ^ 1) * AT_BUFSZ,
                         khig, klog, vhig, vlog, (it + 1) * 128, tid);
            CP_COMMIT();
            asm volatile("cp.async.wait_group 1;" ::: "memory");
        } else {
            asm volatile("cp.async.wait_group 0;" ::: "memory");
        }
        __syncthreads();

        const uint32_t kb_base = sb + AT_BUF + cur * AT_BUFSZ;

        // ---- S = Q K^T (3-term split) ----
        float s[16][4];
#pragma unroll
        for (int nf = 0; nf < 16; nf++)
#pragma unroll
            for (int e = 0; e < 4; e++) s[nf][e] = 0.0f;

#pragma unroll
        for (int kk = 0; kk < 4; kk++) {
            uint32_t kb[16][2];
#pragma unroll
            for (int nf2 = 0; nf2 < 8; nf2++) {
                uint32_t r0, r1, r2, r3;
                LDSM_X4(r0, r1, r2, r3, kb_base + 0 * AT_TILE +
                        sw128((uint32_t)((nf2 * 16 + bRow) * 128 + (bC + 2 * kk) * 16)));
                kb[2 * nf2][0] = r0; kb[2 * nf2][1] = r1;
                kb[2 * nf2 + 1][0] = r2; kb[2 * nf2 + 1][1] = r3;
            }
#pragma unroll
            for (int nf = 0; nf < 16; nf++) MMA_BF16(s[nf], qh[kk], kb[nf]);
#pragma unroll
            for (int nf = 0; nf < 16; nf++) MMA_BF16(s[nf], ql[kk], kb[nf]);
#pragma unroll
            for (int nf2 = 0; nf2 < 8; nf2++) {
                uint32_t r0, r1, r2, r3;
                LDSM_X4(r0, r1, r2, r3, kb_base + 1 * AT_TILE +
                        sw128((uint32_t)((nf2 * 16 + bRow) * 128 + (bC + 2 * kk) * 16)));
                kb[2 * nf2][0] = r0; kb[2 * nf2][1] = r1;
                kb[2 * nf2 + 1][0] = r2; kb[2 * nf2 + 1][1] = r3;
            }
#pragma unroll
            for (int nf = 0; nf < 16; nf++) MMA_BF16(s[nf], qh[kk], kb[nf]);
        }

        // ---- mask + scale ----
        uint4 mwa = *(const uint4*)(pk1 + it * 4);
        uint4 mwb = *(const uint4*)(pk2 + it * 4);
        const uint32_t w1[4] = {mwa.x, mwa.y, mwa.z, mwa.w};
        const uint32_t w2[4] = {mwb.x, mwb.y, mwb.z, mwb.w};
#pragma unroll
        for (int nf = 0; nf < 16; nf++) {
            const uint32_t wa = w1[nf >> 2];
            const uint32_t wb = w2[nf >> 2];
            const int sh = (nf * 8 + (lane & 3) * 2) & 31;
            s[nf][0] = ((wa >> sh) & 1u)       ? s[nf][0] * 0.125f : -1e9f;
            s[nf][1] = ((wa >> (sh + 1)) & 1u) ? s[nf][1] * 0.125f : -1e9f;
            s[nf][2] = ((wb >> sh) & 1u)       ? s[nf][2] * 0.125f : -1e9f;
            s[nf][3] = ((wb >> (sh + 1)) & 1u) ? s[nf][3] * 0.125f : -1e9f;
        }

        // ---- online softmax (rows fully inside lane&3 quads) ----
        float mx1 = -CUDART_INF_F, mx2 = -CUDART_INF_F;
#pragma unroll
        for (int nf = 0; nf < 16; nf++) {
            mx1 = fmaxf(mx1, fmaxf(s[nf][0], s[nf][1]));
            mx2 = fmaxf(mx2, fmaxf(s[nf][2], s[nf][3]));
        }
        mx1 = fmaxf(mx1, __shfl_xor_sync(0xffffffffu, mx1, 1));
        mx1 = fmaxf(mx1, __shfl_xor_sync(0xffffffffu, mx1, 2));
        mx2 = fmaxf(mx2, __shfl_xor_sync(0xffffffffu, mx2, 1));
        mx2 = fmaxf(mx2, __shfl_xor_sync(0xffffffffu, mx2, 2));

        const float mn1 = fmaxf(mrow1, mx1);
        const float mn2 = fmaxf(mrow2, mx2);
        const float c1 = __expf(mrow1 - mn1);
        const float c2 = __expf(mrow2 - mn2);
        mrow1 = mn1; mrow2 = mn2;

        float rs1 = 0.0f, rs2 = 0.0f;
#pragma unroll
        for (int nf = 0; nf < 16; nf++) {
            s[nf][0] = __expf(s[nf][0] - mn1); rs1 += s[nf][0];
            s[nf][1] = __expf(s[nf][1] - mn1); rs1 += s[nf][1];
            s[nf][2] = __expf(s[nf][2] - mn2); rs2 += s[nf][2];
            s[nf][3] = __expf(s[nf][3] - mn2); rs2 += s[nf][3];
        }
        rs1 += __shfl_xor_sync(0xffffffffu, rs1, 1);
        rs1 += __shfl_xor_sync(0xffffffffu, rs1, 2);
        rs2 += __shfl_xor_sync(0xffffffffu, rs2, 1);
        rs2 += __shfl_xor_sync(0xffffffffu, rs2, 2);
        lrow1 = lrow1 * c1 + rs1;
        lrow2 = lrow2 * c2 + rs2;

#pragma unroll
        for (int nf = 0; nf < 8; nf++) {
            o[nf][0] *= c1; o[nf][1] *= c1;
            o[nf][2] *= c2; o[nf][3] *= c2;
        }

        // ---- pack P hi/lo (S acc regs become PV A-fragments) ----
        uint32_t phi[16][2], plo[16][2];
#pragma unroll
        for (int nf = 0; nf < 16; nf++) {
            __nv_bfloat16 h0 = __float2bfloat16_rn(s[nf][0]);
            __nv_bfloat16 h1 = __float2bfloat16_rn(s[nf][1]);
            __nv_bfloat16 h2 = __float2bfloat16_rn(s[nf][2]);
            __nv_bfloat16 h3 = __float2bfloat16_rn(s[nf][3]);
            phi[nf][0] = pack_bf16x2(h0, h1);
            phi[nf][1] = pack_bf16x2(h2, h3);
            plo[nf][0] = pack_bf16x2(
                __float2bfloat16_rn(s[nf][0] - __bfloat162float(h0)),
                __float2bfloat16_rn(s[nf][1] - __bfloat162float(h1)));
            plo[nf][1] = pack_bf16x2(
                __float2bfloat16_rn(s[nf][2] - __bfloat162float(h2)),
                __float2bfloat16_rn(s[nf][3] - __bfloat162float(h3)));
        }

        // ---- O += P V (3-term split); V via trans ldmatrix ----
#pragma unroll
        for (int j = 0; j < 8; j++) {
            uint32_t pa_hi[4] = {phi[2 * j][0], phi[2 * j][1],
                                 phi[2 * j + 1][0], phi[2 * j + 1][1]};
            uint32_t pa_lo[4] = {plo[2 * j][0], plo[2 * j][1],
                                 plo[2 * j + 1][0], plo[2 * j + 1][1]};
            uint32_t vb[8][2];
#pragma unroll
            for (int nf2 = 0; nf2 < 4; nf2++) {
                uint32_t r0, r1, r2, r3;
                LDSM_X4T(r0, r1, r2, r3, kb_base + 2 * AT_TILE +
                         sw128((uint32_t)((j * 16 + vRow) * 128 + (nf2 * 2 + vCh) * 16)));
                vb[2 * nf2][0] = r0; vb[2 * nf2][1] = r1;
                vb[2 * nf2 + 1][0] = r2; vb[2 * nf2 + 1][1] = r3;
            }
#pragma unroll
            for (int nf = 0; nf < 8; nf++) MMA_BF16(o[nf], pa_hi, vb[nf]);
#pragma unroll
            for (int nf = 0; nf < 8; nf++) MMA_BF16(o[nf], pa_lo, vb[nf]);
#pragma unroll
            for (int nf2 = 0; nf2 < 4; nf2++) {
                uint32_t r0, r1, r2, r3;
                LDSM_X4T(r0, r1, r2, r3, kb_base + 3 * AT_TILE +
                         sw128((uint32_t)((j * 16 + vRow) * 128 + (nf2 * 2 + vCh) * 16)));
                vb[2 * nf2][0] = r0; vb[2 * nf2][1] = r1;
                vb[2 * nf2 + 1][0] = r2; vb[2 * nf2 + 1][1] = r3;
            }
#pragma unroll
            for (int nf = 0; nf < 8; nf++) MMA_BF16(o[nf], pa_hi, vb[nf]);
        }

        __syncthreads();  // all reads of cur buffer done before refill
    }

    // ---- epilogue: normalize and write hi/lo split into g_xhi/g_xlo ----
    const float inv1 = 1.0f / lrow1;
    const float inv2 = 1.0f / lrow2;
    const size_t rowg1 = (size_t)b * SEQL + qt * 128 + wid * 16 + (lane >> 2);
    const size_t rowg2 = rowg1 + 8;
#pragma unroll
    for (int nf = 0; nf < 8; nf++) {
        const int col = h * 64 + nf * 8 + (lane & 3) * 2;
        store_hilo2(&g_xhi[rowg1 * D_MODEL + col], &g_xlo[rowg1 * D_MODEL + col],
                    o[nf][0] * inv1, o[nf][1] * inv1);
        store_hilo2(&g_xhi[rowg2 * D_MODEL + col], &g_xlo[rowg2 * D_MODEL + col],
                    o[nf][2] * inv2, o[nf][3] * inv2);
    }
}

// ---------------------------------------------------------------------------
// Host launcher
// ---------------------------------------------------------------------------
extern "C" void kernel_launch(void* const* d_in, const int* in_sizes, int n_in,
                              void* d_out, int out_size)
{
    (void)in_sizes; (void)n_in; (void)out_size;

    const float* q    = (const float*)d_in[0];
    const float* k    = (const float*)d_in[1];
    const float* v    = (const float*)d_in[2];
    const int*   mask = (const int*)  d_in[3];
    const float* Wq   = (const float*)d_in[4];
    const float* bq   = (const float*)d_in[5];
    const float* Wk   = (const float*)d_in[6];
    const float* bk   = (const float*)d_in[7];
    const float* Wv   = (const float*)d_in[8];
    const float* bv   = (const float*)d_in[9];
    const float* Wo   = (const float*)d_in[10];
    const float* bo   = (const float*)d_in[11];
    float* out = (float*)d_out;

    void* p;
    cudaGetSymbolAddress(&p, g_qhi); __nv_bfloat16* qhi = (__nv_bfloat16*)p;
    cudaGetSymbolAddress(&p, g_qlo); __nv_bfloat16* qlo = (__nv_bfloat16*)p;
    cudaGetSymbolAddress(&p, g_khi); __nv_bfloat16* khi = (__nv_bfloat16*)p;
    cudaGetSymbolAddress(&p, g_klo); __nv_bfloat16* klo = (__nv_bfloat16*)p;
    cudaGetSymbolAddress(&p, g_vhi); __nv_bfloat16* vhi = (__nv_bfloat16*)p;
    cudaGetSymbolAddress(&p, g_vlo); __nv_bfloat16* vlo = (__nv_bfloat16*)p;
    cudaGetSymbolAddress(&p, g_xhi); __nv_bfloat16* xhi = (__nv_bfloat16*)p;
    cudaGetSymbolAddress(&p, g_xlo); __nv_bfloat16* xlo = (__nv_bfloat16*)p;
    cudaGetSymbolAddress(&p, g_whi); __nv_bfloat16* whi = (__nv_bfloat16*)p;
    cudaGetSymbolAddress(&p, g_wlo); __nv_bfloat16* wlo = (__nv_bfloat16*)p;

    cudaFuncSetAttribute(attn_mma_kernel,
                         cudaFuncAttributeMaxDynamicSharedMemorySize, AT_SMEM);

    const int n4 = MROWS * D_MODEL / 4;
    const dim3 ggemm(D_MODEL / 128, MROWS / 128);   // (8, 64)
    const dim3 gtr(D_MODEL / 32, D_MODEL / 32);     // (32, 32)

    pack_mask_kernel<<<MROWS / 8, 256>>>(mask);

    // Q projection -> bf16 hi/lo head-split
    split_hilo_kernel<<<(n4 + 255) / 256, 256>>>(q, xhi, xlo, n4);
    split_transpose_kernel<<<gtr, 256>>>(Wq, whi, wlo);
    gemm_bf16x3_kernel<<<ggemm, 256>>>(xhi, xlo, whi, wlo, bq, nullptr, qhi, qlo, 1);
    // K projection
    split_hilo_kernel<<<(n4 + 255) / 256, 256>>>(k, xhi, xlo, n4);
    split_transpose_kernel<<<gtr, 256>>>(Wk, whi, wlo);
    gemm_bf16x3_kernel<<<ggemm, 256>>>(xhi, xlo, whi, wlo, bk, nullptr, khi, klo, 1);
    // V projection
    split_hilo_kernel<<<(n4 + 255) / 256, 256>>>(v, xhi, xlo, n4);
    split_transpose_kernel<<<gtr, 256>>>(Wv, whi, wlo);
    gemm_bf16x3_kernel<<<ggemm, 256>>>(xhi, xlo, whi, wlo, bv, nullptr, vhi, vlo, 1);

    // Attention (writes hi/lo concat directly into g_xhi/g_xlo)
    attn_mma_kernel<<<dim3(SEQL / 128, NHEAD, BSZ), 256, AT_SMEM>>>();

    // Output projection (fp32 -> d_out)
    split_transpose_kernel<<<gtr, 256>>>(Wo, whi, wlo);
    gemm_bf16x3_kernel<<<ggemm, 256>>>(xhi, xlo, whi, wlo, bo, out, nullptr, nullptr, 0);
}

// round 7
// speedup vs baseline: 2.8333x; 1.2471x over previous
#include <cuda_runtime.h>
#include <cuda_bf16.h>
#include <math_constants.h>
#include <cstdint>

// Problem constants
#define D_MODEL 1024
#define NHEAD   16
#define DK      64
#define BSZ     8
#define SEQL    1024
#define MROWS   (BSZ * SEQL)   // 8192

// ---------------------------------------------------------------------------
// Scratch (allocation-free: __device__ globals)
// ---------------------------------------------------------------------------
__device__ __align__(16) __nv_bfloat16 g_qhi[(size_t)BSZ * NHEAD * SEQL * DK];
__device__ __align__(16) __nv_bfloat16 g_qlo[(size_t)BSZ * NHEAD * SEQL * DK];
__device__ __align__(16) __nv_bfloat16 g_khi[(size_t)BSZ * NHEAD * SEQL * DK];
__device__ __align__(16) __nv_bfloat16 g_klo[(size_t)BSZ * NHEAD * SEQL * DK];
__device__ __align__(16) __nv_bfloat16 g_vhi[(size_t)BSZ * NHEAD * SEQL * DK];
__device__ __align__(16) __nv_bfloat16 g_vlo[(size_t)BSZ * NHEAD * SEQL * DK];
__device__ __align__(16) __nv_bfloat16 g_xhi[(size_t)MROWS * D_MODEL];
__device__ __align__(16) __nv_bfloat16 g_xlo[(size_t)MROWS * D_MODEL];
__device__ __align__(16) __nv_bfloat16 g_whi[(size_t)D_MODEL * D_MODEL];  // [N,K]
__device__ __align__(16) __nv_bfloat16 g_wlo[(size_t)D_MODEL * D_MODEL];  // [N,K]
__device__ __align__(16) uint32_t g_pk[(size_t)BSZ * SEQL * (SEQL / 32)]; // packed mask

// ---------------------------------------------------------------------------
// PTX helpers (standard PTX only — tcgen05 is rejected by the sm_103 target)
// ---------------------------------------------------------------------------
__device__ __forceinline__ uint32_t smem_u32(const void* p) {
    uint32_t a;
    asm("{ .reg .u64 t; cvta.to.shared.u64 t, %1; cvt.u32.u64 %0, t; }"
        : "=r"(a) : "l"(p));
    return a;
}

#define LDSM_X4(r0, r1, r2, r3, addr) \
    asm volatile("ldmatrix.sync.aligned.m8n8.x4.shared.b16 {%0,%1,%2,%3}, [%4];" \
                 : "=r"(r0), "=r"(r1), "=r"(r2), "=r"(r3) : "r"(addr))

#define LDSM_X4T(r0, r1, r2, r3, addr) \
    asm volatile("ldmatrix.sync.aligned.m8n8.x4.trans.shared.b16 {%0,%1,%2,%3}, [%4];" \
                 : "=r"(r0), "=r"(r1), "=r"(r2), "=r"(r3) : "r"(addr))

#define MMA_BF16(d, a, b) \
    asm volatile("mma.sync.aligned.m16n8k16.row.col.f32.bf16.bf16.f32 " \
                 "{%0,%1,%2,%3}, {%4,%5,%6,%7}, {%8,%9}, {%0,%1,%2,%3};" \
                 : "+f"((d)[0]), "+f"((d)[1]), "+f"((d)[2]), "+f"((d)[3]) \
                 : "r"((a)[0]), "r"((a)[1]), "r"((a)[2]), "r"((a)[3]), \
                   "r"((b)[0]), "r"((b)[1]))

#define STS128(addr, v) \
    asm volatile("st.shared.v4.b32 [%0], {%1,%2,%3,%4};" \
                 :: "r"(addr), "r"((v).x), "r"((v).y), "r"((v).z), "r"((v).w) \
                 : "memory")

#define CP16(smem_addr, gptr) \
    asm volatile("cp.async.cg.shared.global [%0], [%1], 16;" \
                 :: "r"(smem_addr), "l"(gptr) : "memory")
#define CP_COMMIT() asm volatile("cp.async.commit_group;" ::: "memory")

// 64B-row swizzle (GEMM tiles)
__device__ __forceinline__ uint32_t swz(int row, int c) {
    return (uint32_t)((row << 6) + (((c ^ (row >> 1)) & 3) << 4));
}
// SW128 swizzle for 128B rows (attention tiles)
__device__ __forceinline__ uint32_t sw128(uint32_t off) {
    return off ^ ((off >> 3) & 0x70);
}

__device__ __forceinline__ uint32_t pack_bf16x2(__nv_bfloat16 lo16, __nv_bfloat16 hi16) {
    return ((uint32_t)*(const uint16_t*)&hi16 << 16) | *(const uint16_t*)&lo16;
}

// split fp32 pair into bf16 hi / lo pairs and store as packed u32
__device__ __forceinline__ void store_hilo2(__nv_bfloat16* hi, __nv_bfloat16* lo,
                                            float a, float b) {
    __nv_bfloat16 ha = __float2bfloat16_rn(a), hb = __float2bfloat16_rn(b);
    *(uint32_t*)hi = pack_bf16x2(ha, hb);
    __nv_bfloat16 la = __float2bfloat16_rn(a - __bfloat162float(ha));
    __nv_bfloat16 lb = __float2bfloat16_rn(b - __bfloat162float(hb));
    *(uint32_t*)lo = pack_bf16x2(la, lb);
}

// ---------------------------------------------------------------------------
// fp32 -> (hi,lo) bf16 split, elementwise
// ---------------------------------------------------------------------------
__global__ void split_hilo_kernel(const float* __restrict__ x,
                                  __nv_bfloat16* __restrict__ hi,
                                  __nv_bfloat16* __restrict__ lo, int n4)
{
    int i = blockIdx.x * blockDim.x + threadIdx.x;
    if (i >= n4) return;
    float4 v = ((const float4*)x)[i];
    __nv_bfloat16 h[4], l[4];
    float f[4] = {v.x, v.y, v.z, v.w};
#pragma unroll
    for (int j = 0; j < 4; j++) {
        h[j] = __float2bfloat16_rn(f[j]);
        l[j] = __float2bfloat16_rn(f[j] - __bfloat162float(h[j]));
    }
    ((uint2*)hi)[i] = *(uint2*)h;
    ((uint2*)lo)[i] = *(uint2*)l;
}

// ---------------------------------------------------------------------------
// W [K,N] fp32 -> Wt hi/lo [N,K] bf16 (transpose + split)
// ---------------------------------------------------------------------------
__global__ void split_transpose_kernel(const float* __restrict__ W,
                                       __nv_bfloat16* __restrict__ hi,
                                       __nv_bfloat16* __restrict__ lo)
{
    __shared__ float t[32][33];
    const int kb = blockIdx.y * 32;
    const int nb = blockIdx.x * 32;
    const int tx = threadIdx.x & 31;
    const int ty = threadIdx.x >> 5;
#pragma unroll
    for (int j = 0; j < 4; j++)
        t[ty + 8 * j][tx] = W[(size_t)(kb + ty + 8 * j) * D_MODEL + nb + tx];
    __syncthreads();
#pragma unroll
    for (int j = 0; j < 4; j++) {
        float v = t[tx][ty + 8 * j];
        __nv_bfloat16 h = __float2bfloat16_rn(v);
        __nv_bfloat16 l = __float2bfloat16_rn(v - __bfloat162float(h));
        size_t o = (size_t)(nb + ty + 8 * j) * D_MODEL + kb + tx;
        hi[o] = h;
        lo[o] = l;
    }
}

// ---------------------------------------------------------------------------
// Pack mask [B,S,S] int32 -> bitmask [B,S,S/32]
// ---------------------------------------------------------------------------
__global__ void pack_mask_kernel(const int* __restrict__ mask)
{
    const int warp = (blockIdx.x * blockDim.x + threadIdx.x) >> 5;  // 0..8191
    const int lane = threadIdx.x & 31;
    const int* src = mask + (size_t)warp * SEQL;
    uint32_t* dst = g_pk + (size_t)warp * (SEQL / 32);
#pragma unroll 4
    for (int w = 0; w < 32; w++) {
        int v = src[w * 32 + lane];
        uint32_t bits = __ballot_sync(0xffffffffu, v != 0);
        if (lane == 0) dst[w] = bits;
    }
}

// ---------------------------------------------------------------------------
// Merged bf16x3-split GEMM via mma.sync: C = X*W + bias, fp32 acc.
// ONE pass over K: per 32-wide chunk load Ahi/Alo/Bhi/Blo and compute
// hi*hi + lo*hi + hi*lo from the same staging. cp.async double buffer.
// CTA 128x128, warp tile 32x64. mode 0: fp32 out; mode 1: hi/lo head-split.
// ---------------------------------------------------------------------------
#define G_AHI 0
#define G_ALO 8192
#define G_BHI 16384
#define G_BLO 24576
#define G_STAGE 32768
#define G_SMEM (2 * G_STAGE)  // 65536

__global__ __launch_bounds__(256, 2)
void gemm_bf16x3_kernel(const __nv_bfloat16* __restrict__ Ahi,
                        const __nv_bfloat16* __restrict__ Alo,
                        const __nv_bfloat16* __restrict__ Bhi,
                        const __nv_bfloat16* __restrict__ Blo,
                        const float* __restrict__ bias,
                        float* __restrict__ outf,
                        __nv_bfloat16* __restrict__ ohi,
                        __nv_bfloat16* __restrict__ olo, int mode)
{
    extern __shared__ __align__(1024) char smem[];
    const uint32_t smem_base = smem_u32(smem);

    const int tid   = threadIdx.x;
    const int wid   = tid >> 5;
    const int lane  = tid & 31;
    const int warpM = wid & 3;
    const int warpN = wid >> 2;
    const int mBase = blockIdx.y * 128;
    const int nBase = blockIdx.x * 128;

    const int j8 = lane >> 3;
    const int r8 = lane & 7;
    const int aR = warpM * 32 + r8 + (j8 & 1) * 8;
    const int aC = (j8 >> 1);
    const int bR = warpN * 64 + r8 + (j8 >> 1) * 8;
    const int bC = (j8 & 1);

    const int gRow0 = tid >> 2;   // 0..63
    const int gC    = tid & 3;    // 16B chunk within 64B row

    float acc[2][8][4];
#pragma unroll
    for (int mf = 0; mf < 2; mf++)
#pragma unroll
        for (int nf = 0; nf < 8; nf++)
#pragma unroll
            for (int e = 0; e < 4; e++) acc[mf][nf][e] = 0.0f;

    const __nv_bfloat16* Apg = Ahi + (size_t)mBase * D_MODEL;
    const __nv_bfloat16* Alg = Alo + (size_t)mBase * D_MODEL;
    const __nv_bfloat16* Bpg = Bhi + (size_t)nBase * D_MODEL;
    const __nv_bfloat16* Blg = Blo + (size_t)nBase * D_MODEL;

    // chunk loader: 4 tiles x (128 rows x 64B) via cp.async
    auto load_chunk = [&](int k0, uint32_t stage) {
#pragma unroll
        for (int i = 0; i < 2; i++) {
            const int row = gRow0 + i * 64;
            const uint32_t off = swz(row, gC);
            const size_t goA = (size_t)row * D_MODEL + k0 + gC * 8;
            CP16(stage + G_AHI + off, Apg + goA);
            CP16(stage + G_ALO + off, Alg + goA);
            CP16(stage + G_BHI + off, Bpg + goA);
            CP16(stage + G_BLO + off, Blg + goA);
        }
    };

    const int NCHUNK = D_MODEL / 32;  // 32

    load_chunk(0, smem_base);
    CP_COMMIT();

    for (int it = 0; it < NCHUNK; it++) {
        const int cur = it & 1;
        if (it + 1 < NCHUNK) {
            load_chunk((it + 1) * 32, smem_base + (cur ^ 1) * G_STAGE);
            CP_COMMIT();
            asm volatile("cp.async.wait_group 1;" ::: "memory");
        } else {
            asm volatile("cp.async.wait_group 0;" ::: "memory");
        }
        __syncthreads();

        const uint32_t st = smem_base + cur * G_STAGE;

#pragma unroll
        for (int kk = 0; kk < 2; kk++) {
            uint32_t afh[2][4], afl[2][4];
#pragma unroll
            for (int mf = 0; mf < 2; mf++) {
                const int row = aR + mf * 16;
                const uint32_t off = swz(row, aC + 2 * kk);
                LDSM_X4(afh[mf][0], afh[mf][1], afh[mf][2], afh[mf][3],
                        st + G_AHI + off);
                LDSM_X4(afl[mf][0], afl[mf][1], afl[mf][2], afl[mf][3],
                        st + G_ALO + off);
            }
#pragma unroll
            for (int nf2 = 0; nf2 < 4; nf2++) {
                const int row = bR + nf2 * 16;
                const uint32_t off = swz(row, bC + 2 * kk);
                uint32_t h0, h1, h2, h3, l0, l1, l2, l3;
                LDSM_X4(h0, h1, h2, h3, st + G_BHI + off);
                LDSM_X4(l0, l1, l2, l3, st + G_BLO + off);
                uint32_t bh0[2] = {h0, h1}, bh1[2] = {h2, h3};
                uint32_t bl0[2] = {l0, l1}, bl1[2] = {l2, l3};
#pragma unroll
                for (int mf = 0; mf < 2; mf++) {
                    MMA_BF16(acc[mf][2 * nf2],     afh[mf], bh0);
                    MMA_BF16(acc[mf][2 * nf2],     afl[mf], bh0);
                    MMA_BF16(acc[mf][2 * nf2],     afh[mf], bl0);
                    MMA_BF16(acc[mf][2 * nf2 + 1], afh[mf], bh1);
                    MMA_BF16(acc[mf][2 * nf2 + 1], afl[mf], bh1);
                    MMA_BF16(acc[mf][2 * nf2 + 1], afh[mf], bl1);
                }
            }
        }
        __syncthreads();  // all reads of cur stage done before it is refilled
    }

#pragma unroll
    for (int mf = 0; mf < 2; mf++) {
#pragma unroll
        for (int nf = 0; nf < 8; nf++) {
            const int col = nBase + warpN * 64 + nf * 8 + (lane & 3) * 2;
            const float b0 = bias[col];
            const float b1 = bias[col + 1];
#pragma unroll
            for (int half = 0; half < 2; half++) {
                const int m = mBase + warpM * 32 + mf * 16 + (lane >> 2) + half * 8;
                const float vx = acc[mf][nf][half * 2 + 0] + b0;
                const float vy = acc[mf][nf][half * 2 + 1] + b1;
                if (mode) {
                    const int bb = m >> 10;
                    const int s  = m & 1023;
                    const int h  = col >> 6;
                    const int d  = col & 63;
                    const size_t idx = (((size_t)(bb * NHEAD + h) * SEQL + s) * DK) + d;
                    store_hilo2(&ohi[idx], &olo[idx], vx, vy);
                } else {
                    float2 o2; o2.x = vx; o2.y = vy;
                    *(float2*)&outf[(size_t)m * D_MODEL + col] = o2;
                }
            }
        }
    }
}

// ---------------------------------------------------------------------------
// Tensor-core flash attention (unchanged from R6 passing version).
// CTA = (q-tile of 128 rows, head, batch), 256 threads = 8 warps.
// ---------------------------------------------------------------------------
#define AT_QHI  0
#define AT_QLO  16384
#define AT_BUF  32768
#define AT_TILE 16384
#define AT_BUFSZ 65536
#define AT_SMEM (AT_BUF + 2 * AT_BUFSZ)  // 163840

__device__ __forceinline__ void attn_load_kv(
    uint32_t dstBase,
    const __nv_bfloat16* __restrict__ khi, const __nv_bfloat16* __restrict__ klo,
    const __nv_bfloat16* __restrict__ vhi, const __nv_bfloat16* __restrict__ vlo,
    int kt, int tid)
{
#pragma unroll
    for (int i = 0; i < 4; i++) {
        const int u = tid + i * 256;
        const int row = u >> 3;
        const int c = u & 7;
        const uint32_t so = sw128((uint32_t)(row * 128 + c * 16));
        const size_t go = (size_t)(kt + row) * DK + c * 8;
        CP16(dstBase + 0 * AT_TILE + so, khi + go);
        CP16(dstBase + 1 * AT_TILE + so, klo + go);
        CP16(dstBase + 2 * AT_TILE + so, vhi + go);
        CP16(dstBase + 3 * AT_TILE + so, vlo + go);
    }
}

__global__ __launch_bounds__(256, 1) void attn_mma_kernel()
{
    extern __shared__ char sm[];
    const uint32_t sb = smem_u32(sm);
    const int tid  = threadIdx.x;
    const int wid  = tid >> 5;
    const int lane = tid & 31;
    const int qt = blockIdx.x;
    const int h  = blockIdx.y;
    const int b  = blockIdx.z;

    const size_t headOff = (size_t)(b * NHEAD + h) * SEQL * DK;
    const __nv_bfloat16* qhig = g_qhi + headOff + (size_t)qt * 128 * DK;
    const __nv_bfloat16* qlog = g_qlo + headOff + (size_t)qt * 128 * DK;
    const __nv_bfloat16* khig = g_khi + headOff;
    const __nv_bfloat16* klog = g_klo + headOff;
    const __nv_bfloat16* vhig = g_vhi + headOff;
    const __nv_bfloat16* vlog = g_vlo + headOff;

    {
#pragma unroll
        for (int i = 0; i < 4; i++) {
            const int u = tid + i * 256;
            const int row = u >> 3;
            const int c = u & 7;
            const uint32_t so = sw128((uint32_t)(row * 128 + c * 16));
            const size_t go = (size_t)row * DK + c * 8;
            uint4 vh = *(const uint4*)(qhig + go);
            STS128(sb + AT_QHI + so, vh);
            uint4 vl = *(const uint4*)(qlog + go);
            STS128(sb + AT_QLO + so, vl);
        }
    }
    attn_load_kv(sb + AT_BUF, khig, klog, vhig, vlog, 0, tid);
    CP_COMMIT();
    __syncthreads();

    const int r8 = lane & 7;
    const int j8 = lane >> 3;
    const int aRow = wid * 16 + r8 + (j8 & 1) * 8;
    const int aC0  = j8 >> 1;
    uint32_t qh[4][4], ql[4][4];
#pragma unroll
    for (int kk = 0; kk < 4; kk++) {
        const uint32_t so = sw128((uint32_t)(aRow * 128 + (aC0 + 2 * kk) * 16));
        LDSM_X4(qh[kk][0], qh[kk][1], qh[kk][2], qh[kk][3], sb + AT_QHI + so);
        LDSM_X4(ql[kk][0], ql[kk][1], ql[kk][2], ql[kk][3], sb + AT_QLO + so);
    }

    float o[8][4];
#pragma unroll
    for (int nf = 0; nf < 8; nf++)
#pragma unroll
        for (int e = 0; e < 4; e++) o[nf][e] = 0.0f;
    float mrow1 = -CUDART_INF_F, mrow2 = -CUDART_INF_F;
    float lrow1 = 0.0f, lrow2 = 0.0f;

    const int qrow1 = qt * 128 + wid * 16 + (lane >> 2);
    const uint32_t* pk1 = g_pk + ((size_t)b * SEQL + qrow1) * (SEQL / 32);
    const uint32_t* pk2 = pk1 + 8 * (SEQL / 32);

    const int bRow = r8 + (j8 >> 1) * 8;
    const int bC   = j8 & 1;
    const int vRow = lane & 15;
    const int vCh  = lane >> 4;

    for (int it = 0; it < 8; it++) {
        const int cur = it & 1;
        if (it < 7) {
            attn_load_kv(sb + AT_BUF + (cur ^ 1) * AT_BUFSZ,
                         khig, klog, vhig, vlog, (it + 1) * 128, tid);
            CP_COMMIT();
            asm volatile("cp.async.wait_group 1;" ::: "memory");
        } else {
            asm volatile("cp.async.wait_group 0;" ::: "memory");
        }
        __syncthreads();

        const uint32_t kb_base = sb + AT_BUF + cur * AT_BUFSZ;

        float s[16][4];
#pragma unroll
        for (int nf = 0; nf < 16; nf++)
#pragma unroll
            for (int e = 0; e < 4; e++) s[nf][e] = 0.0f;

#pragma unroll
        for (int kk = 0; kk < 4; kk++) {
            uint32_t kb[16][2];
#pragma unroll
            for (int nf2 = 0; nf2 < 8; nf2++) {
                uint32_t r0, r1, r2, r3;
                LDSM_X4(r0, r1, r2, r3, kb_base + 0 * AT_TILE +
                        sw128((uint32_t)((nf2 * 16 + bRow) * 128 + (bC + 2 * kk) * 16)));
                kb[2 * nf2][0] = r0; kb[2 * nf2][1] = r1;
                kb[2 * nf2 + 1][0] = r2; kb[2 * nf2 + 1][1] = r3;
            }
#pragma unroll
            for (int nf = 0; nf < 16; nf++) MMA_BF16(s[nf], qh[kk], kb[nf]);
#pragma unroll
            for (int nf = 0; nf < 16; nf++) MMA_BF16(s[nf], ql[kk], kb[nf]);
#pragma unroll
            for (int nf2 = 0; nf2 < 8; nf2++) {
                uint32_t r0, r1, r2, r3;
                LDSM_X4(r0, r1, r2, r3, kb_base + 1 * AT_TILE +
                        sw128((uint32_t)((nf2 * 16 + bRow) * 128 + (bC + 2 * kk) * 16)));
                kb[2 * nf2][0] = r0; kb[2 * nf2][1] = r1;
                kb[2 * nf2 + 1][0] = r2; kb[2 * nf2 + 1][1] = r3;
            }
#pragma unroll
            for (int nf = 0; nf < 16; nf++) MMA_BF16(s[nf], qh[kk], kb[nf]);
        }

        uint4 mwa = *(const uint4*)(pk1 + it * 4);
        uint4 mwb = *(const uint4*)(pk2 + it * 4);
        const uint32_t w1[4] = {mwa.x, mwa.y, mwa.z, mwa.w};
        const uint32_t w2[4] = {mwb.x, mwb.y, mwb.z, mwb.w};
#pragma unroll
        for (int nf = 0; nf < 16; nf++) {
            const uint32_t wa = w1[nf >> 2];
            const uint32_t wb = w2[nf >> 2];
            const int sh = (nf * 8 + (lane & 3) * 2) & 31;
            s[nf][0] = ((wa >> sh) & 1u)       ? s[nf][0] * 0.125f : -1e9f;
            s[nf][1] = ((wa >> (sh + 1)) & 1u) ? s[nf][1] * 0.125f : -1e9f;
            s[nf][2] = ((wb >> sh) & 1u)       ? s[nf][2] * 0.125f : -1e9f;
            s[nf][3] = ((wb >> (sh + 1)) & 1u) ? s[nf][3] * 0.125f : -1e9f;
        }

        float mx1 = -CUDART_INF_F, mx2 = -CUDART_INF_F;
#pragma unroll
        for (int nf = 0; nf < 16; nf++) {
            mx1 = fmaxf(mx1, fmaxf(s[nf][0], s[nf][1]));
            mx2 = fmaxf(mx2, fmaxf(s[nf][2], s[nf][3]));
        }
        mx1 = fmaxf(mx1, __shfl_xor_sync(0xffffffffu, mx1, 1));
        mx1 = fmaxf(mx1, __shfl_xor_sync(0xffffffffu, mx1, 2));
        mx2 = fmaxf(mx2, __shfl_xor_sync(0xffffffffu, mx2, 1));
        mx2 = fmaxf(mx2, __shfl_xor_sync(0xffffffffu, mx2, 2));

        const float mn1 = fmaxf(mrow1, mx1);
        const float mn2 = fmaxf(mrow2, mx2);
        const float c1 = __expf(mrow1 - mn1);
        const float c2 = __expf(mrow2 - mn2);
        mrow1 = mn1; mrow2 = mn2;

        float rs1 = 0.0f, rs2 = 0.0f;
#pragma unroll
        for (int nf = 0; nf < 16; nf++) {
            s[nf][0] = __expf(s[nf][0] - mn1); rs1 += s[nf][0];
            s[nf][1] = __expf(s[nf][1] - mn1); rs1 += s[nf][1];
            s[nf][2] = __expf(s[nf][2] - mn2); rs2 += s[nf][2];
            s[nf][3] = __expf(s[nf][3] - mn2); rs2 += s[nf][3];
        }
        rs1 += __shfl_xor_sync(0xffffffffu, rs1, 1);
        rs1 += __shfl_xor_sync(0xffffffffu, rs1, 2);
        rs2 += __shfl_xor_sync(0xffffffffu, rs2, 1);
        rs2 += __shfl_xor_sync(0xffffffffu, rs2, 2);
        lrow1 = lrow1 * c1 + rs1;
        lrow2 = lrow2 * c2 + rs2;

#pragma unroll
        for (int nf = 0; nf < 8; nf++) {
            o[nf][0] *= c1; o[nf][1] *= c1;
            o[nf][2] *= c2; o[nf][3] *= c2;
        }

        uint32_t phi[16][2], plo[16][2];
#pragma unroll
        for (int nf = 0; nf < 16; nf++) {
            __nv_bfloat16 h0 = __float2bfloat16_rn(s[nf][0]);
            __nv_bfloat16 h1 = __float2bfloat16_rn(s[nf][1]);
            __nv_bfloat16 h2 = __float2bfloat16_rn(s[nf][2]);
            __nv_bfloat16 h3 = __float2bfloat16_rn(s[nf][3]);
            phi[nf][0] = pack_bf16x2(h0, h1);
            phi[nf][1] = pack_bf16x2(h2, h3);
            plo[nf][0] = pack_bf16x2(
                __float2bfloat16_rn(s[nf][0] - __bfloat162float(h0)),
                __float2bfloat16_rn(s[nf][1] - __bfloat162float(h1)));
            plo[nf][1] = pack_bf16x2(
                __float2bfloat16_rn(s[nf][2] - __bfloat162float(h2)),
                __float2bfloat16_rn(s[nf][3] - __bfloat162float(h3)));
        }

#pragma unroll
        for (int j = 0; j < 8; j++) {
            uint32_t pa_hi[4] = {phi[2 * j][0], phi[2 * j][1],
                                 phi[2 * j + 1][0], phi[2 * j + 1][1]};
            uint32_t pa_lo[4] = {plo[2 * j][0], plo[2 * j][1],
                                 plo[2 * j + 1][0], plo[2 * j + 1][1]};
            uint32_t vb[8][2];
#pragma unroll
            for (int nf2 = 0; nf2 < 4; nf2++) {
                uint32_t r0, r1, r2, r3;
                LDSM_X4T(r0, r1, r2, r3, kb_base + 2 * AT_TILE +
                         sw128((uint32_t)((j * 16 + vRow) * 128 + (nf2 * 2 + vCh) * 16)));
                vb[2 * nf2][0] = r0; vb[2 * nf2][1] = r1;
                vb[2 * nf2 + 1][0] = r2; vb[2 * nf2 + 1][1] = r3;
            }
#pragma unroll
            for (int nf = 0; nf < 8; nf++) MMA_BF16(o[nf], pa_hi, vb[nf]);
#pragma unroll
            for (int nf = 0; nf < 8; nf++) MMA_BF16(o[nf], pa_lo, vb[nf]);
#pragma unroll
            for (int nf2 = 0; nf2 < 4; nf2++) {
                uint32_t r0, r1, r2, r3;
                LDSM_X4T(r0, r1, r2, r3, kb_base + 3 * AT_TILE +
                         sw128((uint32_t)((j * 16 + vRow) * 128 + (nf2 * 2 + vCh) * 16)));
                vb[2 * nf2][0] = r0; vb[2 * nf2][1] = r1;
                vb[2 * nf2 + 1][0] = r2; vb[2 * nf2 + 1][1] = r3;
            }
#pragma unroll
            for (int nf = 0; nf < 8; nf++) MMA_BF16(o[nf], pa_hi, vb[nf]);
        }

        __syncthreads();
    }

    const float inv1 = 1.0f / lrow1;
    const float inv2 = 1.0f / lrow2;
    const size_t rowg1 = (size_t)b * SEQL + qt * 128 + wid * 16 + (lane >> 2);
    const size_t rowg2 = rowg1 + 8;
#pragma unroll
    for (int nf = 0; nf < 8; nf++) {
        const int col = h * 64 + nf * 8 + (lane & 3) * 2;
        store_hilo2(&g_xhi[rowg1 * D_MODEL + col], &g_xlo[rowg1 * D_MODEL + col],
                    o[nf][0] * inv1, o[nf][1] * inv1);
        store_hilo2(&g_xhi[rowg2 * D_MODEL + col], &g_xlo[rowg2 * D_MODEL + col],
                    o[nf][2] * inv2, o[nf][3] * inv2);
    }
}

// ---------------------------------------------------------------------------
// Host launcher
// ---------------------------------------------------------------------------
extern "C" void kernel_launch(void* const* d_in, const int* in_sizes, int n_in,
                              void* d_out, int out_size)
{
    (void)in_sizes; (void)n_in; (void)out_size;

    const float* q    = (const float*)d_in[0];
    const float* k    = (const float*)d_in[1];
    const float* v    = (const float*)d_in[2];
    const int*   mask = (const int*)  d_in[3];
    const float* Wq   = (const float*)d_in[4];
    const float* bq   = (const float*)d_in[5];
    const float* Wk   = (const float*)d_in[6];
    const float* bk   = (const float*)d_in[7];
    const float* Wv   = (const float*)d_in[8];
    const float* bv   = (const float*)d_in[9];
    const float* Wo   = (const float*)d_in[10];
    const float* bo   = (const float*)d_in[11];
    float* out = (float*)d_out;

    void* p;
    cudaGetSymbolAddress(&p, g_qhi); __nv_bfloat16* qhi = (__nv_bfloat16*)p;
    cudaGetSymbolAddress(&p, g_qlo); __nv_bfloat16* qlo = (__nv_bfloat16*)p;
    cudaGetSymbolAddress(&p, g_khi); __nv_bfloat16* khi = (__nv_bfloat16*)p;
    cudaGetSymbolAddress(&p, g_klo); __nv_bfloat16* klo = (__nv_bfloat16*)p;
    cudaGetSymbolAddress(&p, g_vhi); __nv_bfloat16* vhi = (__nv_bfloat16*)p;
    cudaGetSymbolAddress(&p, g_vlo); __nv_bfloat16* vlo = (__nv_bfloat16*)p;
    cudaGetSymbolAddress(&p, g_xhi); __nv_bfloat16* xhi = (__nv_bfloat16*)p;
    cudaGetSymbolAddress(&p, g_xlo); __nv_bfloat16* xlo = (__nv_bfloat16*)p;
    cudaGetSymbolAddress(&p, g_whi); __nv_bfloat16* whi = (__nv_bfloat16*)p;
    cudaGetSymbolAddress(&p, g_wlo); __nv_bfloat16* wlo = (__nv_bfloat16*)p;

    cudaFuncSetAttribute(attn_mma_kernel,
                         cudaFuncAttributeMaxDynamicSharedMemorySize, AT_SMEM);
    cudaFuncSetAttribute(gemm_bf16x3_kernel,
                         cudaFuncAttributeMaxDynamicSharedMemorySize, G_SMEM);

    const int n4 = MROWS * D_MODEL / 4;
    const dim3 ggemm(D_MODEL / 128, MROWS / 128);   // (8, 64)
    const dim3 gtr(D_MODEL / 32, D_MODEL / 32);     // (32, 32)

    pack_mask_kernel<<<MROWS / 8, 256>>>(mask);

    // Q projection -> bf16 hi/lo head-split
    split_hilo_kernel<<<(n4 + 255) / 256, 256>>>(q, xhi, xlo, n4);
    split_transpose_kernel<<<gtr, 256>>>(Wq, whi, wlo);
    gemm_bf16x3_kernel<<<ggemm, 256, G_SMEM>>>(xhi, xlo, whi, wlo, bq, nullptr, qhi, qlo, 1);
    // K projection
    split_hilo_kernel<<<(n4 + 255) / 256, 256>>>(k, xhi, xlo, n4);
    split_transpose_kernel<<<gtr, 256>>>(Wk, whi, wlo);
    gemm_bf16x3_kernel<<<ggemm, 256, G_SMEM>>>(xhi, xlo, whi, wlo, bk, nullptr, khi, klo, 1);
    // V projection
    split_hilo_kernel<<<(n4 + 255) / 256, 256>>>(v, xhi, xlo, n4);
    split_transpose_kernel<<<gtr, 256>>>(Wv, whi, wlo);
    gemm_bf16x3_kernel<<<ggemm, 256, G_SMEM>>>(xhi, xlo, whi, wlo, bv, nullptr, vhi, vlo, 1);

    // Attention (writes hi/lo concat directly into g_xhi/g_xlo)
    attn_mma_kernel<<<dim3(SEQL / 128, NHEAD, BSZ), 256, AT_SMEM>>>();

    // Output projection (fp32 -> d_out)
    split_transpose_kernel<<<gtr, 256>>>(Wo, whi, wlo);
    gemm_bf16x3_kernel<<<ggemm, 256, G_SMEM>>>(xhi, xlo, whi, wlo, bo, out, nullptr, nullptr, 0);
}

// round 8
// speedup vs baseline: 2.8457x; 1.0044x over previous
#include <cuda_runtime.h>
#include <cuda_bf16.h>
#include <math_constants.h>
#include <cstdint>

// Problem constants
#define D_MODEL 1024
#define NHEAD   16
#define DK      64
#define BSZ     8
#define SEQL    1024
#define MROWS   (BSZ * SEQL)   // 8192

#define XSLICE ((size_t)MROWS * D_MODEL)
#define WSLICE ((size_t)D_MODEL * D_MODEL)

// ---------------------------------------------------------------------------
// Scratch (allocation-free: __device__ globals)
// ---------------------------------------------------------------------------
__device__ __align__(16) __nv_bfloat16 g_qhi[(size_t)BSZ * NHEAD * SEQL * DK];
__device__ __align__(16) __nv_bfloat16 g_qlo[(size_t)BSZ * NHEAD * SEQL * DK];
__device__ __align__(16) __nv_bfloat16 g_khi[(size_t)BSZ * NHEAD * SEQL * DK];
__device__ __align__(16) __nv_bfloat16 g_klo[(size_t)BSZ * NHEAD * SEQL * DK];
__device__ __align__(16) __nv_bfloat16 g_vhi[(size_t)BSZ * NHEAD * SEQL * DK];
__device__ __align__(16) __nv_bfloat16 g_vlo[(size_t)BSZ * NHEAD * SEQL * DK];
__device__ __align__(16) __nv_bfloat16 g_xhi[3 * XSLICE];   // q/k/v input splits; slice 0 reused by attn output
__device__ __align__(16) __nv_bfloat16 g_xlo[3 * XSLICE];
__device__ __align__(16) __nv_bfloat16 g_whi[4 * WSLICE];   // Wq/Wk/Wv/Wo transposed [N,K]
__device__ __align__(16) __nv_bfloat16 g_wlo[4 * WSLICE];
__device__ __align__(16) uint32_t g_pk[(size_t)BSZ * SEQL * (SEQL / 32)]; // packed mask

// ---------------------------------------------------------------------------
// PTX helpers (standard PTX only — tcgen05 is rejected by the sm_103 target)
// ---------------------------------------------------------------------------
__device__ __forceinline__ uint32_t smem_u32(const void* p) {
    uint32_t a;
    asm("{ .reg .u64 t; cvta.to.shared.u64 t, %1; cvt.u32.u64 %0, t; }"
        : "=r"(a) : "l"(p));
    return a;
}

#define LDSM_X4(r0, r1, r2, r3, addr) \
    asm volatile("ldmatrix.sync.aligned.m8n8.x4.shared.b16 {%0,%1,%2,%3}, [%4];" \
                 : "=r"(r0), "=r"(r1), "=r"(r2), "=r"(r3) : "r"(addr))

#define LDSM_X4T(r0, r1, r2, r3, addr) \
    asm volatile("ldmatrix.sync.aligned.m8n8.x4.trans.shared.b16 {%0,%1,%2,%3}, [%4];" \
                 : "=r"(r0), "=r"(r1), "=r"(r2), "=r"(r3) : "r"(addr))

#define MMA_BF16(d, a, b) \
    asm volatile("mma.sync.aligned.m16n8k16.row.col.f32.bf16.bf16.f32 " \
                 "{%0,%1,%2,%3}, {%4,%5,%6,%7}, {%8,%9}, {%0,%1,%2,%3};" \
                 : "+f"((d)[0]), "+f"((d)[1]), "+f"((d)[2]), "+f"((d)[3]) \
                 : "r"((a)[0]), "r"((a)[1]), "r"((a)[2]), "r"((a)[3]), \
                   "r"((b)[0]), "r"((b)[1]))

#define STS128(addr, v) \
    asm volatile("st.shared.v4.b32 [%0], {%1,%2,%3,%4};" \
                 :: "r"(addr), "r"((v).x), "r"((v).y), "r"((v).z), "r"((v).w) \
                 : "memory")

#define CP16(smem_addr, gptr) \
    asm volatile("cp.async.cg.shared.global [%0], [%1], 16;" \
                 :: "r"(smem_addr), "l"(gptr) : "memory")
#define CP_COMMIT() asm volatile("cp.async.commit_group;" ::: "memory")

// 64B-row swizzle (GEMM tiles)
__device__ __forceinline__ uint32_t swz(int row, int c) {
    return (uint32_t)((row << 6) + (((c ^ (row >> 1)) & 3) << 4));
}
// SW128 swizzle for 128B rows (attention tiles)
__device__ __forceinline__ uint32_t sw128(uint32_t off) {
    return off ^ ((off >> 3) & 0x70);
}

__device__ __forceinline__ uint32_t pack_bf16x2(__nv_bfloat16 lo16, __nv_bfloat16 hi16) {
    return ((uint32_t)*(const uint16_t*)&hi16 << 16) | *(const uint16_t*)&lo16;
}

// split fp32 pair into bf16 hi / lo pairs and store as packed u32
__device__ __forceinline__ void store_hilo2(__nv_bfloat16* hi, __nv_bfloat16* lo,
                                            float a, float b) {
    __nv_bfloat16 ha = __float2bfloat16_rn(a), hb = __float2bfloat16_rn(b);
    *(uint32_t*)hi = pack_bf16x2(ha, hb);
    __nv_bfloat16 la = __float2bfloat16_rn(a - __bfloat162float(ha));
    __nv_bfloat16 lb = __float2bfloat16_rn(b - __bfloat162float(hb));
    *(uint32_t*)lo = pack_bf16x2(la, lb);
}

// ---------------------------------------------------------------------------
// fp32 -> (hi,lo) bf16 split for q,k,v in ONE launch (grid.y selects input)
// ---------------------------------------------------------------------------
__global__ void split_hilo3_kernel(const float* __restrict__ q,
                                   const float* __restrict__ k,
                                   const float* __restrict__ v, int n4)
{
    const int z = blockIdx.y;
    const float* x = (z == 0) ? q : (z == 1) ? k : v;
    __nv_bfloat16* hi = g_xhi + (size_t)z * XSLICE;
    __nv_bfloat16* lo = g_xlo + (size_t)z * XSLICE;

    int i = blockIdx.x * blockDim.x + threadIdx.x;
    if (i >= n4) return;
    float4 val = ((const float4*)x)[i];
    __nv_bfloat16 h[4], l[4];
    float f[4] = {val.x, val.y, val.z, val.w};
#pragma unroll
    for (int j = 0; j < 4; j++) {
        h[j] = __float2bfloat16_rn(f[j]);
        l[j] = __float2bfloat16_rn(f[j] - __bfloat162float(h[j]));
    }
    ((uint2*)hi)[i] = *(uint2*)h;
    ((uint2*)lo)[i] = *(uint2*)l;
}

// ---------------------------------------------------------------------------
// All four W [K,N] fp32 -> Wt hi/lo [N,K] bf16 in ONE launch (grid.z selects W)
// ---------------------------------------------------------------------------
__global__ void split_transpose4_kernel(const float* __restrict__ W0,
                                        const float* __restrict__ W1,
                                        const float* __restrict__ W2,
                                        const float* __restrict__ W3)
{
    const int z = blockIdx.z;
    const float* W = (z == 0) ? W0 : (z == 1) ? W1 : (z == 2) ? W2 : W3;
    __nv_bfloat16* hi = g_whi + (size_t)z * WSLICE;
    __nv_bfloat16* lo = g_wlo + (size_t)z * WSLICE;

    __shared__ float t[32][33];
    const int kb = blockIdx.y * 32;
    const int nb = blockIdx.x * 32;
    const int tx = threadIdx.x & 31;
    const int ty = threadIdx.x >> 5;
#pragma unroll
    for (int j = 0; j < 4; j++)
        t[ty + 8 * j][tx] = W[(size_t)(kb + ty + 8 * j) * D_MODEL + nb + tx];
    __syncthreads();
#pragma unroll
    for (int j = 0; j < 4; j++) {
        float v = t[tx][ty + 8 * j];
        __nv_bfloat16 h = __float2bfloat16_rn(v);
        __nv_bfloat16 l = __float2bfloat16_rn(v - __bfloat162float(h));
        size_t o = (size_t)(nb + ty + 8 * j) * D_MODEL + kb + tx;
        hi[o] = h;
        lo[o] = l;
    }
}

// ---------------------------------------------------------------------------
// Pack mask [B,S,S] int32 -> bitmask [B,S,S/32]
// ---------------------------------------------------------------------------
__global__ void pack_mask_kernel(const int* __restrict__ mask)
{
    const int warp = (blockIdx.x * blockDim.x + threadIdx.x) >> 5;  // 0..8191
    const int lane = threadIdx.x & 31;
    const int* src = mask + (size_t)warp * SEQL;
    uint32_t* dst = g_pk + (size_t)warp * (SEQL / 32);
#pragma unroll 4
    for (int w = 0; w < 32; w++) {
        int v = src[w * 32 + lane];
        uint32_t bits = __ballot_sync(0xffffffffu, v != 0);
        if (lane == 0) dst[w] = bits;
    }
}

// ---------------------------------------------------------------------------
// Merged bf16x3-split GEMM via mma.sync: C = X*W + bias, fp32 acc.
// 3-stage cp.async circular pipeline, ONE __syncthreads per 32-wide K chunk.
// CTA 128x128, warp tile 32x64. mode 0: fp32 out; mode 1: hi/lo head-split.
// ---------------------------------------------------------------------------
#define G_AHI 0
#define G_ALO 8192
#define G_BHI 16384
#define G_BLO 24576
#define G_STAGE 32768
#define G_SMEM (3 * G_STAGE)  // 98304

__global__ __launch_bounds__(256, 2)
void gemm_bf16x3_kernel(const __nv_bfloat16* __restrict__ Ahi,
                        const __nv_bfloat16* __restrict__ Alo,
                        const __nv_bfloat16* __restrict__ Bhi,
                        const __nv_bfloat16* __restrict__ Blo,
                        const float* __restrict__ bias,
                        float* __restrict__ outf,
                        __nv_bfloat16* __restrict__ ohi,
                        __nv_bfloat16* __restrict__ olo, int mode)
{
    extern __shared__ __align__(1024) char smem[];
    const uint32_t smem_base = smem_u32(smem);

    const int tid   = threadIdx.x;
    const int wid   = tid >> 5;
    const int lane  = tid & 31;
    const int warpM = wid & 3;
    const int warpN = wid >> 2;
    const int mBase = blockIdx.y * 128;
    const int nBase = blockIdx.x * 128;

    const int j8 = lane >> 3;
    const int r8 = lane & 7;
    const int aR = warpM * 32 + r8 + (j8 & 1) * 8;
    const int aC = (j8 >> 1);
    const int bR = warpN * 64 + r8 + (j8 >> 1) * 8;
    const int bC = (j8 & 1);

    const int gRow0 = tid >> 2;   // 0..63
    const int gC    = tid & 3;    // 16B chunk within 64B row

    float acc[2][8][4];
#pragma unroll
    for (int mf = 0; mf < 2; mf++)
#pragma unroll
        for (int nf = 0; nf < 8; nf++)
#pragma unroll
            for (int e = 0; e < 4; e++) acc[mf][nf][e] = 0.0f;

    const __nv_bfloat16* Apg = Ahi + (size_t)mBase * D_MODEL;
    const __nv_bfloat16* Alg = Alo + (size_t)mBase * D_MODEL;
    const __nv_bfloat16* Bpg = Bhi + (size_t)nBase * D_MODEL;
    const __nv_bfloat16* Blg = Blo + (size_t)nBase * D_MODEL;

    // chunk loader: 4 tiles x (128 rows x 64B) via cp.async
    auto load_chunk = [&](int k0, uint32_t stage) {
#pragma unroll
        for (int i = 0; i < 2; i++) {
            const int row = gRow0 + i * 64;
            const uint32_t off = swz(row, gC);
            const size_t goA = (size_t)row * D_MODEL + k0 + gC * 8;
            CP16(stage + G_AHI + off, Apg + goA);
            CP16(stage + G_ALO + off, Alg + goA);
            CP16(stage + G_BHI + off, Bpg + goA);
            CP16(stage + G_BLO + off, Blg + goA);
        }
    };

    const int NCHUNK = D_MODEL / 32;  // 32

    load_chunk(0, smem_base + 0 * G_STAGE);
    CP_COMMIT();
    load_chunk(32, smem_base + 1 * G_STAGE);
    CP_COMMIT();

    for (int it = 0; it < NCHUNK; it++) {
        // chunk `it` complete: allow 1 pending (the it+1 prefetch), except tail
        if (it + 1 < NCHUNK) {
            asm volatile("cp.async.wait_group 1;" ::: "memory");
        } else {
            asm volatile("cp.async.wait_group 0;" ::: "memory");
        }
        __syncthreads();  // also proves all warps finished compute(it-1):
                          // stage (it+2)%3 (== stage of it-1) is safe to refill

        if (it + 2 < NCHUNK) {
            load_chunk((it + 2) * 32, smem_base + ((it + 2) % 3) * G_STAGE);
            CP_COMMIT();
        }

        const uint32_t st = smem_base + (it % 3) * G_STAGE;

#pragma unroll
        for (int kk = 0; kk < 2; kk++) {
            uint32_t afh[2][4], afl[2][4];
#pragma unroll
            for (int mf = 0; mf < 2; mf++) {
                const int row = aR + mf * 16;
                const uint32_t off = swz(row, aC + 2 * kk);
                LDSM_X4(afh[mf][0], afh[mf][1], afh[mf][2], afh[mf][3],
                        st + G_AHI + off);
                LDSM_X4(afl[mf][0], afl[mf][1], afl[mf][2], afl[mf][3],
                        st + G_ALO + off);
            }
#pragma unroll
            for (int nf2 = 0; nf2 < 4; nf2++) {
                const int row = bR + nf2 * 16;
                const uint32_t off = swz(row, bC + 2 * kk);
                uint32_t h0, h1, h2, h3, l0, l1, l2, l3;
                LDSM_X4(h0, h1, h2, h3, st + G_BHI + off);
                LDSM_X4(l0, l1, l2, l3, st + G_BLO + off);
                uint32_t bh0[2] = {h0, h1}, bh1[2] = {h2, h3};
                uint32_t bl0[2] = {l0, l1}, bl1[2] = {l2, l3};
#pragma unroll
                for (int mf = 0; mf < 2; mf++) {
                    MMA_BF16(acc[mf][2 * nf2],     afh[mf], bh0);
                    MMA_BF16(acc[mf][2 * nf2],     afl[mf], bh0);
                    MMA_BF16(acc[mf][2 * nf2],     afh[mf], bl0);
                    MMA_BF16(acc[mf][2 * nf2 + 1], afh[mf], bh1);
                    MMA_BF16(acc[mf][2 * nf2 + 1], afl[mf], bh1);
                    MMA_BF16(acc[mf][2 * nf2 + 1], afh[mf], bl1);
                }
            }
        }
    }

#pragma unroll
    for (int mf = 0; mf < 2; mf++) {
#pragma unroll
        for (int nf = 0; nf < 8; nf++) {
            const int col = nBase + warpN * 64 + nf * 8 + (lane & 3) * 2;
            const float b0 = bias[col];
            const float b1 = bias[col + 1];
#pragma unroll
            for (int half = 0; half < 2; half++) {
                const int m = mBase + warpM * 32 + mf * 16 + (lane >> 2) + half * 8;
                const float vx = acc[mf][nf][half * 2 + 0] + b0;
                const float vy = acc[mf][nf][half * 2 + 1] + b1;
                if (mode) {
                    const int bb = m >> 10;
                    const int s  = m & 1023;
                    const int h  = col >> 6;
                    const int d  = col & 63;
                    const size_t idx = (((size_t)(bb * NHEAD + h) * SEQL + s) * DK) + d;
                    store_hilo2(&ohi[idx], &olo[idx], vx, vy);
                } else {
                    float2 o2; o2.x = vx; o2.y = vy;
                    *(float2*)&outf[(size_t)m * D_MODEL + col] = o2;
                }
            }
        }
    }
}

// ---------------------------------------------------------------------------
// Tensor-core flash attention (unchanged from R7 passing version).
// CTA = (q-tile of 128 rows, head, batch), 256 threads = 8 warps.
// ---------------------------------------------------------------------------
#define AT_QHI  0
#define AT_QLO  16384
#define AT_BUF  32768
#define AT_TILE 16384
#define AT_BUFSZ 65536
#define AT_SMEM (AT_BUF + 2 * AT_BUFSZ)  // 163840

__device__ __forceinline__ void attn_load_kv(
    uint32_t dstBase,
    const __nv_bfloat16* __restrict__ khi, const __nv_bfloat16* __restrict__ klo,
    const __nv_bfloat16* __restrict__ vhi, const __nv_bfloat16* __restrict__ vlo,
    int kt, int tid)
{
#pragma unroll
    for (int i = 0; i < 4; i++) {
        const int u = tid + i * 256;
        const int row = u >> 3;
        const int c = u & 7;
        const uint32_t so = sw128((uint32_t)(row * 128 + c * 16));
        const size_t go = (size_t)(kt + row) * DK + c * 8;
        CP16(dstBase + 0 * AT_TILE + so, khi + go);
        CP16(dstBase + 1 * AT_TILE + so, klo + go);
        CP16(dstBase + 2 * AT_TILE + so, vhi + go);
        CP16(dstBase + 3 * AT_TILE + so, vlo + go);
    }
}

__global__ __launch_bounds__(256, 1) void attn_mma_kernel()
{
    extern __shared__ char sm[];
    const uint32_t sb = smem_u32(sm);
    const int tid  = threadIdx.x;
    const int wid  = tid >> 5;
    const int lane = tid & 31;
    const int qt = blockIdx.x;
    const int h  = blockIdx.y;
    const int b  = blockIdx.z;

    const size_t headOff = (size_t)(b * NHEAD + h) * SEQL * DK;
    const __nv_bfloat16* qhig = g_qhi + headOff + (size_t)qt * 128 * DK;
    const __nv_bfloat16* qlog = g_qlo + headOff + (size_t)qt * 128 * DK;
    const __nv_bfloat16* khig = g_khi + headOff;
    const __nv_bfloat16* klog = g_klo + headOff;
    const __nv_bfloat16* vhig = g_vhi + headOff;
    const __nv_bfloat16* vlog = g_vlo + headOff;

    {
#pragma unroll
        for (int i = 0; i < 4; i++) {
            const int u = tid + i * 256;
            const int row = u >> 3;
            const int c = u & 7;
            const uint32_t so = sw128((uint32_t)(row * 128 + c * 16));
            const size_t go = (size_t)row * DK + c * 8;
            uint4 vh = *(const uint4*)(qhig + go);
            STS128(sb + AT_QHI + so, vh);
            uint4 vl = *(const uint4*)(qlog + go);
            STS128(sb + AT_QLO + so, vl);
        }
    }
    attn_load_kv(sb + AT_BUF, khig, klog, vhig, vlog, 0, tid);
    CP_COMMIT();
    __syncthreads();

    const int r8 = lane & 7;
    const int j8 = lane >> 3;
    const int aRow = wid * 16 + r8 + (j8 & 1) * 8;
    const int aC0  = j8 >> 1;
    uint32_t qh[4][4], ql[4][4];
#pragma unroll
    for (int kk = 0; kk < 4; kk++) {
        const uint32_t so = sw128((uint32_t)(aRow * 128 + (aC0 + 2 * kk) * 16));
        LDSM_X4(qh[kk][0], qh[kk][1], qh[kk][2], qh[kk][3], sb + AT_QHI + so);
        LDSM_X4(ql[kk][0], ql[kk][1], ql[kk][2], ql[kk][3], sb + AT_QLO + so);
    }

    float o[8][4];
#pragma unroll
    for (int nf = 0; nf < 8; nf++)
#pragma unroll
        for (int e = 0; e < 4; e++) o[nf][e] = 0.0f;
    float mrow1 = -CUDART_INF_F, mrow2 = -CUDART_INF_F;
    float lrow1 = 0.0f, lrow2 = 0.0f;

    const int qrow1 = qt * 128 + wid * 16 + (lane >> 2);
    const uint32_t* pk1 = g_pk + ((size_t)b * SEQL + qrow1) * (SEQL / 32);
    const uint32_t* pk2 = pk1 + 8 * (SEQL / 32);

    const int bRow = r8 + (j8 >> 1) * 8;
    const int bC   = j8 & 1;
    const int vRow = lane & 15;
    const int vCh  = lane >> 4;

    for (int it = 0; it < 8; it++) {
        const int cur = it & 1;
        if (it < 7) {
            attn_load_kv(sb + AT_BUF + (cur ^ 1) * AT_BUFSZ,
                         khig, klog, vhig, vlog, (it + 1) * 128, tid);
            CP_COMMIT();
            asm volatile("cp.async.wait_group 1;" ::: "memory");
        } else {
            asm volatile("cp.async.wait_group 0;" ::: "memory");
        }
        __syncthreads();

        const uint32_t kb_base = sb + AT_BUF + cur * AT_BUFSZ;

        float s[16][4];
#pragma unroll
        for (int nf = 0; nf < 16; nf++)
#pragma unroll
            for (int e = 0; e < 4; e++) s[nf][e] = 0.0f;

#pragma unroll
        for (int kk = 0; kk < 4; kk++) {
            uint32_t kb[16][2];
#pragma unroll
            for (int nf2 = 0; nf2 < 8; nf2++) {
                uint32_t r0, r1, r2, r3;
                LDSM_X4(r0, r1, r2, r3, kb_base + 0 * AT_TILE +
                        sw128((uint32_t)((nf2 * 16 + bRow) * 128 + (bC + 2 * kk) * 16)));
                kb[2 * nf2][0] = r0; kb[2 * nf2][1] = r1;
                kb[2 * nf2 + 1][0] = r2; kb[2 * nf2 + 1][1] = r3;
            }
#pragma unroll
            for (int nf = 0; nf < 16; nf++) MMA_BF16(s[nf], qh[kk], kb[nf]);
#pragma unroll
            for (int nf = 0; nf < 16; nf++) MMA_BF16(s[nf], ql[kk], kb[nf]);
#pragma unroll
            for (int nf2 = 0; nf2 < 8; nf2++) {
                uint32_t r0, r1, r2, r3;
                LDSM_X4(r0, r1, r2, r3, kb_base + 1 * AT_TILE +
                        sw128((uint32_t)((nf2 * 16 + bRow) * 128 + (bC + 2 * kk) * 16)));
                kb[2 * nf2][0] = r0; kb[2 * nf2][1] = r1;
                kb[2 * nf2 + 1][0] = r2; kb[2 * nf2 + 1][1] = r3;
            }
#pragma unroll
            for (int nf = 0; nf < 16; nf++) MMA_BF16(s[nf], qh[kk], kb[nf]);
        }

        uint4 mwa = *(const uint4*)(pk1 + it * 4);
        uint4 mwb = *(const uint4*)(pk2 + it * 4);
        const uint32_t w1[4] = {mwa.x, mwa.y, mwa.z, mwa.w};
        const uint32_t w2[4] = {mwb.x, mwb.y, mwb.z, mwb.w};
#pragma unroll
        for (int nf = 0; nf < 16; nf++) {
            const uint32_t wa = w1[nf >> 2];
            const uint32_t wb = w2[nf >> 2];
            const int sh = (nf * 8 + (lane & 3) * 2) & 31;
            s[nf][0] = ((wa >> sh) & 1u)       ? s[nf][0] * 0.125f : -1e9f;
            s[nf][1] = ((wa >> (sh + 1)) & 1u) ? s[nf][1] * 0.125f : -1e9f;
            s[nf][2] = ((wb >> sh) & 1u)       ? s[nf][2] * 0.125f : -1e9f;
            s[nf][3] = ((wb >> (sh + 1)) & 1u) ? s[nf][3] * 0.125f : -1e9f;
        }

        float mx1 = -CUDART_INF_F, mx2 = -CUDART_INF_F;
#pragma unroll
        for (int nf = 0; nf < 16; nf++) {
            mx1 = fmaxf(mx1, fmaxf(s[nf][0], s[nf][1]));
            mx2 = fmaxf(mx2, fmaxf(s[nf][2], s[nf][3]));
        }
        mx1 = fmaxf(mx1, __shfl_xor_sync(0xffffffffu, mx1, 1));
        mx1 = fmaxf(mx1, __shfl_xor_sync(0xffffffffu, mx1, 2));
        mx2 = fmaxf(mx2, __shfl_xor_sync(0xffffffffu, mx2, 1));
        mx2 = fmaxf(mx2, __shfl_xor_sync(0xffffffffu, mx2, 2));

        const float mn1 = fmaxf(mrow1, mx1);
        const float mn2 = fmaxf(mrow2, mx2);
        const float c1 = __expf(mrow1 - mn1);
        const float c2 = __expf(mrow2 - mn2);
        mrow1 = mn1; mrow2 = mn2;

        float rs1 = 0.0f, rs2 = 0.0f;
#pragma unroll
        for (int nf = 0; nf < 16; nf++) {
            s[nf][0] = __expf(s[nf][0] - mn1); rs1 += s[nf][0];
            s[nf][1] = __expf(s[nf][1] - mn1); rs1 += s[nf][1];
            s[nf][2] = __expf(s[nf][2] - mn2); rs2 += s[nf][2];
            s[nf][3] = __expf(s[nf][3] - mn2); rs2 += s[nf][3];
        }
        rs1 += __shfl_xor_sync(0xffffffffu, rs1, 1);
        rs1 += __shfl_xor_sync(0xffffffffu, rs1, 2);
        rs2 += __shfl_xor_sync(0xffffffffu, rs2, 1);
        rs2 += __shfl_xor_sync(0xffffffffu, rs2, 2);
        lrow1 = lrow1 * c1 + rs1;
        lrow2 = lrow2 * c2 + rs2;

#pragma unroll
        for (int nf = 0; nf < 8; nf++) {
            o[nf][0] *= c1; o[nf][1] *= c1;
            o[nf][2] *= c2; o[nf][3] *= c2;
        }

        uint32_t phi[16][2], plo[16][2];
#pragma unroll
        for (int nf = 0; nf < 16; nf++) {
            __nv_bfloat16 h0 = __float2bfloat16_rn(s[nf][0]);
            __nv_bfloat16 h1 = __float2bfloat16_rn(s[nf][1]);
            __nv_bfloat16 h2 = __float2bfloat16_rn(s[nf][2]);
            __nv_bfloat16 h3 = __float2bfloat16_rn(s[nf][3]);
            phi[nf][0] = pack_bf16x2(h0, h1);
            phi[nf][1] = pack_bf16x2(h2, h3);
            plo[nf][0] = pack_bf16x2(
                __float2bfloat16_rn(s[nf][0] - __bfloat162float(h0)),
                __float2bfloat16_rn(s[nf][1] - __bfloat162float(h1)));
            plo[nf][1] = pack_bf16x2(
                __float2bfloat16_rn(s[nf][2] - __bfloat162float(h2)),
                __float2bfloat16_rn(s[nf][3] - __bfloat162float(h3)));
        }

#pragma unroll
        for (int j = 0; j < 8; j++) {
            uint32_t pa_hi[4] = {phi[2 * j][0], phi[2 * j][1],
                                 phi[2 * j + 1][0], phi[2 * j + 1][1]};
            uint32_t pa_lo[4] = {plo[2 * j][0], plo[2 * j][1],
                                 plo[2 * j + 1][0], plo[2 * j + 1][1]};
            uint32_t vb[8][2];
#pragma unroll
            for (int nf2 = 0; nf2 < 4; nf2++) {
                uint32_t r0, r1, r2, r3;
                LDSM_X4T(r0, r1, r2, r3, kb_base + 2 * AT_TILE +
                         sw128((uint32_t)((j * 16 + vRow) * 128 + (nf2 * 2 + vCh) * 16)));
                vb[2 * nf2][0] = r0; vb[2 * nf2][1] = r1;
                vb[2 * nf2 + 1][0] = r2; vb[2 * nf2 + 1][1] = r3;
            }
#pragma unroll
            for (int nf = 0; nf < 8; nf++) MMA_BF16(o[nf], pa_hi, vb[nf]);
#pragma unroll
            for (int nf = 0; nf < 8; nf++) MMA_BF16(o[nf], pa_lo, vb[nf]);
#pragma unroll
            for (int nf2 = 0; nf2 < 4; nf2++) {
                uint32_t r0, r1, r2, r3;
                LDSM_X4T(r0, r1, r2, r3, kb_base + 3 * AT_TILE +
                         sw128((uint32_t)((j * 16 + vRow) * 128 + (nf2 * 2 + vCh) * 16)));
                vb[2 * nf2][0] = r0; vb[2 * nf2][1] = r1;
                vb[2 * nf2 + 1][0] = r2; vb[2 * nf2 + 1][1] = r3;
            }
#pragma unroll
            for (int nf = 0; nf < 8; nf++) MMA_BF16(o[nf], pa_hi, vb[nf]);
        }

        __syncthreads();
    }

    const float inv1 = 1.0f / lrow1;
    const float inv2 = 1.0f / lrow2;
    const size_t rowg1 = (size_t)b * SEQL + qt * 128 + wid * 16 + (lane >> 2);
    const size_t rowg2 = rowg1 + 8;
#pragma unroll
    for (int nf = 0; nf < 8; nf++) {
        const int col = h * 64 + nf * 8 + (lane & 3) * 2;
        store_hilo2(&g_xhi[rowg1 * D_MODEL + col], &g_xlo[rowg1 * D_MODEL + col],
                    o[nf][0] * inv1, o[nf][1] * inv1);
        store_hilo2(&g_xhi[rowg2 * D_MODEL + col], &g_xlo[rowg2 * D_MODEL + col],
                    o[nf][2] * inv2, o[nf][3] * inv2);
    }
}

// ---------------------------------------------------------------------------
// Host launcher
// ---------------------------------------------------------------------------
extern "C" void kernel_launch(void* const* d_in, const int* in_sizes, int n_in,
                              void* d_out, int out_size)
{
    (void)in_sizes; (void)n_in; (void)out_size;

    const float* q    = (const float*)d_in[0];
    const float* k    = (const float*)d_in[1];
    const float* v    = (const float*)d_in[2];
    const int*   mask = (const int*)  d_in[3];
    const float* Wq   = (const float*)d_in[4];
    const float* bq   = (const float*)d_in[5];
    const float* Wk   = (const float*)d_in[6];
    const float* bk   = (const float*)d_in[7];
    const float* Wv   = (const float*)d_in[8];
    const float* bv   = (const float*)d_in[9];
    const float* Wo   = (const float*)d_in[10];
    const float* bo   = (const float*)d_in[11];
    float* out = (float*)d_out;

    void* p;
    cudaGetSymbolAddress(&p, g_qhi); __nv_bfloat16* qhi = (__nv_bfloat16*)p;
    cudaGetSymbolAddress(&p, g_qlo); __nv_bfloat16* qlo = (__nv_bfloat16*)p;
    cudaGetSymbolAddress(&p, g_khi); __nv_bfloat16* khi = (__nv_bfloat16*)p;
    cudaGetSymbolAddress(&p, g_klo); __nv_bfloat16* klo = (__nv_bfloat16*)p;
    cudaGetSymbolAddress(&p, g_vhi); __nv_bfloat16* vhi = (__nv_bfloat16*)p;
    cudaGetSymbolAddress(&p, g_vlo); __nv_bfloat16* vlo = (__nv_bfloat16*)p;
    cudaGetSymbolAddress(&p, g_xhi); __nv_bfloat16* xhi = (__nv_bfloat16*)p;
    cudaGetSymbolAddress(&p, g_xlo); __nv_bfloat16* xlo = (__nv_bfloat16*)p;
    cudaGetSymbolAddress(&p, g_whi); __nv_bfloat16* whi = (__nv_bfloat16*)p;
    cudaGetSymbolAddress(&p, g_wlo); __nv_bfloat16* wlo = (__nv_bfloat16*)p;

    cudaFuncSetAttribute(attn_mma_kernel,
                         cudaFuncAttributeMaxDynamicSharedMemorySize, AT_SMEM);
    cudaFuncSetAttribute(gemm_bf16x3_kernel,
                         cudaFuncAttributeMaxDynamicSharedMemorySize, G_SMEM);

    const int n4 = MROWS * D_MODEL / 4;
    const dim3 ggemm(D_MODEL / 128, MROWS / 128);   // (8, 64)
    const dim3 gtr(D_MODEL / 32, D_MODEL / 32, 4);  // (32, 32, 4)
    const dim3 gsplit((n4 + 255) / 256, 3);

    pack_mask_kernel<<<MROWS / 8, 256>>>(mask);
    split_hilo3_kernel<<<gsplit, 256>>>(q, k, v, n4);
    split_transpose4_kernel<<<gtr, 256>>>(Wq, Wk, Wv, Wo);

    // Projections -> bf16 hi/lo head-split
    gemm_bf16x3_kernel<<<ggemm, 256, G_SMEM>>>(
        xhi + 0 * XSLICE, xlo + 0 * XSLICE, whi + 0 * WSLICE, wlo + 0 * WSLICE,
        bq, nullptr, qhi, qlo, 1);
    gemm_bf16x3_kernel<<<ggemm, 256, G_SMEM>>>(
        xhi + 1 * XSLICE, xlo + 1 * XSLICE, whi + 1 * WSLICE, wlo + 1 * WSLICE,
        bk, nullptr, khi, klo, 1);
    gemm_bf16x3_kernel<<<ggemm, 256, G_SMEM>>>(
        xhi + 2 * XSLICE, xlo + 2 * XSLICE, whi + 2 * WSLICE, wlo + 2 * WSLICE,
        bv, nullptr, vhi, vlo, 1);

    // Attention (writes hi/lo concat into xhi/xlo slice 0)
    attn_mma_kernel<<<dim3(SEQL / 128, NHEAD, BSZ), 256, AT_SMEM>>>();

    // Output projection (fp32 -> d_out)
    gemm_bf16x3_kernel<<<ggemm, 256, G_SMEM>>>(
        xhi + 0 * XSLICE, xlo + 0 * XSLICE, whi + 3 * WSLICE, wlo + 3 * WSLICE,
        bo, out, nullptr, nullptr, 0);
}

// round 9
// speedup vs baseline: 2.8460x; 1.0001x over previous
#include <cuda_runtime.h>
#include <cuda_bf16.h>
#include <math_constants.h>
#include <cstdint>

// Problem constants
#define D_MODEL 1024
#define NHEAD   16
#define DK      64
#define BSZ     8
#define SEQL    1024
#define MROWS   (BSZ * SEQL)   // 8192

#define XSLICE ((size_t)MROWS * D_MODEL)
#define WSLICE ((size_t)D_MODEL * D_MODEL)

// ---------------------------------------------------------------------------
// Scratch (allocation-free: __device__ globals)
// ---------------------------------------------------------------------------
__device__ __align__(16) __nv_bfloat16 g_qhi[(size_t)BSZ * NHEAD * SEQL * DK];
__device__ __align__(16) __nv_bfloat16 g_qlo[(size_t)BSZ * NHEAD * SEQL * DK];
__device__ __align__(16) __nv_bfloat16 g_khi[(size_t)BSZ * NHEAD * SEQL * DK];
__device__ __align__(16) __nv_bfloat16 g_klo[(size_t)BSZ * NHEAD * SEQL * DK];
__device__ __align__(16) __nv_bfloat16 g_vhi[(size_t)BSZ * NHEAD * SEQL * DK];
__device__ __align__(16) __nv_bfloat16 g_vlo[(size_t)BSZ * NHEAD * SEQL * DK];
__device__ __align__(16) __nv_bfloat16 g_xhi[3 * XSLICE];   // q/k/v input splits; slice 0 reused by attn output
__device__ __align__(16) __nv_bfloat16 g_xlo[3 * XSLICE];
__device__ __align__(16) __nv_bfloat16 g_whi[4 * WSLICE];   // Wq/Wk/Wv/Wo transposed [N,K]
__device__ __align__(16) __nv_bfloat16 g_wlo[4 * WSLICE];
__device__ __align__(16) uint32_t g_pk[(size_t)BSZ * SEQL * (SEQL / 32)]; // packed mask

// ---------------------------------------------------------------------------
// PTX helpers (standard PTX only — tcgen05 is rejected by the sm_103 target)
// ---------------------------------------------------------------------------
__device__ __forceinline__ uint32_t smem_u32(const void* p) {
    uint32_t a;
    asm("{ .reg .u64 t; cvta.to.shared.u64 t, %1; cvt.u32.u64 %0, t; }"
        : "=r"(a) : "l"(p));
    return a;
}

#define LDSM_X4(r0, r1, r2, r3, addr) \
    asm volatile("ldmatrix.sync.aligned.m8n8.x4.shared.b16 {%0,%1,%2,%3}, [%4];" \
                 : "=r"(r0), "=r"(r1), "=r"(r2), "=r"(r3) : "r"(addr))

#define LDSM_X4T(r0, r1, r2, r3, addr) \
    asm volatile("ldmatrix.sync.aligned.m8n8.x4.trans.shared.b16 {%0,%1,%2,%3}, [%4];" \
                 : "=r"(r0), "=r"(r1), "=r"(r2), "=r"(r3) : "r"(addr))

// NOTE: non-volatile on purpose — register-only op, lets the compiler/ptxas
// interleave independent MMAs to hide dependent-accumulator latency.
#define MMA_BF16(d, a, b) \
    asm("mma.sync.aligned.m16n8k16.row.col.f32.bf16.bf16.f32 " \
        "{%0,%1,%2,%3}, {%4,%5,%6,%7}, {%8,%9}, {%0,%1,%2,%3};" \
        : "+f"((d)[0]), "+f"((d)[1]), "+f"((d)[2]), "+f"((d)[3]) \
        : "r"((a)[0]), "r"((a)[1]), "r"((a)[2]), "r"((a)[3]), \
          "r"((b)[0]), "r"((b)[1]))

#define STS128(addr, v) \
    asm volatile("st.shared.v4.b32 [%0], {%1,%2,%3,%4};" \
                 :: "r"(addr), "r"((v).x), "r"((v).y), "r"((v).z), "r"((v).w) \
                 : "memory")

#define CP16(smem_addr, gptr) \
    asm volatile("cp.async.cg.shared.global [%0], [%1], 16;" \
                 :: "r"(smem_addr), "l"(gptr) : "memory")
#define CP_COMMIT() asm volatile("cp.async.commit_group;" ::: "memory")

// 64B-row swizzle (GEMM tiles)
__device__ __forceinline__ uint32_t swz(int row, int c) {
    return (uint32_t)((row << 6) + (((c ^ (row >> 1)) & 3) << 4));
}
// SW128 swizzle for 128B rows (attention tiles)
__device__ __forceinline__ uint32_t sw128(uint32_t off) {
    return off ^ ((off >> 3) & 0x70);
}

__device__ __forceinline__ uint32_t pack_bf16x2(__nv_bfloat16 lo16, __nv_bfloat16 hi16) {
    return ((uint32_t)*(const uint16_t*)&hi16 << 16) | *(const uint16_t*)&lo16;
}

// split fp32 pair into bf16 hi / lo pairs and store as packed u32
__device__ __forceinline__ void store_hilo2(__nv_bfloat16* hi, __nv_bfloat16* lo,
                                            float a, float b) {
    __nv_bfloat16 ha = __float2bfloat16_rn(a), hb = __float2bfloat16_rn(b);
    *(uint32_t*)hi = pack_bf16x2(ha, hb);
    __nv_bfloat16 la = __float2bfloat16_rn(a - __bfloat162float(ha));
    __nv_bfloat16 lb = __float2bfloat16_rn(b - __bfloat162float(hb));
    *(uint32_t*)lo = pack_bf16x2(la, lb);
}

// ---------------------------------------------------------------------------
// fp32 -> (hi,lo) bf16 split for q,k,v in ONE launch (grid.y selects input)
// ---------------------------------------------------------------------------
__global__ void split_hilo3_kernel(const float* __restrict__ q,
                                   const float* __restrict__ k,
                                   const float* __restrict__ v, int n4)
{
    const int z = blockIdx.y;
    const float* x = (z == 0) ? q : (z == 1) ? k : v;
    __nv_bfloat16* hi = g_xhi + (size_t)z * XSLICE;
    __nv_bfloat16* lo = g_xlo + (size_t)z * XSLICE;

    int i = blockIdx.x * blockDim.x + threadIdx.x;
    if (i >= n4) return;
    float4 val = ((const float4*)x)[i];
    __nv_bfloat16 h[4], l[4];
    float f[4] = {val.x, val.y, val.z, val.w};
#pragma unroll
    for (int j = 0; j < 4; j++) {
        h[j] = __float2bfloat16_rn(f[j]);
        l[j] = __float2bfloat16_rn(f[j] - __bfloat162float(h[j]));
    }
    ((uint2*)hi)[i] = *(uint2*)h;
    ((uint2*)lo)[i] = *(uint2*)l;
}

// ---------------------------------------------------------------------------
// All four W [K,N] fp32 -> Wt hi/lo [N,K] bf16 in ONE launch (grid.z selects W)
// ---------------------------------------------------------------------------
__global__ void split_transpose4_kernel(const float* __restrict__ W0,
                                        const float* __restrict__ W1,
                                        const float* __restrict__ W2,
                                        const float* __restrict__ W3)
{
    const int z = blockIdx.z;
    const float* W = (z == 0) ? W0 : (z == 1) ? W1 : (z == 2) ? W2 : W3;
    __nv_bfloat16* hi = g_whi + (size_t)z * WSLICE;
    __nv_bfloat16* lo = g_wlo + (size_t)z * WSLICE;

    __shared__ float t[32][33];
    const int kb = blockIdx.y * 32;
    const int nb = blockIdx.x * 32;
    const int tx = threadIdx.x & 31;
    const int ty = threadIdx.x >> 5;
#pragma unroll
    for (int j = 0; j < 4; j++)
        t[ty + 8 * j][tx] = W[(size_t)(kb + ty + 8 * j) * D_MODEL + nb + tx];
    __syncthreads();
#pragma unroll
    for (int j = 0; j < 4; j++) {
        float v = t[tx][ty + 8 * j];
        __nv_bfloat16 h = __float2bfloat16_rn(v);
        __nv_bfloat16 l = __float2bfloat16_rn(v - __bfloat162float(h));
        size_t o = (size_t)(nb + ty + 8 * j) * D_MODEL + kb + tx;
        hi[o] = h;
        lo[o] = l;
    }
}

// ---------------------------------------------------------------------------
// Pack mask [B,S,S] int32 -> bitmask [B,S,S/32]
// ---------------------------------------------------------------------------
__global__ void pack_mask_kernel(const int* __restrict__ mask)
{
    const int warp = (blockIdx.x * blockDim.x + threadIdx.x) >> 5;  // 0..8191
    const int lane = threadIdx.x & 31;
    const int* src = mask + (size_t)warp * SEQL;
    uint32_t* dst = g_pk + (size_t)warp * (SEQL / 32);
#pragma unroll 4
    for (int w = 0; w < 32; w++) {
        int v = src[w * 32 + lane];
        uint32_t bits = __ballot_sync(0xffffffffu, v != 0);
        if (lane == 0) dst[w] = bits;
    }
}

// ---------------------------------------------------------------------------
// Merged bf16x3-split GEMM via mma.sync: C = X*W + bias, fp32 acc.
// 3-stage cp.async circular pipeline, ONE __syncthreads per 32-wide K chunk.
// MMAs ordered term-major inside each nf2 group so no accumulator receives
// back-to-back dependent MMAs (chain separation = 4 MMAs).
// CTA 128x128, warp tile 32x64. mode 0: fp32 out; mode 1: hi/lo head-split.
// ---------------------------------------------------------------------------
#define G_AHI 0
#define G_ALO 8192
#define G_BHI 16384
#define G_BLO 24576
#define G_STAGE 32768
#define G_SMEM (3 * G_STAGE)  // 98304

__global__ __launch_bounds__(256, 2)
void gemm_bf16x3_kernel(const __nv_bfloat16* __restrict__ Ahi,
                        const __nv_bfloat16* __restrict__ Alo,
                        const __nv_bfloat16* __restrict__ Bhi,
                        const __nv_bfloat16* __restrict__ Blo,
                        const float* __restrict__ bias,
                        float* __restrict__ outf,
                        __nv_bfloat16* __restrict__ ohi,
                        __nv_bfloat16* __restrict__ olo, int mode)
{
    extern __shared__ __align__(1024) char smem[];
    const uint32_t smem_base = smem_u32(smem);

    const int tid   = threadIdx.x;
    const int wid   = tid >> 5;
    const int lane  = tid & 31;
    const int warpM = wid & 3;
    const int warpN = wid >> 2;
    const int mBase = blockIdx.y * 128;
    const int nBase = blockIdx.x * 128;

    const int j8 = lane >> 3;
    const int r8 = lane & 7;
    const int aR = warpM * 32 + r8 + (j8 & 1) * 8;
    const int aC = (j8 >> 1);
    const int bR = warpN * 64 + r8 + (j8 >> 1) * 8;
    const int bC = (j8 & 1);

    const int gRow0 = tid >> 2;   // 0..63
    const int gC    = tid & 3;    // 16B chunk within 64B row

    float acc[2][8][4];
#pragma unroll
    for (int mf = 0; mf < 2; mf++)
#pragma unroll
        for (int nf = 0; nf < 8; nf++)
#pragma unroll
            for (int e = 0; e < 4; e++) acc[mf][nf][e] = 0.0f;

    const __nv_bfloat16* Apg = Ahi + (size_t)mBase * D_MODEL;
    const __nv_bfloat16* Alg = Alo + (size_t)mBase * D_MODEL;
    const __nv_bfloat16* Bpg = Bhi + (size_t)nBase * D_MODEL;
    const __nv_bfloat16* Blg = Blo + (size_t)nBase * D_MODEL;

    // chunk loader: 4 tiles x (128 rows x 64B) via cp.async
    auto load_chunk = [&](int k0, uint32_t stage) {
#pragma unroll
        for (int i = 0; i < 2; i++) {
            const int row = gRow0 + i * 64;
            const uint32_t off = swz(row, gC);
            const size_t goA = (size_t)row * D_MODEL + k0 + gC * 8;
            CP16(stage + G_AHI + off, Apg + goA);
            CP16(stage + G_ALO + off, Alg + goA);
            CP16(stage + G_BHI + off, Bpg + goA);
            CP16(stage + G_BLO + off, Blg + goA);
        }
    };

    const int NCHUNK = D_MODEL / 32;  // 32

    load_chunk(0, smem_base + 0 * G_STAGE);
    CP_COMMIT();
    load_chunk(32, smem_base + 1 * G_STAGE);
    CP_COMMIT();

    for (int it = 0; it < NCHUNK; it++) {
        if (it + 1 < NCHUNK) {
            asm volatile("cp.async.wait_group 1;" ::: "memory");
        } else {
            asm volatile("cp.async.wait_group 0;" ::: "memory");
        }
        __syncthreads();  // proves all warps finished compute(it-1):
                          // stage (it+2)%3 (== stage of it-1) is safe to refill

        if (it + 2 < NCHUNK) {
            load_chunk((it + 2) * 32, smem_base + ((it + 2) % 3) * G_STAGE);
            CP_COMMIT();
        }

        const uint32_t st = smem_base + (it % 3) * G_STAGE;

#pragma unroll
        for (int kk = 0; kk < 2; kk++) {
            uint32_t afh[2][4], afl[2][4];
#pragma unroll
            for (int mf = 0; mf < 2; mf++) {
                const int row = aR + mf * 16;
                const uint32_t off = swz(row, aC + 2 * kk);
                LDSM_X4(afh[mf][0], afh[mf][1], afh[mf][2], afh[mf][3],
                        st + G_AHI + off);
                LDSM_X4(afl[mf][0], afl[mf][1], afl[mf][2], afl[mf][3],
                        st + G_ALO + off);
            }
#pragma unroll
            for (int nf2 = 0; nf2 < 4; nf2++) {
                const int row = bR + nf2 * 16;
                const uint32_t off = swz(row, bC + 2 * kk);
                uint32_t h0, h1, h2, h3, l0, l1, l2, l3;
                LDSM_X4(h0, h1, h2, h3, st + G_BHI + off);
                LDSM_X4(l0, l1, l2, l3, st + G_BLO + off);
                uint32_t bh0[2] = {h0, h1}, bh1[2] = {h2, h3};
                uint32_t bl0[2] = {l0, l1}, bl1[2] = {l2, l3};
                // term-major: each accumulator revisited only every 4 MMAs
                // hh
                MMA_BF16(acc[0][2 * nf2],     afh[0], bh0);
                MMA_BF16(acc[0][2 * nf2 + 1], afh[0], bh1);
                MMA_BF16(acc[1][2 * nf2],     afh[1], bh0);
                MMA_BF16(acc[1][2 * nf2 + 1], afh[1], bh1);
                // lh
                MMA_BF16(acc[0][2 * nf2],     afl[0], bh0);
                MMA_BF16(acc[0][2 * nf2 + 1], afl[0], bh1);
                MMA_BF16(acc[1][2 * nf2],     afl[1], bh0);
                MMA_BF16(acc[1][2 * nf2 + 1], afl[1], bh1);
                // hl
                MMA_BF16(acc[0][2 * nf2],     afh[0], bl0);
                MMA_BF16(acc[0][2 * nf2 + 1], afh[0], bl1);
                MMA_BF16(acc[1][2 * nf2],     afh[1], bl0);
                MMA_BF16(acc[1][2 * nf2 + 1], afh[1], bl1);
            }
        }
    }

#pragma unroll
    for (int mf = 0; mf < 2; mf++) {
#pragma unroll
        for (int nf = 0; nf < 8; nf++) {
            const int col = nBase + warpN * 64 + nf * 8 + (lane & 3) * 2;
            const float b0 = bias[col];
            const float b1 = bias[col + 1];
#pragma unroll
            for (int half = 0; half < 2; half++) {
                const int m = mBase + warpM * 32 + mf * 16 + (lane >> 2) + half * 8;
                const float vx = acc[mf][nf][half * 2 + 0] + b0;
                const float vy = acc[mf][nf][half * 2 + 1] + b1;
                if (mode) {
                    const int bb = m >> 10;
                    const int s  = m & 1023;
                    const int h  = col >> 6;
                    const int d  = col & 63;
                    const size_t idx = (((size_t)(bb * NHEAD + h) * SEQL + s) * DK) + d;
                    store_hilo2(&ohi[idx], &olo[idx], vx, vy);
                } else {
                    float2 o2; o2.x = vx; o2.y = vy;
                    *(float2*)&outf[(size_t)m * D_MODEL + col] = o2;
                }
            }
        }
    }
}

// ---------------------------------------------------------------------------
// Tensor-core flash attention (unchanged from R8 passing version).
// CTA = (q-tile of 128 rows, head, batch), 256 threads = 8 warps.
// ---------------------------------------------------------------------------
#define AT_QHI  0
#define AT_QLO  16384
#define AT_BUF  32768
#define AT_TILE 16384
#define AT_BUFSZ 65536
#define AT_SMEM (AT_BUF + 2 * AT_BUFSZ)  // 163840

__device__ __forceinline__ void attn_load_kv(
    uint32_t dstBase,
    const __nv_bfloat16* __restrict__ khi, const __nv_bfloat16* __restrict__ klo,
    const __nv_bfloat16* __restrict__ vhi, const __nv_bfloat16* __restrict__ vlo,
    int kt, int tid)
{
#pragma unroll
    for (int i = 0; i < 4; i++) {
        const int u = tid + i * 256;
        const int row = u >> 3;
        const int c = u & 7;
        const uint32_t so = sw128((uint32_t)(row * 128 + c * 16));
        const size_t go = (size_t)(kt + row) * DK + c * 8;
        CP16(dstBase + 0 * AT_TILE + so, khi + go);
        CP16(dstBase + 1 * AT_TILE + so, klo + go);
        CP16(dstBase + 2 * AT_TILE + so, vhi + go);
        CP16(dstBase + 3 * AT_TILE + so, vlo + go);
    }
}

__global__ __launch_bounds__(256, 1) void attn_mma_kernel()
{
    extern __shared__ char sm[];
    const uint32_t sb = smem_u32(sm);
    const int tid  = threadIdx.x;
    const int wid  = tid >> 5;
    const int lane = tid & 31;
    const int qt = blockIdx.x;
    const int h  = blockIdx.y;
    const int b  = blockIdx.z;

    const size_t headOff = (size_t)(b * NHEAD + h) * SEQL * DK;
    const __nv_bfloat16* qhig = g_qhi + headOff + (size_t)qt * 128 * DK;
    const __nv_bfloat16* qlog = g_qlo + headOff + (size_t)qt * 128 * DK;
    const __nv_bfloat16* khig = g_khi + headOff;
    const __nv_bfloat16* klog = g_klo + headOff;
    const __nv_bfloat16* vhig = g_vhi + headOff;
    const __nv_bfloat16* vlog = g_vlo + headOff;

    {
#pragma unroll
        for (int i = 0; i < 4; i++) {
            const int u = tid + i * 256;
            const int row = u >> 3;
            const int c = u & 7;
            const uint32_t so = sw128((uint32_t)(row * 128 + c * 16));
            const size_t go = (size_t)row * DK + c * 8;
            uint4 vh = *(const uint4*)(qhig + go);
            STS128(sb + AT_QHI + so, vh);
            uint4 vl = *(const uint4*)(qlog + go);
            STS128(sb + AT_QLO + so, vl);
        }
    }
    attn_load_kv(sb + AT_BUF, khig, klog, vhig, vlog, 0, tid);
    CP_COMMIT();
    __syncthreads();

    const int r8 = lane & 7;
    const int j8 = lane >> 3;
    const int aRow = wid * 16 + r8 + (j8 & 1) * 8;
    const int aC0  = j8 >> 1;
    uint32_t qh[4][4], ql[4][4];
#pragma unroll
    for (int kk = 0; kk < 4; kk++) {
        const uint32_t so = sw128((uint32_t)(aRow * 128 + (aC0 + 2 * kk) * 16));
        LDSM_X4(qh[kk][0], qh[kk][1], qh[kk][2], qh[kk][3], sb + AT_QHI + so);
        LDSM_X4(ql[kk][0], ql[kk][1], ql[kk][2], ql[kk][3], sb + AT_QLO + so);
    }

    float o[8][4];
#pragma unroll
    for (int nf = 0; nf < 8; nf++)
#pragma unroll
        for (int e = 0; e < 4; e++) o[nf][e] = 0.0f;
    float mrow1 = -CUDART_INF_F, mrow2 = -CUDART_INF_F;
    float lrow1 = 0.0f, lrow2 = 0.0f;

    const int qrow1 = qt * 128 + wid * 16 + (lane >> 2);
    const uint32_t* pk1 = g_pk + ((size_t)b * SEQL + qrow1) * (SEQL / 32);
    const uint32_t* pk2 = pk1 + 8 * (SEQL / 32);

    const int bRow = r8 + (j8 >> 1) * 8;
    const int bC   = j8 & 1;
    const int vRow = lane & 15;
    const int vCh  = lane >> 4;

    for (int it = 0; it < 8; it++) {
        const int cur = it & 1;
        if (it < 7) {
            attn_load_kv(sb + AT_BUF + (cur ^ 1) * AT_BUFSZ,
                         khig, klog, vhig, vlog, (it + 1) * 128, tid);
            CP_COMMIT();
            asm volatile("cp.async.wait_group 1;" ::: "memory");
        } else {
            asm volatile("cp.async.wait_group 0;" ::: "memory");
        }
        __syncthreads();

        const uint32_t kb_base = sb + AT_BUF + cur * AT_BUFSZ;

        float s[16][4];
#pragma unroll
        for (int nf = 0; nf < 16; nf++)
#pragma unroll
            for (int e = 0; e < 4; e++) s[nf][e] = 0.0f;

#pragma unroll
        for (int kk = 0; kk < 4; kk++) {
            uint32_t kb[16][2];
#pragma unroll
            for (int nf2 = 0; nf2 < 8; nf2++) {
                uint32_t r0, r1, r2, r3;
                LDSM_X4(r0, r1, r2, r3, kb_base + 0 * AT_TILE +
                        sw128((uint32_t)((nf2 * 16 + bRow) * 128 + (bC + 2 * kk) * 16)));
                kb[2 * nf2][0] = r0; kb[2 * nf2][1] = r1;
                kb[2 * nf2 + 1][0] = r2; kb[2 * nf2 + 1][1] = r3;
            }
#pragma unroll
            for (int nf = 0; nf < 16; nf++) MMA_BF16(s[nf], qh[kk], kb[nf]);
#pragma unroll
            for (int nf = 0; nf < 16; nf++) MMA_BF16(s[nf], ql[kk], kb[nf]);
#pragma unroll
            for (int nf2 = 0; nf2 < 8; nf2++) {
                uint32_t r0, r1, r2, r3;
                LDSM_X4(r0, r1, r2, r3, kb_base + 1 * AT_TILE +
                        sw128((uint32_t)((nf2 * 16 + bRow) * 128 + (bC + 2 * kk) * 16)));
                kb[2 * nf2][0] = r0; kb[2 * nf2][1] = r1;
                kb[2 * nf2 + 1][0] = r2; kb[2 * nf2 + 1][1] = r3;
            }
#pragma unroll
            for (int nf = 0; nf < 16; nf++) MMA_BF16(s[nf], qh[kk], kb[nf]);
        }

        uint4 mwa = *(const uint4*)(pk1 + it * 4);
        uint4 mwb = *(const uint4*)(pk2 + it * 4);
        const uint32_t w1[4] = {mwa.x, mwa.y, mwa.z, mwa.w};
        const uint32_t w2[4] = {mwb.x, mwb.y, mwb.z, mwb.w};
#pragma unroll
        for (int nf = 0; nf < 16; nf++) {
            const uint32_t wa = w1[nf >> 2];
            const uint32_t wb = w2[nf >> 2];
            const int sh = (nf * 8 + (lane & 3) * 2) & 31;
            s[nf][0] = ((wa >> sh) & 1u)       ? s[nf][0] * 0.125f : -1e9f;
            s[nf][1] = ((wa >> (sh + 1)) & 1u) ? s[nf][1] * 0.125f : -1e9f;
            s[nf][2] = ((wb >> sh) & 1u)       ? s[nf][2] * 0.125f : -1e9f;
            s[nf][3] = ((wb >> (sh + 1)) & 1u) ? s[nf][3] * 0.125f : -1e9f;
        }

        float mx1 = -CUDART_INF_F, mx2 = -CUDART_INF_F;
#pragma unroll
        for (int nf = 0; nf < 16; nf++) {
            mx1 = fmaxf(mx1, fmaxf(s[nf][0], s[nf][1]));
            mx2 = fmaxf(mx2, fmaxf(s[nf][2], s[nf][3]));
        }
        mx1 = fmaxf(mx1, __shfl_xor_sync(0xffffffffu, mx1, 1));
        mx1 = fmaxf(mx1, __shfl_xor_sync(0xffffffffu, mx1, 2));
        mx2 = fmaxf(mx2, __shfl_xor_sync(0xffffffffu, mx2, 1));
        mx2 = fmaxf(mx2, __shfl_xor_sync(0xffffffffu, mx2, 2));

        const float mn1 = fmaxf(mrow1, mx1);
        const float mn2 = fmaxf(mrow2, mx2);
        const float c1 = __expf(mrow1 - mn1);
        const float c2 = __expf(mrow2 - mn2);
        mrow1 = mn1; mrow2 = mn2;

        float rs1 = 0.0f, rs2 = 0.0f;
#pragma unroll
        for (int nf = 0; nf < 16; nf++) {
            s[nf][0] = __expf(s[nf][0] - mn1); rs1 += s[nf][0];
            s[nf][1] = __expf(s[nf][1] - mn1); rs1 += s[nf][1];
            s[nf][2] = __expf(s[nf][2] - mn2); rs2 += s[nf][2];
            s[nf][3] = __expf(s[nf][3] - mn2); rs2 += s[nf][3];
        }
        rs1 += __shfl_xor_sync(0xffffffffu, rs1, 1);
        rs1 += __shfl_xor_sync(0xffffffffu, rs1, 2);
        rs2 += __shfl_xor_sync(0xffffffffu, rs2, 1);
        rs2 += __shfl_xor_sync(0xffffffffu, rs2, 2);
        lrow1 = lrow1 * c1 + rs1;
        lrow2 = lrow2 * c2 + rs2;

#pragma unroll
        for (int nf = 0; nf < 8; nf++) {
            o[nf][0] *= c1; o[nf][1] *= c1;
            o[nf][2] *= c2; o[nf][3] *= c2;
        }

        uint32_t phi[16][2], plo[16][2];
#pragma unroll
        for (int nf = 0; nf < 16; nf++) {
            __nv_bfloat16 h0 = __float2bfloat16_rn(s[nf][0]);
            __nv_bfloat16 h1 = __float2bfloat16_rn(s[nf][1]);
            __nv_bfloat16 h2 = __float2bfloat16_rn(s[nf][2]);
            __nv_bfloat16 h3 = __float2bfloat16_rn(s[nf][3]);
            phi[nf][0] = pack_bf16x2(h0, h1);
            phi[nf][1] = pack_bf16x2(h2, h3);
            plo[nf][0] = pack_bf16x2(
                __float2bfloat16_rn(s[nf][0] - __bfloat162float(h0)),
                __float2bfloat16_rn(s[nf][1] - __bfloat162float(h1)));
            plo[nf][1] = pack_bf16x2(
                __float2bfloat16_rn(s[nf][2] - __bfloat162float(h2)),
                __float2bfloat16_rn(s[nf][3] - __bfloat162float(h3)));
        }

#pragma unroll
        for (int j = 0; j < 8; j++) {
            uint32_t pa_hi[4] = {phi[2 * j][0], phi[2 * j][1],
                                 phi[2 * j + 1][0], phi[2 * j + 1][1]};
            uint32_t pa_lo[4] = {plo[2 * j][0], plo[2 * j][1],
                                 plo[2 * j + 1][0], plo[2 * j + 1][1]};
            uint32_t vb[8][2];
#pragma unroll
            for (int nf2 = 0; nf2 < 4; nf2++) {
                uint32_t r0, r1, r2, r3;
                LDSM_X4T(r0, r1, r2, r3, kb_base + 2 * AT_TILE +
                         sw128((uint32_t)((j * 16 + vRow) * 128 + (nf2 * 2 + vCh) * 16)));
                vb[2 * nf2][0] = r0; vb[2 * nf2][1] = r1;
                vb[2 * nf2 + 1][0] = r2; vb[2 * nf2 + 1][1] = r3;
            }
#pragma unroll
            for (int nf = 0; nf < 8; nf++) MMA_BF16(o[nf], pa_hi, vb[nf]);
#pragma unroll
            for (int nf = 0; nf < 8; nf++) MMA_BF16(o[nf], pa_lo, vb[nf]);
#pragma unroll
            for (int nf2 = 0; nf2 < 4; nf2++) {
                uint32_t r0, r1, r2, r3;
                LDSM_X4T(r0, r1, r2, r3, kb_base + 3 * AT_TILE +
                         sw128((uint32_t)((j * 16 + vRow) * 128 + (nf2 * 2 + vCh) * 16)));
                vb[2 * nf2][0] = r0; vb[2 * nf2][1] = r1;
                vb[2 * nf2 + 1][0] = r2; vb[2 * nf2 + 1][1] = r3;
            }
#pragma unroll
            for (int nf = 0; nf < 8; nf++) MMA_BF16(o[nf], pa_hi, vb[nf]);
        }

        __syncthreads();
    }

    const float inv1 = 1.0f / lrow1;
    const float inv2 = 1.0f / lrow2;
    const size_t rowg1 = (size_t)b * SEQL + qt * 128 + wid * 16 + (lane >> 2);
    const size_t rowg2 = rowg1 + 8;
#pragma unroll
    for (int nf = 0; nf < 8; nf++) {
        const int col = h * 64 + nf * 8 + (lane & 3) * 2;
        store_hilo2(&g_xhi[rowg1 * D_MODEL + col], &g_xlo[rowg1 * D_MODEL + col],
                    o[nf][0] * inv1, o[nf][1] * inv1);
        store_hilo2(&g_xhi[rowg2 * D_MODEL + col], &g_xlo[rowg2 * D_MODEL + col],
                    o[nf][2] * inv2, o[nf][3] * inv2);
    }
}

// ---------------------------------------------------------------------------
// Host launcher
// ---------------------------------------------------------------------------
extern "C" void kernel_launch(void* const* d_in, const int* in_sizes, int n_in,
                              void* d_out, int out_size)
{
    (void)in_sizes; (void)n_in; (void)out_size;

    const float* q    = (const float*)d_in[0];
    const float* k    = (const float*)d_in[1];
    const float* v    = (const float*)d_in[2];
    const int*   mask = (const int*)  d_in[3];
    const float* Wq   = (const float*)d_in[4];
    const float* bq   = (const float*)d_in[5];
    const float* Wk   = (const float*)d_in[6];
    const float* bk   = (const float*)d_in[7];
    const float* Wv   = (const float*)d_in[8];
    const float* bv   = (const float*)d_in[9];
    const float* Wo   = (const float*)d_in[10];
    const float* bo   = (const float*)d_in[11];
    float* out = (float*)d_out;

    void* p;
    cudaGetSymbolAddress(&p, g_qhi); __nv_bfloat16* qhi = (__nv_bfloat16*)p;
    cudaGetSymbolAddress(&p, g_qlo); __nv_bfloat16* qlo = (__nv_bfloat16*)p;
    cudaGetSymbolAddress(&p, g_khi); __nv_bfloat16* khi = (__nv_bfloat16*)p;
    cudaGetSymbolAddress(&p, g_klo); __nv_bfloat16* klo = (__nv_bfloat16*)p;
    cudaGetSymbolAddress(&p, g_vhi); __nv_bfloat16* vhi = (__nv_bfloat16*)p;
    cudaGetSymbolAddress(&p, g_vlo); __nv_bfloat16* vlo = (__nv_bfloat16*)p;
    cudaGetSymbolAddress(&p, g_xhi); __nv_bfloat16* xhi = (__nv_bfloat16*)p;
    cudaGetSymbolAddress(&p, g_xlo); __nv_bfloat16* xlo = (__nv_bfloat16*)p;
    cudaGetSymbolAddress(&p, g_whi); __nv_bfloat16* whi = (__nv_bfloat16*)p;
    cudaGetSymbolAddress(&p, g_wlo); __nv_bfloat16* wlo = (__nv_bfloat16*)p;

    cudaFuncSetAttribute(attn_mma_kernel,
                         cudaFuncAttributeMaxDynamicSharedMemorySize, AT_SMEM);
    cudaFuncSetAttribute(gemm_bf16x3_kernel,
                         cudaFuncAttributeMaxDynamicSharedMemorySize, G_SMEM);

    const int n4 = MROWS * D_MODEL / 4;
    const dim3 ggemm(D_MODEL / 128, MROWS / 128);   // (8, 64)
    const dim3 gtr(D_MODEL / 32, D_MODEL / 32, 4);  // (32, 32, 4)
    const dim3 gsplit((n4 + 255) / 256, 3);

    pack_mask_kernel<<<MROWS / 8, 256>>>(mask);
    split_hilo3_kernel<<<gsplit, 256>>>(q, k, v, n4);
    split_transpose4_kernel<<<gtr, 256>>>(Wq, Wk, Wv, Wo);

    // Projections -> bf16 hi/lo head-split
    gemm_bf16x3_kernel<<<ggemm, 256, G_SMEM>>>(
        xhi + 0 * XSLICE, xlo + 0 * XSLICE, whi + 0 * WSLICE, wlo + 0 * WSLICE,
        bq, nullptr, qhi, qlo, 1);
    gemm_bf16x3_kernel<<<ggemm, 256, G_SMEM>>>(
        xhi + 1 * XSLICE, xlo + 1 * XSLICE, whi + 1 * WSLICE, wlo + 1 * WSLICE,
        bk, nullptr, khi, klo, 1);
    gemm_bf16x3_kernel<<<ggemm, 256, G_SMEM>>>(
        xhi + 2 * XSLICE, xlo + 2 * XSLICE, whi + 2 * WSLICE, wlo + 2 * WSLICE,
        bv, nullptr, vhi, vlo, 1);

    // Attention (writes hi/lo concat into xhi/xlo slice 0)
    attn_mma_kernel<<<dim3(SEQL / 128, NHEAD, BSZ), 256, AT_SMEM>>>();

    // Output projection (fp32 -> d_out)
    gemm_bf16x3_kernel<<<ggemm, 256, G_SMEM>>>(
        xhi + 0 * XSLICE, xlo + 0 * XSLICE, whi + 3 * WSLICE, wlo + 3 * WSLICE,
        bo, out, nullptr, nullptr, 0);
}

// round 10
// speedup vs baseline: 2.9440x; 1.0345x over previous
#include <cuda_runtime.h>
#include <cuda_bf16.h>
#include <math_constants.h>
#include <cstdint>

// Problem constants
#define D_MODEL 1024
#define NHEAD   16
#define DK      64
#define BSZ     8
#define SEQL    1024
#define MROWS   (BSZ * SEQL)   // 8192

#define XSLICE ((size_t)MROWS * D_MODEL)
#define WSLICE ((size_t)D_MODEL * D_MODEL)

// ---------------------------------------------------------------------------
// Scratch (allocation-free: __device__ globals)
// ---------------------------------------------------------------------------
__device__ __align__(16) __nv_bfloat16 g_qhi[(size_t)BSZ * NHEAD * SEQL * DK];
__device__ __align__(16) __nv_bfloat16 g_qlo[(size_t)BSZ * NHEAD * SEQL * DK];
__device__ __align__(16) __nv_bfloat16 g_khi[(size_t)BSZ * NHEAD * SEQL * DK];
__device__ __align__(16) __nv_bfloat16 g_klo[(size_t)BSZ * NHEAD * SEQL * DK];
__device__ __align__(16) __nv_bfloat16 g_vhi[(size_t)BSZ * NHEAD * SEQL * DK];
__device__ __align__(16) __nv_bfloat16 g_vlo[(size_t)BSZ * NHEAD * SEQL * DK];
__device__ __align__(16) __nv_bfloat16 g_xhi[3 * XSLICE];   // q/k/v input splits; slice 0 reused by attn output
__device__ __align__(16) __nv_bfloat16 g_xlo[3 * XSLICE];
__device__ __align__(16) __nv_bfloat16 g_whi[4 * WSLICE];   // Wq/Wk/Wv/Wo transposed [N,K]
__device__ __align__(16) __nv_bfloat16 g_wlo[4 * WSLICE];
__device__ __align__(16) uint32_t g_pk[(size_t)BSZ * SEQL * (SEQL / 32)]; // packed mask

// ---------------------------------------------------------------------------
// PTX helpers (standard PTX only — tcgen05 is rejected by the sm_103 target)
// ---------------------------------------------------------------------------
__device__ __forceinline__ uint32_t smem_u32(const void* p) {
    uint32_t a;
    asm("{ .reg .u64 t; cvta.to.shared.u64 t, %1; cvt.u32.u64 %0, t; }"
        : "=r"(a) : "l"(p));
    return a;
}

#define LDSM_X4(r0, r1, r2, r3, addr) \
    asm volatile("ldmatrix.sync.aligned.m8n8.x4.shared.b16 {%0,%1,%2,%3}, [%4];" \
                 : "=r"(r0), "=r"(r1), "=r"(r2), "=r"(r3) : "r"(addr))

#define LDSM_X4T(r0, r1, r2, r3, addr) \
    asm volatile("ldmatrix.sync.aligned.m8n8.x4.trans.shared.b16 {%0,%1,%2,%3}, [%4];" \
                 : "=r"(r0), "=r"(r1), "=r"(r2), "=r"(r3) : "r"(addr))

#define MMA_BF16(d, a, b) \
    asm("mma.sync.aligned.m16n8k16.row.col.f32.bf16.bf16.f32 " \
        "{%0,%1,%2,%3}, {%4,%5,%6,%7}, {%8,%9}, {%0,%1,%2,%3};" \
        : "+f"((d)[0]), "+f"((d)[1]), "+f"((d)[2]), "+f"((d)[3]) \
        : "r"((a)[0]), "r"((a)[1]), "r"((a)[2]), "r"((a)[3]), \
          "r"((b)[0]), "r"((b)[1]))

#define STS128(addr, v) \
    asm volatile("st.shared.v4.b32 [%0], {%1,%2,%3,%4};" \
                 :: "r"(addr), "r"((v).x), "r"((v).y), "r"((v).z), "r"((v).w) \
                 : "memory")

#define CP16(smem_addr, gptr) \
    asm volatile("cp.async.cg.shared.global [%0], [%1], 16;" \
                 :: "r"(smem_addr), "l"(gptr) : "memory")
#define CP_COMMIT() asm volatile("cp.async.commit_group;" ::: "memory")

// 64B-row swizzle (GEMM tiles)
__device__ __forceinline__ uint32_t swz(int row, int c) {
    return (uint32_t)((row << 6) + (((c ^ (row >> 1)) & 3) << 4));
}
// SW128 swizzle for 128B rows (attention tiles)
__device__ __forceinline__ uint32_t sw128(uint32_t off) {
    return off ^ ((off >> 3) & 0x70);
}

__device__ __forceinline__ uint32_t pack_bf16x2(__nv_bfloat16 lo16, __nv_bfloat16 hi16) {
    return ((uint32_t)*(const uint16_t*)&hi16 << 16) | *(const uint16_t*)&lo16;
}

// split fp32 pair into bf16 hi / lo pairs and store as packed u32
__device__ __forceinline__ void store_hilo2(__nv_bfloat16* hi, __nv_bfloat16* lo,
                                            float a, float b) {
    __nv_bfloat16 ha = __float2bfloat16_rn(a), hb = __float2bfloat16_rn(b);
    *(uint32_t*)hi = pack_bf16x2(ha, hb);
    __nv_bfloat16 la = __float2bfloat16_rn(a - __bfloat162float(ha));
    __nv_bfloat16 lb = __float2bfloat16_rn(b - __bfloat162float(hb));
    *(uint32_t*)lo = pack_bf16x2(la, lb);
}

// ---------------------------------------------------------------------------
// fp32 -> (hi,lo) bf16 split for q,k,v in ONE launch (grid.y selects input)
// ---------------------------------------------------------------------------
__global__ void split_hilo3_kernel(const float* __restrict__ q,
                                   const float* __restrict__ k,
                                   const float* __restrict__ v, int n4)
{
    const int z = blockIdx.y;
    const float* x = (z == 0) ? q : (z == 1) ? k : v;
    __nv_bfloat16* hi = g_xhi + (size_t)z * XSLICE;
    __nv_bfloat16* lo = g_xlo + (size_t)z * XSLICE;

    int i = blockIdx.x * blockDim.x + threadIdx.x;
    if (i >= n4) return;
    float4 val = ((const float4*)x)[i];
    __nv_bfloat16 h[4], l[4];
    float f[4] = {val.x, val.y, val.z, val.w};
#pragma unroll
    for (int j = 0; j < 4; j++) {
        h[j] = __float2bfloat16_rn(f[j]);
        l[j] = __float2bfloat16_rn(f[j] - __bfloat162float(h[j]));
    }
    ((uint2*)hi)[i] = *(uint2*)h;
    ((uint2*)lo)[i] = *(uint2*)l;
}

// ---------------------------------------------------------------------------
// All four W [K,N] fp32 -> Wt hi/lo [N,K] bf16 in ONE launch (grid.z selects W)
// ---------------------------------------------------------------------------
__global__ void split_transpose4_kernel(const float* __restrict__ W0,
                                        const float* __restrict__ W1,
                                        const float* __restrict__ W2,
                                        const float* __restrict__ W3)
{
    const int z = blockIdx.z;
    const float* W = (z == 0) ? W0 : (z == 1) ? W1 : (z == 2) ? W2 : W3;
    __nv_bfloat16* hi = g_whi + (size_t)z * WSLICE;
    __nv_bfloat16* lo = g_wlo + (size_t)z * WSLICE;

    __shared__ float t[32][33];
    const int kb = blockIdx.y * 32;
    const int nb = blockIdx.x * 32;
    const int tx = threadIdx.x & 31;
    const int ty = threadIdx.x >> 5;
#pragma unroll
    for (int j = 0; j < 4; j++)
        t[ty + 8 * j][tx] = W[(size_t)(kb + ty + 8 * j) * D_MODEL + nb + tx];
    __syncthreads();
#pragma unroll
    for (int j = 0; j < 4; j++) {
        float v = t[tx][ty + 8 * j];
        __nv_bfloat16 h = __float2bfloat16_rn(v);
        __nv_bfloat16 l = __float2bfloat16_rn(v - __bfloat162float(h));
        size_t o = (size_t)(nb + ty + 8 * j) * D_MODEL + kb + tx;
        hi[o] = h;
        lo[o] = l;
    }
}

// ---------------------------------------------------------------------------
// Pack mask [B,S,S] int32 -> bitmask [B,S,S/32]
// ---------------------------------------------------------------------------
__global__ void pack_mask_kernel(const int* __restrict__ mask)
{
    const int warp = (blockIdx.x * blockDim.x + threadIdx.x) >> 5;  // 0..8191
    const int lane = threadIdx.x & 31;
    const int* src = mask + (size_t)warp * SEQL;
    uint32_t* dst = g_pk + (size_t)warp * (SEQL / 32);
#pragma unroll 4
    for (int w = 0; w < 32; w++) {
        int v = src[w * 32 + lane];
        uint32_t bits = __ballot_sync(0xffffffffu, v != 0);
        if (lane == 0) dst[w] = bits;
    }
}

// ---------------------------------------------------------------------------
// Merged bf16x3-split GEMM via mma.sync (frozen at R7 structure — at the
// measured ~360 TF/s mma.sync ceiling).
// ---------------------------------------------------------------------------
#define G_AHI 0
#define G_ALO 8192
#define G_BHI 16384
#define G_BLO 24576
#define G_STAGE 32768
#define G_SMEM (3 * G_STAGE)  // 98304

__global__ __launch_bounds__(256, 2)
void gemm_bf16x3_kernel(const __nv_bfloat16* __restrict__ Ahi,
                        const __nv_bfloat16* __restrict__ Alo,
                        const __nv_bfloat16* __restrict__ Bhi,
                        const __nv_bfloat16* __restrict__ Blo,
                        const float* __restrict__ bias,
                        float* __restrict__ outf,
                        __nv_bfloat16* __restrict__ ohi,
                        __nv_bfloat16* __restrict__ olo, int mode)
{
    extern __shared__ __align__(1024) char smem[];
    const uint32_t smem_base = smem_u32(smem);

    const int tid   = threadIdx.x;
    const int wid   = tid >> 5;
    const int lane  = tid & 31;
    const int warpM = wid & 3;
    const int warpN = wid >> 2;
    const int mBase = blockIdx.y * 128;
    const int nBase = blockIdx.x * 128;

    const int j8 = lane >> 3;
    const int r8 = lane & 7;
    const int aR = warpM * 32 + r8 + (j8 & 1) * 8;
    const int aC = (j8 >> 1);
    const int bR = warpN * 64 + r8 + (j8 >> 1) * 8;
    const int bC = (j8 & 1);

    const int gRow0 = tid >> 2;   // 0..63
    const int gC    = tid & 3;    // 16B chunk within 64B row

    float acc[2][8][4];
#pragma unroll
    for (int mf = 0; mf < 2; mf++)
#pragma unroll
        for (int nf = 0; nf < 8; nf++)
#pragma unroll
            for (int e = 0; e < 4; e++) acc[mf][nf][e] = 0.0f;

    const __nv_bfloat16* Apg = Ahi + (size_t)mBase * D_MODEL;
    const __nv_bfloat16* Alg = Alo + (size_t)mBase * D_MODEL;
    const __nv_bfloat16* Bpg = Bhi + (size_t)nBase * D_MODEL;
    const __nv_bfloat16* Blg = Blo + (size_t)nBase * D_MODEL;

    auto load_chunk = [&](int k0, uint32_t stage) {
#pragma unroll
        for (int i = 0; i < 2; i++) {
            const int row = gRow0 + i * 64;
            const uint32_t off = swz(row, gC);
            const size_t goA = (size_t)row * D_MODEL + k0 + gC * 8;
            CP16(stage + G_AHI + off, Apg + goA);
            CP16(stage + G_ALO + off, Alg + goA);
            CP16(stage + G_BHI + off, Bpg + goA);
            CP16(stage + G_BLO + off, Blg + goA);
        }
    };

    const int NCHUNK = D_MODEL / 32;  // 32

    load_chunk(0, smem_base + 0 * G_STAGE);
    CP_COMMIT();
    load_chunk(32, smem_base + 1 * G_STAGE);
    CP_COMMIT();

    for (int it = 0; it < NCHUNK; it++) {
        if (it + 1 < NCHUNK) {
            asm volatile("cp.async.wait_group 1;" ::: "memory");
        } else {
            asm volatile("cp.async.wait_group 0;" ::: "memory");
        }
        __syncthreads();

        if (it + 2 < NCHUNK) {
            load_chunk((it + 2) * 32, smem_base + ((it + 2) % 3) * G_STAGE);
            CP_COMMIT();
        }

        const uint32_t st = smem_base + (it % 3) * G_STAGE;

#pragma unroll
        for (int kk = 0; kk < 2; kk++) {
            uint32_t afh[2][4], afl[2][4];
#pragma unroll
            for (int mf = 0; mf < 2; mf++) {
                const int row = aR + mf * 16;
                const uint32_t off = swz(row, aC + 2 * kk);
                LDSM_X4(afh[mf][0], afh[mf][1], afh[mf][2], afh[mf][3],
                        st + G_AHI + off);
                LDSM_X4(afl[mf][0], afl[mf][1], afl[mf][2], afl[mf][3],
                        st + G_ALO + off);
            }
#pragma unroll
            for (int nf2 = 0; nf2 < 4; nf2++) {
                const int row = bR + nf2 * 16;
                const uint32_t off = swz(row, bC + 2 * kk);
                uint32_t h0, h1, h2, h3, l0, l1, l2, l3;
                LDSM_X4(h0, h1, h2, h3, st + G_BHI + off);
                LDSM_X4(l0, l1, l2, l3, st + G_BLO + off);
                uint32_t bh0[2] = {h0, h1}, bh1[2] = {h2, h3};
                uint32_t bl0[2] = {l0, l1}, bl1[2] = {l2, l3};
                MMA_BF16(acc[0][2 * nf2],     afh[0], bh0);
                MMA_BF16(acc[0][2 * nf2 + 1], afh[0], bh1);
                MMA_BF16(acc[1][2 * nf2],     afh[1], bh0);
                MMA_BF16(acc[1][2 * nf2 + 1], afh[1], bh1);
                MMA_BF16(acc[0][2 * nf2],     afl[0], bh0);
                MMA_BF16(acc[0][2 * nf2 + 1], afl[0], bh1);
                MMA_BF16(acc[1][2 * nf2],     afl[1], bh0);
                MMA_BF16(acc[1][2 * nf2 + 1], afl[1], bh1);
                MMA_BF16(acc[0][2 * nf2],     afh[0], bl0);
                MMA_BF16(acc[0][2 * nf2 + 1], afh[0], bl1);
                MMA_BF16(acc[1][2 * nf2],     afh[1], bl0);
                MMA_BF16(acc[1][2 * nf2 + 1], afh[1], bl1);
            }
        }
    }

#pragma unroll
    for (int mf = 0; mf < 2; mf++) {
#pragma unroll
        for (int nf = 0; nf < 8; nf++) {
            const int col = nBase + warpN * 64 + nf * 8 + (lane & 3) * 2;
            const float b0 = bias[col];
            const float b1 = bias[col + 1];
#pragma unroll
            for (int half = 0; half < 2; half++) {
                const int m = mBase + warpM * 32 + mf * 16 + (lane >> 2) + half * 8;
                const float vx = acc[mf][nf][half * 2 + 0] + b0;
                const float vy = acc[mf][nf][half * 2 + 1] + b1;
                if (mode) {
                    const int bb = m >> 10;
                    const int s  = m & 1023;
                    const int h  = col >> 6;
                    const int d  = col & 63;
                    const size_t idx = (((size_t)(bb * NHEAD + h) * SEQL + s) * DK) + d;
                    store_hilo2(&ohi[idx], &olo[idx], vx, vy);
                } else {
                    float2 o2; o2.x = vx; o2.y = vy;
                    *(float2*)&outf[(size_t)m * D_MODEL + col] = o2;
                }
            }
        }
    }
}

// ---------------------------------------------------------------------------
// Tensor-core flash attention, 64-key KV tiles for 2 CTAs/SM.
// CTA = (q-tile of 128 rows, head, batch), 256 threads = 8 warps.
// Smem: Q hi/lo 32KB + double-buffered KV (4 tiles x 8KB = 32KB/stage) = 96KB.
// ---------------------------------------------------------------------------
#define AT_QHI  0
#define AT_QLO  16384
#define AT_BUF  32768
#define AT_TILE 8192
#define AT_BUFSZ 32768
#define AT_SMEM (AT_BUF + 2 * AT_BUFSZ)  // 98304

__device__ __forceinline__ void attn_load_kv(
    uint32_t dstBase,
    const __nv_bfloat16* __restrict__ khi, const __nv_bfloat16* __restrict__ klo,
    const __nv_bfloat16* __restrict__ vhi, const __nv_bfloat16* __restrict__ vlo,
    int kt, int tid)
{
#pragma unroll
    for (int i = 0; i < 2; i++) {
        const int u = tid + i * 256;          // 0..511
        const int row = u >> 3;               // 0..63
        const int c = u & 7;
        const uint32_t so = sw128((uint32_t)(row * 128 + c * 16));
        const size_t go = (size_t)(kt + row) * DK + c * 8;
        CP16(dstBase + 0 * AT_TILE + so, khi + go);
        CP16(dstBase + 1 * AT_TILE + so, klo + go);
        CP16(dstBase + 2 * AT_TILE + so, vhi + go);
        CP16(dstBase + 3 * AT_TILE + so, vlo + go);
    }
}

__global__ __launch_bounds__(256, 2) void attn_mma_kernel()
{
    extern __shared__ char sm[];
    const uint32_t sb = smem_u32(sm);
    const int tid  = threadIdx.x;
    const int wid  = tid >> 5;
    const int lane = tid & 31;
    const int qt = blockIdx.x;
    const int h  = blockIdx.y;
    const int b  = blockIdx.z;

    const size_t headOff = (size_t)(b * NHEAD + h) * SEQL * DK;
    const __nv_bfloat16* qhig = g_qhi + headOff + (size_t)qt * 128 * DK;
    const __nv_bfloat16* qlog = g_qlo + headOff + (size_t)qt * 128 * DK;
    const __nv_bfloat16* khig = g_khi + headOff;
    const __nv_bfloat16* klog = g_klo + headOff;
    const __nv_bfloat16* vhig = g_vhi + headOff;
    const __nv_bfloat16* vlog = g_vlo + headOff;

    {
#pragma unroll
        for (int i = 0; i < 4; i++) {
            const int u = tid + i * 256;
            const int row = u >> 3;
            const int c = u & 7;
            const uint32_t so = sw128((uint32_t)(row * 128 + c * 16));
            const size_t go = (size_t)row * DK + c * 8;
            uint4 vh = *(const uint4*)(qhig + go);
            STS128(sb + AT_QHI + so, vh);
            uint4 vl = *(const uint4*)(qlog + go);
            STS128(sb + AT_QLO + so, vl);
        }
    }
    attn_load_kv(sb + AT_BUF, khig, klog, vhig, vlog, 0, tid);
    CP_COMMIT();
    __syncthreads();

    const int r8 = lane & 7;
    const int j8 = lane >> 3;
    const int aRow = wid * 16 + r8 + (j8 & 1) * 8;
    const int aC0  = j8 >> 1;
    uint32_t qh[4][4], ql[4][4];
#pragma unroll
    for (int kk = 0; kk < 4; kk++) {
        const uint32_t so = sw128((uint32_t)(aRow * 128 + (aC0 + 2 * kk) * 16));
        LDSM_X4(qh[kk][0], qh[kk][1], qh[kk][2], qh[kk][3], sb + AT_QHI + so);
        LDSM_X4(ql[kk][0], ql[kk][1], ql[kk][2], ql[kk][3], sb + AT_QLO + so);
    }

    float o[8][4];
#pragma unroll
    for (int nf = 0; nf < 8; nf++)
#pragma unroll
        for (int e = 0; e < 4; e++) o[nf][e] = 0.0f;
    float mrow1 = -CUDART_INF_F, mrow2 = -CUDART_INF_F;
    float lrow1 = 0.0f, lrow2 = 0.0f;

    const int qrow1 = qt * 128 + wid * 16 + (lane >> 2);
    const uint32_t* pk1 = g_pk + ((size_t)b * SEQL + qrow1) * (SEQL / 32);
    const uint32_t* pk2 = pk1 + 8 * (SEQL / 32);

    const int bRow = r8 + (j8 >> 1) * 8;
    const int bC   = j8 & 1;
    const int vRow = lane & 15;
    const int vCh  = lane >> 4;

    for (int it = 0; it < 16; it++) {
        const int cur = it & 1;
        if (it < 15) {
            attn_load_kv(sb + AT_BUF + (cur ^ 1) * AT_BUFSZ,
                         khig, klog, vhig, vlog, (it + 1) * 64, tid);
            CP_COMMIT();
            asm volatile("cp.async.wait_group 1;" ::: "memory");
        } else {
            asm volatile("cp.async.wait_group 0;" ::: "memory");
        }
        __syncthreads();

        const uint32_t kb_base = sb + AT_BUF + cur * AT_BUFSZ;

        // ---- S = Q K^T over 64 keys (3-term split) ----
        float s[8][4];
#pragma unroll
        for (int nf = 0; nf < 8; nf++)
#pragma unroll
            for (int e = 0; e < 4; e++) s[nf][e] = 0.0f;

#pragma unroll
        for (int kk = 0; kk < 4; kk++) {
            uint32_t kb[8][2];
#pragma unroll
            for (int nf2 = 0; nf2 < 4; nf2++) {
                uint32_t r0, r1, r2, r3;
                LDSM_X4(r0, r1, r2, r3, kb_base + 0 * AT_TILE +
                        sw128((uint32_t)((nf2 * 16 + bRow) * 128 + (bC + 2 * kk) * 16)));
                kb[2 * nf2][0] = r0; kb[2 * nf2][1] = r1;
                kb[2 * nf2 + 1][0] = r2; kb[2 * nf2 + 1][1] = r3;
            }
#pragma unroll
            for (int nf = 0; nf < 8; nf++) MMA_BF16(s[nf], qh[kk], kb[nf]);
#pragma unroll
            for (int nf = 0; nf < 8; nf++) MMA_BF16(s[nf], ql[kk], kb[nf]);
#pragma unroll
            for (int nf2 = 0; nf2 < 4; nf2++) {
                uint32_t r0, r1, r2, r3;
                LDSM_X4(r0, r1, r2, r3, kb_base + 1 * AT_TILE +
                        sw128((uint32_t)((nf2 * 16 + bRow) * 128 + (bC + 2 * kk) * 16)));
                kb[2 * nf2][0] = r0; kb[2 * nf2][1] = r1;
                kb[2 * nf2 + 1][0] = r2; kb[2 * nf2 + 1][1] = r3;
            }
#pragma unroll
            for (int nf = 0; nf < 8; nf++) MMA_BF16(s[nf], qh[kk], kb[nf]);
        }

        // ---- mask + scale (64 keys = 2 mask words per row) ----
        uint2 mwa = *(const uint2*)(pk1 + it * 2);
        uint2 mwb = *(const uint2*)(pk2 + it * 2);
        const uint32_t w1[2] = {mwa.x, mwa.y};
        const uint32_t w2[2] = {mwb.x, mwb.y};
#pragma unroll
        for (int nf = 0; nf < 8; nf++) {
            const uint32_t wa = w1[nf >> 2];
            const uint32_t wb = w2[nf >> 2];
            const int sh = (nf * 8 + (lane & 3) * 2) & 31;
            s[nf][0] = ((wa >> sh) & 1u)       ? s[nf][0] * 0.125f : -1e9f;
            s[nf][1] = ((wa >> (sh + 1)) & 1u) ? s[nf][1] * 0.125f : -1e9f;
            s[nf][2] = ((wb >> sh) & 1u)       ? s[nf][2] * 0.125f : -1e9f;
            s[nf][3] = ((wb >> (sh + 1)) & 1u) ? s[nf][3] * 0.125f : -1e9f;
        }

        // ---- online softmax ----
        float mx1 = -CUDART_INF_F, mx2 = -CUDART_INF_F;
#pragma unroll
        for (int nf = 0; nf < 8; nf++) {
            mx1 = fmaxf(mx1, fmaxf(s[nf][0], s[nf][1]));
            mx2 = fmaxf(mx2, fmaxf(s[nf][2], s[nf][3]));
        }
        mx1 = fmaxf(mx1, __shfl_xor_sync(0xffffffffu, mx1, 1));
        mx1 = fmaxf(mx1, __shfl_xor_sync(0xffffffffu, mx1, 2));
        mx2 = fmaxf(mx2, __shfl_xor_sync(0xffffffffu, mx2, 1));
        mx2 = fmaxf(mx2, __shfl_xor_sync(0xffffffffu, mx2, 2));

        const float mn1 = fmaxf(mrow1, mx1);
        const float mn2 = fmaxf(mrow2, mx2);
        const float c1 = __expf(mrow1 - mn1);
        const float c2 = __expf(mrow2 - mn2);
        mrow1 = mn1; mrow2 = mn2;

        float rs1 = 0.0f, rs2 = 0.0f;
#pragma unroll
        for (int nf = 0; nf < 8; nf++) {
            s[nf][0] = __expf(s[nf][0] - mn1); rs1 += s[nf][0];
            s[nf][1] = __expf(s[nf][1] - mn1); rs1 += s[nf][1];
            s[nf][2] = __expf(s[nf][2] - mn2); rs2 += s[nf][2];
            s[nf][3] = __expf(s[nf][3] - mn2); rs2 += s[nf][3];
        }
        rs1 += __shfl_xor_sync(0xffffffffu, rs1, 1);
        rs1 += __shfl_xor_sync(0xffffffffu, rs1, 2);
        rs2 += __shfl_xor_sync(0xffffffffu, rs2, 1);
        rs2 += __shfl_xor_sync(0xffffffffu, rs2, 2);
        lrow1 = lrow1 * c1 + rs1;
        lrow2 = lrow2 * c2 + rs2;

#pragma unroll
        for (int nf = 0; nf < 8; nf++) {
            o[nf][0] *= c1; o[nf][1] *= c1;
            o[nf][2] *= c2; o[nf][3] *= c2;
        }

        // ---- pack P hi/lo ----
        uint32_t phi[8][2], plo[8][2];
#pragma unroll
        for (int nf = 0; nf < 8; nf++) {
            __nv_bfloat16 h0 = __float2bfloat16_rn(s[nf][0]);
            __nv_bfloat16 h1 = __float2bfloat16_rn(s[nf][1]);
            __nv_bfloat16 h2 = __float2bfloat16_rn(s[nf][2]);
            __nv_bfloat16 h3 = __float2bfloat16_rn(s[nf][3]);
            phi[nf][0] = pack_bf16x2(h0, h1);
            phi[nf][1] = pack_bf16x2(h2, h3);
            plo[nf][0] = pack_bf16x2(
                __float2bfloat16_rn(s[nf][0] - __bfloat162float(h0)),
                __float2bfloat16_rn(s[nf][1] - __bfloat162float(h1)));
            plo[nf][1] = pack_bf16x2(
                __float2bfloat16_rn(s[nf][2] - __bfloat162float(h2)),
                __float2bfloat16_rn(s[nf][3] - __bfloat162float(h3)));
        }

        // ---- O += P V (3-term split); 4 k16 blocks over 64 keys ----
#pragma unroll
        for (int j = 0; j < 4; j++) {
            uint32_t pa_hi[4] = {phi[2 * j][0], phi[2 * j][1],
                                 phi[2 * j + 1][0], phi[2 * j + 1][1]};
            uint32_t pa_lo[4] = {plo[2 * j][0], plo[2 * j][1],
                                 plo[2 * j + 1][0], plo[2 * j + 1][1]};
            uint32_t vb[8][2];
#pragma unroll
            for (int nf2 = 0; nf2 < 4; nf2++) {
                uint32_t r0, r1, r2, r3;
                LDSM_X4T(r0, r1, r2, r3, kb_base + 2 * AT_TILE +
                         sw128((uint32_t)((j * 16 + vRow) * 128 + (nf2 * 2 + vCh) * 16)));
                vb[2 * nf2][0] = r0; vb[2 * nf2][1] = r1;
                vb[2 * nf2 + 1][0] = r2; vb[2 * nf2 + 1][1] = r3;
            }
#pragma unroll
            for (int nf = 0; nf < 8; nf++) MMA_BF16(o[nf], pa_hi, vb[nf]);
#pragma unroll
            for (int nf = 0; nf < 8; nf++) MMA_BF16(o[nf], pa_lo, vb[nf]);
#pragma unroll
            for (int nf2 = 0; nf2 < 4; nf2++) {
                uint32_t r0, r1, r2, r3;
                LDSM_X4T(r0, r1, r2, r3, kb_base + 3 * AT_TILE +
                         sw128((uint32_t)((j * 16 + vRow) * 128 + (nf2 * 2 + vCh) * 16)));
                vb[2 * nf2][0] = r0; vb[2 * nf2][1] = r1;
                vb[2 * nf2 + 1][0] = r2; vb[2 * nf2 + 1][1] = r3;
            }
#pragma unroll
            for (int nf = 0; nf < 8; nf++) MMA_BF16(o[nf], pa_hi, vb[nf]);
        }

        __syncthreads();
    }

    const float inv1 = 1.0f / lrow1;
    const float inv2 = 1.0f / lrow2;
    const size_t rowg1 = (size_t)b * SEQL + qt * 128 + wid * 16 + (lane >> 2);
    const size_t rowg2 = rowg1 + 8;
#pragma unroll
    for (int nf = 0; nf < 8; nf++) {
        const int col = h * 64 + nf * 8 + (lane & 3) * 2;
        store_hilo2(&g_xhi[rowg1 * D_MODEL + col], &g_xlo[rowg1 * D_MODEL + col],
                    o[nf][0] * inv1, o[nf][1] * inv1);
        store_hilo2(&g_xhi[rowg2 * D_MODEL + col], &g_xlo[rowg2 * D_MODEL + col],
                    o[nf][2] * inv2, o[nf][3] * inv2);
    }
}

// ---------------------------------------------------------------------------
// Host launcher
// ---------------------------------------------------------------------------
extern "C" void kernel_launch(void* const* d_in, const int* in_sizes, int n_in,
                              void* d_out, int out_size)
{
    (void)in_sizes; (void)n_in; (void)out_size;

    const float* q    = (const float*)d_in[0];
    const float* k    = (const float*)d_in[1];
    const float* v    = (const float*)d_in[2];
    const int*   mask = (const int*)  d_in[3];
    const float* Wq   = (const float*)d_in[4];
    const float* bq   = (const float*)d_in[5];
    const float* Wk   = (const float*)d_in[6];
    const float* bk   = (const float*)d_in[7];
    const float* Wv   = (const float*)d_in[8];
    const float* bv   = (const float*)d_in[9];
    const float* Wo   = (const float*)d_in[10];
    const float* bo   = (const float*)d_in[11];
    float* out = (float*)d_out;

    void* p;
    cudaGetSymbolAddress(&p, g_qhi); __nv_bfloat16* qhi = (__nv_bfloat16*)p;
    cudaGetSymbolAddress(&p, g_qlo); __nv_bfloat16* qlo = (__nv_bfloat16*)p;
    cudaGetSymbolAddress(&p, g_khi); __nv_bfloat16* khi = (__nv_bfloat16*)p;
    cudaGetSymbolAddress(&p, g_klo); __nv_bfloat16* klo = (__nv_bfloat16*)p;
    cudaGetSymbolAddress(&p, g_vhi); __nv_bfloat16* vhi = (__nv_bfloat16*)p;
    cudaGetSymbolAddress(&p, g_vlo); __nv_bfloat16* vlo = (__nv_bfloat16*)p;
    cudaGetSymbolAddress(&p, g_xhi); __nv_bfloat16* xhi = (__nv_bfloat16*)p;
    cudaGetSymbolAddress(&p, g_xlo); __nv_bfloat16* xlo = (__nv_bfloat16*)p;
    cudaGetSymbolAddress(&p, g_whi); __nv_bfloat16* whi = (__nv_bfloat16*)p;
    cudaGetSymbolAddress(&p, g_wlo); __nv_bfloat16* wlo = (__nv_bfloat16*)p;

    cudaFuncSetAttribute(attn_mma_kernel,
                         cudaFuncAttributeMaxDynamicSharedMemorySize, AT_SMEM);
    cudaFuncSetAttribute(gemm_bf16x3_kernel,
                         cudaFuncAttributeMaxDynamicSharedMemorySize, G_SMEM);

    const int n4 = MROWS * D_MODEL / 4;
    const dim3 ggemm(D_MODEL / 128, MROWS / 128);   // (8, 64)
    const dim3 gtr(D_MODEL / 32, D_MODEL / 32, 4);  // (32, 32, 4)
    const dim3 gsplit((n4 + 255) / 256, 3);

    pack_mask_kernel<<<MROWS / 8, 256>>>(mask);
    split_hilo3_kernel<<<gsplit, 256>>>(q, k, v, n4);
    split_transpose4_kernel<<<gtr, 256>>>(Wq, Wk, Wv, Wo);

    // Projections -> bf16 hi/lo head-split
    gemm_bf16x3_kernel<<<ggemm, 256, G_SMEM>>>(
        xhi + 0 * XSLICE, xlo + 0 * XSLICE, whi + 0 * WSLICE, wlo + 0 * WSLICE,
        bq, nullptr, qhi, qlo, 1);
    gemm_bf16x3_kernel<<<ggemm, 256, G_SMEM>>>(
        xhi + 1 * XSLICE, xlo + 1 * XSLICE, whi + 1 * WSLICE, wlo + 1 * WSLICE,
        bk, nullptr, khi, klo, 1);
    gemm_bf16x3_kernel<<<ggemm, 256, G_SMEM>>>(
        xhi + 2 * XSLICE, xlo + 2 * XSLICE, whi + 2 * WSLICE, wlo + 2 * WSLICE,
        bv, nullptr, vhi, vlo, 1);

    // Attention (writes hi/lo concat into xhi/xlo slice 0)
    attn_mma_kernel<<<dim3(SEQL / 128, NHEAD, BSZ), 256, AT_SMEM>>>();

    // Output projection (fp32 -> d_out)
    gemm_bf16x3_kernel<<<ggemm, 256, G_SMEM>>>(
        xhi + 0 * XSLICE, xlo + 0 * XSLICE, whi + 3 * WSLICE, wlo + 3 * WSLICE,
        bo, out, nullptr, nullptr, 0);
}

// round 11
// speedup vs baseline: 3.9630x; 1.3461x over previous
#include <cuda_runtime.h>
#include <cuda_fp16.h>
#include <math_constants.h>
#include <cstdint>

// Problem constants
#define D_MODEL 1024
#define NHEAD   16
#define DK      64
#define BSZ     8
#define SEQL    1024
#define MROWS   (BSZ * SEQL)   // 8192

#define XSLICE ((size_t)MROWS * D_MODEL)
#define WSLICE ((size_t)D_MODEL * D_MODEL)

// ---------------------------------------------------------------------------
// Scratch (allocation-free: __device__ globals)  — fp16 2-term split
// ---------------------------------------------------------------------------
__device__ __align__(16) __half g_qhi[(size_t)BSZ * NHEAD * SEQL * DK];
__device__ __align__(16) __half g_qlo[(size_t)BSZ * NHEAD * SEQL * DK];
__device__ __align__(16) __half g_khi[(size_t)BSZ * NHEAD * SEQL * DK];  // hi only
__device__ __align__(16) __half g_vhi[(size_t)BSZ * NHEAD * SEQL * DK];  // hi only
__device__ __align__(16) __half g_xhi[3 * XSLICE];  // q/k/v input splits; slice 0 reused by attn output
__device__ __align__(16) __half g_xlo[3 * XSLICE];
__device__ __align__(16) __half g_whi[4 * WSLICE];  // Wq/Wk/Wv/Wo transposed [N,K], hi only
__device__ __align__(16) uint32_t g_pk[(size_t)BSZ * SEQL * (SEQL / 32)]; // packed mask

// ---------------------------------------------------------------------------
// PTX helpers (standard PTX only — tcgen05 is rejected by the sm_103 target)
// ---------------------------------------------------------------------------
__device__ __forceinline__ uint32_t smem_u32(const void* p) {
    uint32_t a;
    asm("{ .reg .u64 t; cvta.to.shared.u64 t, %1; cvt.u32.u64 %0, t; }"
        : "=r"(a) : "l"(p));
    return a;
}

#define LDSM_X4(r0, r1, r2, r3, addr) \
    asm volatile("ldmatrix.sync.aligned.m8n8.x4.shared.b16 {%0,%1,%2,%3}, [%4];" \
                 : "=r"(r0), "=r"(r1), "=r"(r2), "=r"(r3) : "r"(addr))

#define LDSM_X4T(r0, r1, r2, r3, addr) \
    asm volatile("ldmatrix.sync.aligned.m8n8.x4.trans.shared.b16 {%0,%1,%2,%3}, [%4];" \
                 : "=r"(r0), "=r"(r1), "=r"(r2), "=r"(r3) : "r"(addr))

#define MMA_F16(d, a, b) \
    asm("mma.sync.aligned.m16n8k16.row.col.f32.f16.f16.f32 " \
        "{%0,%1,%2,%3}, {%4,%5,%6,%7}, {%8,%9}, {%0,%1,%2,%3};" \
        : "+f"((d)[0]), "+f"((d)[1]), "+f"((d)[2]), "+f"((d)[3]) \
        : "r"((a)[0]), "r"((a)[1]), "r"((a)[2]), "r"((a)[3]), \
          "r"((b)[0]), "r"((b)[1]))

#define STS128(addr, v) \
    asm volatile("st.shared.v4.b32 [%0], {%1,%2,%3,%4};" \
                 :: "r"(addr), "r"((v).x), "r"((v).y), "r"((v).z), "r"((v).w) \
                 : "memory")

#define CP16(smem_addr, gptr) \
    asm volatile("cp.async.cg.shared.global [%0], [%1], 16;" \
                 :: "r"(smem_addr), "l"(gptr) : "memory")
#define CP_COMMIT() asm volatile("cp.async.commit_group;" ::: "memory")

// 64B-row swizzle (GEMM tiles)
__device__ __forceinline__ uint32_t swz(int row, int c) {
    return (uint32_t)((row << 6) + (((c ^ (row >> 1)) & 3) << 4));
}
// SW128 swizzle for 128B rows (attention tiles)
__device__ __forceinline__ uint32_t sw128(uint32_t off) {
    return off ^ ((off >> 3) & 0x70);
}

__device__ __forceinline__ uint32_t pack_h2(__half lo16, __half hi16) {
    return ((uint32_t)*(const uint16_t*)&hi16 << 16) | *(const uint16_t*)&lo16;
}

// split fp32 pair into fp16 hi / lo pairs and store as packed u32
__device__ __forceinline__ void store_hilo2h(__half* hi, __half* lo,
                                             float a, float b) {
    __half ha = __float2half_rn(a), hb = __float2half_rn(b);
    *(uint32_t*)hi = pack_h2(ha, hb);
    __half la = __float2half_rn(a - __half2float(ha));
    __half lb = __float2half_rn(b - __half2float(hb));
    *(uint32_t*)lo = pack_h2(la, lb);
}

__device__ __forceinline__ void store_hi2h(__half* hi, float a, float b) {
    *(uint32_t*)hi = pack_h2(__float2half_rn(a), __float2half_rn(b));
}

// ---------------------------------------------------------------------------
// fp32 -> (hi,lo) fp16 split for q,k,v in ONE launch (grid.y selects input)
// ---------------------------------------------------------------------------
__global__ void split_hilo3_kernel(const float* __restrict__ q,
                                   const float* __restrict__ k,
                                   const float* __restrict__ v, int n4)
{
    const int z = blockIdx.y;
    const float* x = (z == 0) ? q : (z == 1) ? k : v;
    __half* hi = g_xhi + (size_t)z * XSLICE;
    __half* lo = g_xlo + (size_t)z * XSLICE;

    int i = blockIdx.x * blockDim.x + threadIdx.x;
    if (i >= n4) return;
    float4 val = ((const float4*)x)[i];
    __half h[4], l[4];
    float f[4] = {val.x, val.y, val.z, val.w};
#pragma unroll
    for (int j = 0; j < 4; j++) {
        h[j] = __float2half_rn(f[j]);
        l[j] = __float2half_rn(f[j] - __half2float(h[j]));
    }
    ((uint2*)hi)[i] = *(uint2*)h;
    ((uint2*)lo)[i] = *(uint2*)l;
}

// ---------------------------------------------------------------------------
// All four W [K,N] fp32 -> Wt hi [N,K] fp16 in ONE launch (grid.z selects W)
// ---------------------------------------------------------------------------
__global__ void split_transpose4_kernel(const float* __restrict__ W0,
                                        const float* __restrict__ W1,
                                        const float* __restrict__ W2,
                                        const float* __restrict__ W3)
{
    const int z = blockIdx.z;
    const float* W = (z == 0) ? W0 : (z == 1) ? W1 : (z == 2) ? W2 : W3;
    __half* hi = g_whi + (size_t)z * WSLICE;

    __shared__ float t[32][33];
    const int kb = blockIdx.y * 32;
    const int nb = blockIdx.x * 32;
    const int tx = threadIdx.x & 31;
    const int ty = threadIdx.x >> 5;
#pragma unroll
    for (int j = 0; j < 4; j++)
        t[ty + 8 * j][tx] = W[(size_t)(kb + ty + 8 * j) * D_MODEL + nb + tx];
    __syncthreads();
#pragma unroll
    for (int j = 0; j < 4; j++) {
        float v = t[tx][ty + 8 * j];
        hi[(size_t)(nb + ty + 8 * j) * D_MODEL + kb + tx] = __float2half_rn(v);
    }
}

// ---------------------------------------------------------------------------
// Pack mask [B,S,S] int32 -> bitmask [B,S,S/32]
// ---------------------------------------------------------------------------
__global__ void pack_mask_kernel(const int* __restrict__ mask)
{
    const int warp = (blockIdx.x * blockDim.x + threadIdx.x) >> 5;  // 0..8191
    const int lane = threadIdx.x & 31;
    const int* src = mask + (size_t)warp * SEQL;
    uint32_t* dst = g_pk + (size_t)warp * (SEQL / 32);
#pragma unroll 4
    for (int w = 0; w < 32; w++) {
        int v = src[w * 32 + lane];
        uint32_t bits = __ballot_sync(0xffffffffu, v != 0);
        if (lane == 0) dst[w] = bits;
    }
}

// ---------------------------------------------------------------------------
// fp16x2-split GEMM via mma.sync: C = X*W + bias, fp32 acc.
// C = Ahi*Bhi + Alo*Bhi  (A exact to 2^-22, B quantized to 11 bits).
// 3-stage cp.async circular pipeline, one __syncthreads per 32-wide K chunk.
// CTA 128x128, warp tile 32x64. mode 0: fp32 out; mode 1: fp16 head-split
// (hi always; lo only if olo != null).
// ---------------------------------------------------------------------------
#define G_AHI 0
#define G_ALO 8192
#define G_BHI 16384
#define G_STAGE 24576
#define G_SMEM (3 * G_STAGE)  // 73728

__global__ __launch_bounds__(256, 2)
void gemm_f16x2_kernel(const __half* __restrict__ Ahi,
                       const __half* __restrict__ Alo,
                       const __half* __restrict__ Bhi,
                       const float* __restrict__ bias,
                       float* __restrict__ outf,
                       __half* __restrict__ ohi,
                       __half* __restrict__ olo, int mode)
{
    extern __shared__ __align__(1024) char smem[];
    const uint32_t smem_base = smem_u32(smem);

    const int tid   = threadIdx.x;
    const int wid   = tid >> 5;
    const int lane  = tid & 31;
    const int warpM = wid & 3;
    const int warpN = wid >> 2;
    const int mBase = blockIdx.y * 128;
    const int nBase = blockIdx.x * 128;

    const int j8 = lane >> 3;
    const int r8 = lane & 7;
    const int aR = warpM * 32 + r8 + (j8 & 1) * 8;
    const int aC = (j8 >> 1);
    const int bR = warpN * 64 + r8 + (j8 >> 1) * 8;
    const int bC = (j8 & 1);

    const int gRow0 = tid >> 2;   // 0..63
    const int gC    = tid & 3;    // 16B chunk within 64B row

    float acc[2][8][4];
#pragma unroll
    for (int mf = 0; mf < 2; mf++)
#pragma unroll
        for (int nf = 0; nf < 8; nf++)
#pragma unroll
            for (int e = 0; e < 4; e++) acc[mf][nf][e] = 0.0f;

    const __half* Apg = Ahi + (size_t)mBase * D_MODEL;
    const __half* Alg = Alo + (size_t)mBase * D_MODEL;
    const __half* Bpg = Bhi + (size_t)nBase * D_MODEL;

    auto load_chunk = [&](int k0, uint32_t stage) {
#pragma unroll
        for (int i = 0; i < 2; i++) {
            const int row = gRow0 + i * 64;
            const uint32_t off = swz(row, gC);
            const size_t goA = (size_t)row * D_MODEL + k0 + gC * 8;
            CP16(stage + G_AHI + off, Apg + goA);
            CP16(stage + G_ALO + off, Alg + goA);
            CP16(stage + G_BHI + off, Bpg + goA);
        }
    };

    const int NCHUNK = D_MODEL / 32;  // 32

    load_chunk(0, smem_base + 0 * G_STAGE);
    CP_COMMIT();
    load_chunk(32, smem_base + 1 * G_STAGE);
    CP_COMMIT();

    for (int it = 0; it < NCHUNK; it++) {
        if (it + 1 < NCHUNK) {
            asm volatile("cp.async.wait_group 1;" ::: "memory");
        } else {
            asm volatile("cp.async.wait_group 0;" ::: "memory");
        }
        __syncthreads();

        if (it + 2 < NCHUNK) {
            load_chunk((it + 2) * 32, smem_base + ((it + 2) % 3) * G_STAGE);
            CP_COMMIT();
        }

        const uint32_t st = smem_base + (it % 3) * G_STAGE;

#pragma unroll
        for (int kk = 0; kk < 2; kk++) {
            uint32_t afh[2][4], afl[2][4];
#pragma unroll
            for (int mf = 0; mf < 2; mf++) {
                const int row = aR + mf * 16;
                const uint32_t off = swz(row, aC + 2 * kk);
                LDSM_X4(afh[mf][0], afh[mf][1], afh[mf][2], afh[mf][3],
                        st + G_AHI + off);
                LDSM_X4(afl[mf][0], afl[mf][1], afl[mf][2], afl[mf][3],
                        st + G_ALO + off);
            }
#pragma unroll
            for (int nf2 = 0; nf2 < 4; nf2++) {
                const int row = bR + nf2 * 16;
                const uint32_t off = swz(row, bC + 2 * kk);
                uint32_t h0, h1, h2, h3;
                LDSM_X4(h0, h1, h2, h3, st + G_BHI + off);
                uint32_t bh0[2] = {h0, h1}, bh1[2] = {h2, h3};
                MMA_F16(acc[0][2 * nf2],     afh[0], bh0);
                MMA_F16(acc[0][2 * nf2 + 1], afh[0], bh1);
                MMA_F16(acc[1][2 * nf2],     afh[1], bh0);
                MMA_F16(acc[1][2 * nf2 + 1], afh[1], bh1);
                MMA_F16(acc[0][2 * nf2],     afl[0], bh0);
                MMA_F16(acc[0][2 * nf2 + 1], afl[0], bh1);
                MMA_F16(acc[1][2 * nf2],     afl[1], bh0);
                MMA_F16(acc[1][2 * nf2 + 1], afl[1], bh1);
            }
        }
    }

#pragma unroll
    for (int mf = 0; mf < 2; mf++) {
#pragma unroll
        for (int nf = 0; nf < 8; nf++) {
            const int col = nBase + warpN * 64 + nf * 8 + (lane & 3) * 2;
            const float b0 = bias[col];
            const float b1 = bias[col + 1];
#pragma unroll
            for (int half = 0; half < 2; half++) {
                const int m = mBase + warpM * 32 + mf * 16 + (lane >> 2) + half * 8;
                const float vx = acc[mf][nf][half * 2 + 0] + b0;
                const float vy = acc[mf][nf][half * 2 + 1] + b1;
                if (mode) {
                    const int bb = m >> 10;
                    const int s  = m & 1023;
                    const int h  = col >> 6;
                    const int d  = col & 63;
                    const size_t idx = (((size_t)(bb * NHEAD + h) * SEQL + s) * DK) + d;
                    if (olo) store_hilo2h(&ohi[idx], &olo[idx], vx, vy);
                    else     store_hi2h(&ohi[idx], vx, vy);
                } else {
                    float2 o2; o2.x = vx; o2.y = vy;
                    *(float2*)&outf[(size_t)m * D_MODEL + col] = o2;
                }
            }
        }
    }
}

// ---------------------------------------------------------------------------
// Tensor-core flash attention, fp16 2-term.
// S = Qhi*Khi + Qlo*Khi ; O += Phi*Vhi + Plo*Vhi.
// 64-key KV tiles; smem: Q hi/lo 32KB + double-buffered K/V hi (16KB/stage)
// = 64KB -> 2 CTAs/SM.
// ---------------------------------------------------------------------------
#define AT_QHI  0
#define AT_QLO  16384
#define AT_BUF  32768
#define AT_TILE 8192
#define AT_BUFSZ 16384
#define AT_SMEM (AT_BUF + 2 * AT_BUFSZ)  // 65536

__device__ __forceinline__ void attn_load_kv(
    uint32_t dstBase,
    const __half* __restrict__ khi, const __half* __restrict__ vhi,
    int kt, int tid)
{
#pragma unroll
    for (int i = 0; i < 2; i++) {
        const int u = tid + i * 256;          // 0..511
        const int row = u >> 3;               // 0..63
        const int c = u & 7;
        const uint32_t so = sw128((uint32_t)(row * 128 + c * 16));
        const size_t go = (size_t)(kt + row) * DK + c * 8;
        CP16(dstBase + 0 * AT_TILE + so, khi + go);
        CP16(dstBase + 1 * AT_TILE + so, vhi + go);
    }
}

__global__ __launch_bounds__(256, 2) void attn_mma_kernel()
{
    extern __shared__ char sm[];
    const uint32_t sb = smem_u32(sm);
    const int tid  = threadIdx.x;
    const int wid  = tid >> 5;
    const int lane = tid & 31;
    const int qt = blockIdx.x;
    const int h  = blockIdx.y;
    const int b  = blockIdx.z;

    const size_t headOff = (size_t)(b * NHEAD + h) * SEQL * DK;
    const __half* qhig = g_qhi + headOff + (size_t)qt * 128 * DK;
    const __half* qlog = g_qlo + headOff + (size_t)qt * 128 * DK;
    const __half* khig = g_khi + headOff;
    const __half* vhig = g_vhi + headOff;

    {
#pragma unroll
        for (int i = 0; i < 4; i++) {
            const int u = tid + i * 256;
            const int row = u >> 3;
            const int c = u & 7;
            const uint32_t so = sw128((uint32_t)(row * 128 + c * 16));
            const size_t go = (size_t)row * DK + c * 8;
            uint4 vh = *(const uint4*)(qhig + go);
            STS128(sb + AT_QHI + so, vh);
            uint4 vl = *(const uint4*)(qlog + go);
            STS128(sb + AT_QLO + so, vl);
        }
    }
    attn_load_kv(sb + AT_BUF, khig, vhig, 0, tid);
    CP_COMMIT();
    __syncthreads();

    const int r8 = lane & 7;
    const int j8 = lane >> 3;
    const int aRow = wid * 16 + r8 + (j8 & 1) * 8;
    const int aC0  = j8 >> 1;
    uint32_t qh[4][4], ql[4][4];
#pragma unroll
    for (int kk = 0; kk < 4; kk++) {
        const uint32_t so = sw128((uint32_t)(aRow * 128 + (aC0 + 2 * kk) * 16));
        LDSM_X4(qh[kk][0], qh[kk][1], qh[kk][2], qh[kk][3], sb + AT_QHI + so);
        LDSM_X4(ql[kk][0], ql[kk][1], ql[kk][2], ql[kk][3], sb + AT_QLO + so);
    }

    float o[8][4];
#pragma unroll
    for (int nf = 0; nf < 8; nf++)
#pragma unroll
        for (int e = 0; e < 4; e++) o[nf][e] = 0.0f;
    float mrow1 = -CUDART_INF_F, mrow2 = -CUDART_INF_F;
    float lrow1 = 0.0f, lrow2 = 0.0f;

    const int qrow1 = qt * 128 + wid * 16 + (lane >> 2);
    const uint32_t* pk1 = g_pk + ((size_t)b * SEQL + qrow1) * (SEQL / 32);
    const uint32_t* pk2 = pk1 + 8 * (SEQL / 32);

    const int bRow = r8 + (j8 >> 1) * 8;
    const int bC   = j8 & 1;
    const int vRow = lane & 15;
    const int vCh  = lane >> 4;

    for (int it = 0; it < 16; it++) {
        const int cur = it & 1;
        if (it < 15) {
            attn_load_kv(sb + AT_BUF + (cur ^ 1) * AT_BUFSZ,
                         khig, vhig, (it + 1) * 64, tid);
            CP_COMMIT();
            asm volatile("cp.async.wait_group 1;" ::: "memory");
        } else {
            asm volatile("cp.async.wait_group 0;" ::: "memory");
        }
        __syncthreads();

        const uint32_t kb_base = sb + AT_BUF + cur * AT_BUFSZ;

        // ---- S = Q K^T over 64 keys (2-term) ----
        float s[8][4];
#pragma unroll
        for (int nf = 0; nf < 8; nf++)
#pragma unroll
            for (int e = 0; e < 4; e++) s[nf][e] = 0.0f;

#pragma unroll
        for (int kk = 0; kk < 4; kk++) {
            uint32_t kb[8][2];
#pragma unroll
            for (int nf2 = 0; nf2 < 4; nf2++) {
                uint32_t r0, r1, r2, r3;
                LDSM_X4(r0, r1, r2, r3, kb_base + 0 * AT_TILE +
                        sw128((uint32_t)((nf2 * 16 + bRow) * 128 + (bC + 2 * kk) * 16)));
                kb[2 * nf2][0] = r0; kb[2 * nf2][1] = r1;
                kb[2 * nf2 + 1][0] = r2; kb[2 * nf2 + 1][1] = r3;
            }
#pragma unroll
            for (int nf = 0; nf < 8; nf++) MMA_F16(s[nf], qh[kk], kb[nf]);
#pragma unroll
            for (int nf = 0; nf < 8; nf++) MMA_F16(s[nf], ql[kk], kb[nf]);
        }

        // ---- mask + scale (64 keys = 2 mask words per row) ----
        uint2 mwa = *(const uint2*)(pk1 + it * 2);
        uint2 mwb = *(const uint2*)(pk2 + it * 2);
        const uint32_t w1[2] = {mwa.x, mwa.y};
        const uint32_t w2[2] = {mwb.x, mwb.y};
#pragma unroll
        for (int nf = 0; nf < 8; nf++) {
            const uint32_t wa = w1[nf >> 2];
            const uint32_t wb = w2[nf >> 2];
            const int sh = (nf * 8 + (lane & 3) * 2) & 31;
            s[nf][0] = ((wa >> sh) & 1u)       ? s[nf][0] * 0.125f : -1e9f;
            s[nf][1] = ((wa >> (sh + 1)) & 1u) ? s[nf][1] * 0.125f : -1e9f;
            s[nf][2] = ((wb >> sh) & 1u)       ? s[nf][2] * 0.125f : -1e9f;
            s[nf][3] = ((wb >> (sh + 1)) & 1u) ? s[nf][3] * 0.125f : -1e9f;
        }

        // ---- online softmax ----
        float mx1 = -CUDART_INF_F, mx2 = -CUDART_INF_F;
#pragma unroll
        for (int nf = 0; nf < 8; nf++) {
            mx1 = fmaxf(mx1, fmaxf(s[nf][0], s[nf][1]));
            mx2 = fmaxf(mx2, fmaxf(s[nf][2], s[nf][3]));
        }
        mx1 = fmaxf(mx1, __shfl_xor_sync(0xffffffffu, mx1, 1));
        mx1 = fmaxf(mx1, __shfl_xor_sync(0xffffffffu, mx1, 2));
        mx2 = fmaxf(mx2, __shfl_xor_sync(0xffffffffu, mx2, 1));
        mx2 = fmaxf(mx2, __shfl_xor_sync(0xffffffffu, mx2, 2));

        const float mn1 = fmaxf(mrow1, mx1);
        const float mn2 = fmaxf(mrow2, mx2);
        const float c1 = __expf(mrow1 - mn1);
        const float c2 = __expf(mrow2 - mn2);
        mrow1 = mn1; mrow2 = mn2;

        float rs1 = 0.0f, rs2 = 0.0f;
#pragma unroll
        for (int nf = 0; nf < 8; nf++) {
            s[nf][0] = __expf(s[nf][0] - mn1); rs1 += s[nf][0];
            s[nf][1] = __expf(s[nf][1] - mn1); rs1 += s[nf][1];
            s[nf][2] = __expf(s[nf][2] - mn2); rs2 += s[nf][2];
            s[nf][3] = __expf(s[nf][3] - mn2); rs2 += s[nf][3];
        }
        rs1 += __shfl_xor_sync(0xffffffffu, rs1, 1);
        rs1 += __shfl_xor_sync(0xffffffffu, rs1, 2);
        rs2 += __shfl_xor_sync(0xffffffffu, rs2, 1);
        rs2 += __shfl_xor_sync(0xffffffffu, rs2, 2);
        lrow1 = lrow1 * c1 + rs1;
        lrow2 = lrow2 * c2 + rs2;

#pragma unroll
        for (int nf = 0; nf < 8; nf++) {
            o[nf][0] *= c1; o[nf][1] *= c1;
            o[nf][2] *= c2; o[nf][3] *= c2;
        }

        // ---- pack P hi/lo (fp16) ----
        uint32_t phi[8][2], plo[8][2];
#pragma unroll
        for (int nf = 0; nf < 8; nf++) {
            __half h0 = __float2half_rn(s[nf][0]);
            __half h1 = __float2half_rn(s[nf][1]);
            __half h2 = __float2half_rn(s[nf][2]);
            __half h3 = __float2half_rn(s[nf][3]);
            phi[nf][0] = pack_h2(h0, h1);
            phi[nf][1] = pack_h2(h2, h3);
            plo[nf][0] = pack_h2(
                __float2half_rn(s[nf][0] - __half2float(h0)),
                __float2half_rn(s[nf][1] - __half2float(h1)));
            plo[nf][1] = pack_h2(
                __float2half_rn(s[nf][2] - __half2float(h2)),
                __float2half_rn(s[nf][3] - __half2float(h3)));
        }

        // ---- O += P V (2-term); 4 k16 blocks over 64 keys ----
#pragma unroll
        for (int j = 0; j < 4; j++) {
            uint32_t pa_hi[4] = {phi[2 * j][0], phi[2 * j][1],
                                 phi[2 * j + 1][0], phi[2 * j + 1][1]};
            uint32_t pa_lo[4] = {plo[2 * j][0], plo[2 * j][1],
                                 plo[2 * j + 1][0], plo[2 * j + 1][1]};
            uint32_t vb[8][2];
#pragma unroll
            for (int nf2 = 0; nf2 < 4; nf2++) {
                uint32_t r0, r1, r2, r3;
                LDSM_X4T(r0, r1, r2, r3, kb_base + 1 * AT_TILE +
                         sw128((uint32_t)((j * 16 + vRow) * 128 + (nf2 * 2 + vCh) * 16)));
                vb[2 * nf2][0] = r0; vb[2 * nf2][1] = r1;
                vb[2 * nf2 + 1][0] = r2; vb[2 * nf2 + 1][1] = r3;
            }
#pragma unroll
            for (int nf = 0; nf < 8; nf++) MMA_F16(o[nf], pa_hi, vb[nf]);
#pragma unroll
            for (int nf = 0; nf < 8; nf++) MMA_F16(o[nf], pa_lo, vb[nf]);
        }

        __syncthreads();
    }

    const float inv1 = 1.0f / lrow1;
    const float inv2 = 1.0f / lrow2;
    const size_t rowg1 = (size_t)b * SEQL + qt * 128 + wid * 16 + (lane >> 2);
    const size_t rowg2 = rowg1 + 8;
#pragma unroll
    for (int nf = 0; nf < 8; nf++) {
        const int col = h * 64 + nf * 8 + (lane & 3) * 2;
        store_hilo2h(&g_xhi[rowg1 * D_MODEL + col], &g_xlo[rowg1 * D_MODEL + col],
                     o[nf][0] * inv1, o[nf][1] * inv1);
        store_hilo2h(&g_xhi[rowg2 * D_MODEL + col], &g_xlo[rowg2 * D_MODEL + col],
                     o[nf][2] * inv2, o[nf][3] * inv2);
    }
}

// ---------------------------------------------------------------------------
// Host launcher
// ---------------------------------------------------------------------------
extern "C" void kernel_launch(void* const* d_in, const int* in_sizes, int n_in,
                              void* d_out, int out_size)
{
    (void)in_sizes; (void)n_in; (void)out_size;

    const float* q    = (const float*)d_in[0];
    const float* k    = (const float*)d_in[1];
    const float* v    = (const float*)d_in[2];
    const int*   mask = (const int*)  d_in[3];
    const float* Wq   = (const float*)d_in[4];
    const float* bq   = (const float*)d_in[5];
    const float* Wk   = (const float*)d_in[6];
    const float* bk   = (const float*)d_in[7];
    const float* Wv   = (const float*)d_in[8];
    const float* bv   = (const float*)d_in[9];
    const float* Wo   = (const float*)d_in[10];
    const float* bo   = (const float*)d_in[11];
    float* out = (float*)d_out;

    void* p;
    cudaGetSymbolAddress(&p, g_qhi); __half* qhi = (__half*)p;
    cudaGetSymbolAddress(&p, g_qlo); __half* qlo = (__half*)p;
    cudaGetSymbolAddress(&p, g_khi); __half* khi = (__half*)p;
    cudaGetSymbolAddress(&p, g_vhi); __half* vhi = (__half*)p;
    cudaGetSymbolAddress(&p, g_xhi); __half* xhi = (__half*)p;
    cudaGetSymbolAddress(&p, g_xlo); __half* xlo = (__half*)p;
    cudaGetSymbolAddress(&p, g_whi); __half* whi = (__half*)p;

    cudaFuncSetAttribute(attn_mma_kernel,
                         cudaFuncAttributeMaxDynamicSharedMemorySize, AT_SMEM);
    cudaFuncSetAttribute(gemm_f16x2_kernel,
                         cudaFuncAttributeMaxDynamicSharedMemorySize, G_SMEM);

    const int n4 = MROWS * D_MODEL / 4;
    const dim3 ggemm(D_MODEL / 128, MROWS / 128);   // (8, 64)
    const dim3 gtr(D_MODEL / 32, D_MODEL / 32, 4);  // (32, 32, 4)
    const dim3 gsplit((n4 + 255) / 256, 3);

    pack_mask_kernel<<<MROWS / 8, 256>>>(mask);
    split_hilo3_kernel<<<gsplit, 256>>>(q, k, v, n4);
    split_transpose4_kernel<<<gtr, 256>>>(Wq, Wk, Wv, Wo);

    // Projections: Q needs hi+lo; K and V hi only
    gemm_f16x2_kernel<<<ggemm, 256, G_SMEM>>>(
        xhi + 0 * XSLICE, xlo + 0 * XSLICE, whi + 0 * WSLICE,
        bq, nullptr, qhi, qlo, 1);
    gemm_f16x2_kernel<<<ggemm, 256, G_SMEM>>>(
        xhi + 1 * XSLICE, xlo + 1 * XSLICE, whi + 1 * WSLICE,
        bk, nullptr, khi, nullptr, 1);
    gemm_f16x2_kernel<<<ggemm, 256, G_SMEM>>>(
        xhi + 2 * XSLICE, xlo + 2 * XSLICE, whi + 2 * WSLICE,
        bv, nullptr, vhi, nullptr, 1);

    // Attention (writes hi/lo concat into xhi/xlo slice 0)
    attn_mma_kernel<<<dim3(SEQL / 128, NHEAD, BSZ), 256, AT_SMEM>>>();

    // Output projection (fp32 -> d_out)
    gemm_f16x2_kernel<<<ggemm, 256, G_SMEM>>>(
        xhi + 0 * XSLICE, xlo + 0 * XSLICE, whi + 3 * WSLICE,
        bo, out, nullptr, nullptr, 0);
}

// round 12
// speedup vs baseline: 4.4753x; 1.1293x over previous
#include <cuda_runtime.h>
#include <cuda_fp16.h>
#include <math_constants.h>
#include <cstdint>

// Problem constants
#define D_MODEL 1024
#define NHEAD   16
#define DK      64
#define BSZ     8
#define SEQL    1024
#define MROWS   (BSZ * SEQL)   // 8192

#define XSLICE ((size_t)MROWS * D_MODEL)
#define WSLICE ((size_t)D_MODEL * D_MODEL)

// ---------------------------------------------------------------------------
// Scratch (allocation-free: __device__ globals)  — fp16 2-term split
// ---------------------------------------------------------------------------
__device__ __align__(16) __half g_qhi[(size_t)BSZ * NHEAD * SEQL * DK];
__device__ __align__(16) __half g_qlo[(size_t)BSZ * NHEAD * SEQL * DK];
__device__ __align__(16) __half g_khi[(size_t)BSZ * NHEAD * SEQL * DK];  // hi only
__device__ __align__(16) __half g_vhi[(size_t)BSZ * NHEAD * SEQL * DK];  // hi only
__device__ __align__(16) __half g_xhi[3 * XSLICE];  // q/k/v input splits; slice 0 reused by attn output
__device__ __align__(16) __half g_xlo[3 * XSLICE];
__device__ __align__(16) __half g_whi[4 * WSLICE];  // Wq/Wk/Wv/Wo transposed [N,K], hi only
__device__ __align__(16) uint32_t g_pk[(size_t)BSZ * SEQL * (SEQL / 32)]; // packed mask

// ---------------------------------------------------------------------------
// PTX helpers (standard PTX only — tcgen05 is rejected by the sm_103 target)
// ---------------------------------------------------------------------------
__device__ __forceinline__ uint32_t smem_u32(const void* p) {
    uint32_t a;
    asm("{ .reg .u64 t; cvta.to.shared.u64 t, %1; cvt.u32.u64 %0, t; }"
        : "=r"(a) : "l"(p));
    return a;
}

#define LDSM_X4(r0, r1, r2, r3, addr) \
    asm volatile("ldmatrix.sync.aligned.m8n8.x4.shared.b16 {%0,%1,%2,%3}, [%4];" \
                 : "=r"(r0), "=r"(r1), "=r"(r2), "=r"(r3) : "r"(addr))

#define LDSM_X4T(r0, r1, r2, r3, addr) \
    asm volatile("ldmatrix.sync.aligned.m8n8.x4.trans.shared.b16 {%0,%1,%2,%3}, [%4];" \
                 : "=r"(r0), "=r"(r1), "=r"(r2), "=r"(r3) : "r"(addr))

#define MMA_F16(d, a, b) \
    asm("mma.sync.aligned.m16n8k16.row.col.f32.f16.f16.f32 " \
        "{%0,%1,%2,%3}, {%4,%5,%6,%7}, {%8,%9}, {%0,%1,%2,%3};" \
        : "+f"((d)[0]), "+f"((d)[1]), "+f"((d)[2]), "+f"((d)[3]) \
        : "r"((a)[0]), "r"((a)[1]), "r"((a)[2]), "r"((a)[3]), \
          "r"((b)[0]), "r"((b)[1]))

#define STS128(addr, v) \
    asm volatile("st.shared.v4.b32 [%0], {%1,%2,%3,%4};" \
                 :: "r"(addr), "r"((v).x), "r"((v).y), "r"((v).z), "r"((v).w) \
                 : "memory")

#define CP16(smem_addr, gptr) \
    asm volatile("cp.async.cg.shared.global [%0], [%1], 16;" \
                 :: "r"(smem_addr), "l"(gptr) : "memory")
#define CP_COMMIT() asm volatile("cp.async.commit_group;" ::: "memory")

// 64B-row swizzle (GEMM tiles)
__device__ __forceinline__ uint32_t swz(int row, int c) {
    return (uint32_t)((row << 6) + (((c ^ (row >> 1)) & 3) << 4));
}
// SW128 swizzle for 128B rows (attention tiles)
__device__ __forceinline__ uint32_t sw128(uint32_t off) {
    return off ^ ((off >> 3) & 0x70);
}

__device__ __forceinline__ uint32_t pack_h2(__half lo16, __half hi16) {
    return ((uint32_t)*(const uint16_t*)&hi16 << 16) | *(const uint16_t*)&lo16;
}

// split fp32 pair into fp16 hi / lo pairs and store as packed u32
__device__ __forceinline__ void store_hilo2h(__half* hi, __half* lo,
                                             float a, float b) {
    __half ha = __float2half_rn(a), hb = __float2half_rn(b);
    *(uint32_t*)hi = pack_h2(ha, hb);
    __half la = __float2half_rn(a - __half2float(ha));
    __half lb = __float2half_rn(b - __half2float(hb));
    *(uint32_t*)lo = pack_h2(la, lb);
}

__device__ __forceinline__ void store_hi2h(__half* hi, float a, float b) {
    *(uint32_t*)hi = pack_h2(__float2half_rn(a), __float2half_rn(b));
}

// ---------------------------------------------------------------------------
// fp32 -> (hi,lo) fp16 split for q,k,v in ONE launch (grid.y selects input)
// ---------------------------------------------------------------------------
__global__ void split_hilo3_kernel(const float* __restrict__ q,
                                   const float* __restrict__ k,
                                   const float* __restrict__ v, int n4)
{
    const int z = blockIdx.y;
    const float* x = (z == 0) ? q : (z == 1) ? k : v;
    __half* hi = g_xhi + (size_t)z * XSLICE;
    __half* lo = g_xlo + (size_t)z * XSLICE;

    int i = blockIdx.x * blockDim.x + threadIdx.x;
    if (i >= n4) return;
    float4 val = ((const float4*)x)[i];
    __half h[4], l[4];
    float f[4] = {val.x, val.y, val.z, val.w};
#pragma unroll
    for (int j = 0; j < 4; j++) {
        h[j] = __float2half_rn(f[j]);
        l[j] = __float2half_rn(f[j] - __half2float(h[j]));
    }
    ((uint2*)hi)[i] = *(uint2*)h;
    ((uint2*)lo)[i] = *(uint2*)l;
}

// ---------------------------------------------------------------------------
// All four W [K,N] fp32 -> Wt hi [N,K] fp16 in ONE launch (grid.z selects W)
// ---------------------------------------------------------------------------
__global__ void split_transpose4_kernel(const float* __restrict__ W0,
                                        const float* __restrict__ W1,
                                        const float* __restrict__ W2,
                                        const float* __restrict__ W3)
{
    const int z = blockIdx.z;
    const float* W = (z == 0) ? W0 : (z == 1) ? W1 : (z == 2) ? W2 : W3;
    __half* hi = g_whi + (size_t)z * WSLICE;

    __shared__ float t[32][33];
    const int kb = blockIdx.y * 32;
    const int nb = blockIdx.x * 32;
    const int tx = threadIdx.x & 31;
    const int ty = threadIdx.x >> 5;
#pragma unroll
    for (int j = 0; j < 4; j++)
        t[ty + 8 * j][tx] = W[(size_t)(kb + ty + 8 * j) * D_MODEL + nb + tx];
    __syncthreads();
#pragma unroll
    for (int j = 0; j < 4; j++) {
        float v = t[tx][ty + 8 * j];
        hi[(size_t)(nb + ty + 8 * j) * D_MODEL + kb + tx] = __float2half_rn(v);
    }
}

// ---------------------------------------------------------------------------
// Pack mask [B,S,S] int32 -> bitmask [B,S,S/32]
// ---------------------------------------------------------------------------
__global__ void pack_mask_kernel(const int* __restrict__ mask)
{
    const int warp = (blockIdx.x * blockDim.x + threadIdx.x) >> 5;  // 0..8191
    const int lane = threadIdx.x & 31;
    const int* src = mask + (size_t)warp * SEQL;
    uint32_t* dst = g_pk + (size_t)warp * (SEQL / 32);
#pragma unroll 4
    for (int w = 0; w < 32; w++) {
        int v = src[w * 32 + lane];
        uint32_t bits = __ballot_sync(0xffffffffu, v != 0);
        if (lane == 0) dst[w] = bits;
    }
}

// ---------------------------------------------------------------------------
// fp16 GEMM via mma.sync: C = X*W + bias, fp32 acc.
// TWO=1: C = Ahi*Bhi + Alo*Bhi (A exact to 2^-22).  TWO=0: C = Ahi*Bhi.
// 3-stage cp.async circular pipeline, one __syncthreads per 32-wide K chunk.
// CTA 128x128, warp tile 32x64. mode 0: fp32 out; mode 1: fp16 head-split
// (hi always; lo only if olo != null).
// ---------------------------------------------------------------------------
template <int TWO>
__global__ __launch_bounds__(256, 2)
void gemm_f16_kernel(const __half* __restrict__ Ahi,
                     const __half* __restrict__ Alo,
                     const __half* __restrict__ Bhi,
                     const float* __restrict__ bias,
                     float* __restrict__ outf,
                     __half* __restrict__ ohi,
                     __half* __restrict__ olo, int mode)
{
    constexpr uint32_t ST_AHI  = 0;
    constexpr uint32_t ST_ALO  = 8192;                 // valid only if TWO
    constexpr uint32_t ST_BHI  = TWO ? 16384 : 8192;
    constexpr uint32_t ST_SIZE = TWO ? 24576 : 16384;

    extern __shared__ __align__(1024) char smem[];
    const uint32_t smem_base = smem_u32(smem);

    const int tid   = threadIdx.x;
    const int wid   = tid >> 5;
    const int lane  = tid & 31;
    const int warpM = wid & 3;
    const int warpN = wid >> 2;
    const int mBase = blockIdx.y * 128;
    const int nBase = blockIdx.x * 128;

    const int j8 = lane >> 3;
    const int r8 = lane & 7;
    const int aR = warpM * 32 + r8 + (j8 & 1) * 8;
    const int aC = (j8 >> 1);
    const int bR = warpN * 64 + r8 + (j8 >> 1) * 8;
    const int bC = (j8 & 1);

    const int gRow0 = tid >> 2;   // 0..63
    const int gC    = tid & 3;    // 16B chunk within 64B row

    float acc[2][8][4];
#pragma unroll
    for (int mf = 0; mf < 2; mf++)
#pragma unroll
        for (int nf = 0; nf < 8; nf++)
#pragma unroll
            for (int e = 0; e < 4; e++) acc[mf][nf][e] = 0.0f;

    const __half* Apg = Ahi + (size_t)mBase * D_MODEL;
    const __half* Alg = TWO ? (Alo + (size_t)mBase * D_MODEL) : nullptr;
    const __half* Bpg = Bhi + (size_t)nBase * D_MODEL;

    auto load_chunk = [&](int k0, uint32_t stage) {
#pragma unroll
        for (int i = 0; i < 2; i++) {
            const int row = gRow0 + i * 64;
            const uint32_t off = swz(row, gC);
            const size_t goA = (size_t)row * D_MODEL + k0 + gC * 8;
            CP16(stage + ST_AHI + off, Apg + goA);
            if (TWO) CP16(stage + ST_ALO + off, Alg + goA);
            CP16(stage + ST_BHI + off, Bpg + goA);
        }
    };

    const int NCHUNK = D_MODEL / 32;  // 32

    load_chunk(0, smem_base + 0 * ST_SIZE);
    CP_COMMIT();
    load_chunk(32, smem_base + 1 * ST_SIZE);
    CP_COMMIT();

    for (int it = 0; it < NCHUNK; it++) {
        if (it + 1 < NCHUNK) {
            asm volatile("cp.async.wait_group 1;" ::: "memory");
        } else {
            asm volatile("cp.async.wait_group 0;" ::: "memory");
        }
        __syncthreads();

        if (it + 2 < NCHUNK) {
            load_chunk((it + 2) * 32, smem_base + ((it + 2) % 3) * ST_SIZE);
            CP_COMMIT();
        }

        const uint32_t st = smem_base + (it % 3) * ST_SIZE;

#pragma unroll
        for (int kk = 0; kk < 2; kk++) {
            uint32_t afh[2][4], afl[2][4];
#pragma unroll
            for (int mf = 0; mf < 2; mf++) {
                const int row = aR + mf * 16;
                const uint32_t off = swz(row, aC + 2 * kk);
                LDSM_X4(afh[mf][0], afh[mf][1], afh[mf][2], afh[mf][3],
                        st + ST_AHI + off);
                if (TWO)
                    LDSM_X4(afl[mf][0], afl[mf][1], afl[mf][2], afl[mf][3],
                            st + ST_ALO + off);
            }
#pragma unroll
            for (int nf2 = 0; nf2 < 4; nf2++) {
                const int row = bR + nf2 * 16;
                const uint32_t off = swz(row, bC + 2 * kk);
                uint32_t h0, h1, h2, h3;
                LDSM_X4(h0, h1, h2, h3, st + ST_BHI + off);
                uint32_t bh0[2] = {h0, h1}, bh1[2] = {h2, h3};
                MMA_F16(acc[0][2 * nf2],     afh[0], bh0);
                MMA_F16(acc[0][2 * nf2 + 1], afh[0], bh1);
                MMA_F16(acc[1][2 * nf2],     afh[1], bh0);
                MMA_F16(acc[1][2 * nf2 + 1], afh[1], bh1);
                if (TWO) {
                    MMA_F16(acc[0][2 * nf2],     afl[0], bh0);
                    MMA_F16(acc[0][2 * nf2 + 1], afl[0], bh1);
                    MMA_F16(acc[1][2 * nf2],     afl[1], bh0);
                    MMA_F16(acc[1][2 * nf2 + 1], afl[1], bh1);
                }
            }
        }
    }

#pragma unroll
    for (int mf = 0; mf < 2; mf++) {
#pragma unroll
        for (int nf = 0; nf < 8; nf++) {
            const int col = nBase + warpN * 64 + nf * 8 + (lane & 3) * 2;
            const float b0 = bias[col];
            const float b1 = bias[col + 1];
#pragma unroll
            for (int half = 0; half < 2; half++) {
                const int m = mBase + warpM * 32 + mf * 16 + (lane >> 2) + half * 8;
                const float vx = acc[mf][nf][half * 2 + 0] + b0;
                const float vy = acc[mf][nf][half * 2 + 1] + b1;
                if (mode) {
                    const int bb = m >> 10;
                    const int s  = m & 1023;
                    const int h  = col >> 6;
                    const int d  = col & 63;
                    const size_t idx = (((size_t)(bb * NHEAD + h) * SEQL + s) * DK) + d;
                    if (olo) store_hilo2h(&ohi[idx], &olo[idx], vx, vy);
                    else     store_hi2h(&ohi[idx], vx, vy);
                } else {
                    float2 o2; o2.x = vx; o2.y = vy;
                    *(float2*)&outf[(size_t)m * D_MODEL + col] = o2;
                }
            }
        }
    }
}

// ---------------------------------------------------------------------------
// Tensor-core flash attention, fp16 2-term (unchanged from R11 passing version).
// S = Qhi*Khi + Qlo*Khi ; O += Phi*Vhi + Plo*Vhi.
// ---------------------------------------------------------------------------
#define AT_QHI  0
#define AT_QLO  16384
#define AT_BUF  32768
#define AT_TILE 8192
#define AT_BUFSZ 16384
#define AT_SMEM (AT_BUF + 2 * AT_BUFSZ)  // 65536

__device__ __forceinline__ void attn_load_kv(
    uint32_t dstBase,
    const __half* __restrict__ khi, const __half* __restrict__ vhi,
    int kt, int tid)
{
#pragma unroll
    for (int i = 0; i < 2; i++) {
        const int u = tid + i * 256;          // 0..511
        const int row = u >> 3;               // 0..63
        const int c = u & 7;
        const uint32_t so = sw128((uint32_t)(row * 128 + c * 16));
        const size_t go = (size_t)(kt + row) * DK + c * 8;
        CP16(dstBase + 0 * AT_TILE + so, khi + go);
        CP16(dstBase + 1 * AT_TILE + so, vhi + go);
    }
}

__global__ __launch_bounds__(256, 2) void attn_mma_kernel()
{
    extern __shared__ char sm[];
    const uint32_t sb = smem_u32(sm);
    const int tid  = threadIdx.x;
    const int wid  = tid >> 5;
    const int lane = tid & 31;
    const int qt = blockIdx.x;
    const int h  = blockIdx.y;
    const int b  = blockIdx.z;

    const size_t headOff = (size_t)(b * NHEAD + h) * SEQL * DK;
    const __half* qhig = g_qhi + headOff + (size_t)qt * 128 * DK;
    const __half* qlog = g_qlo + headOff + (size_t)qt * 128 * DK;
    const __half* khig = g_khi + headOff;
    const __half* vhig = g_vhi + headOff;

    {
#pragma unroll
        for (int i = 0; i < 4; i++) {
            const int u = tid + i * 256;
            const int row = u >> 3;
            const int c = u & 7;
            const uint32_t so = sw128((uint32_t)(row * 128 + c * 16));
            const size_t go = (size_t)row * DK + c * 8;
            uint4 vh = *(const uint4*)(qhig + go);
            STS128(sb + AT_QHI + so, vh);
            uint4 vl = *(const uint4*)(qlog + go);
            STS128(sb + AT_QLO + so, vl);
        }
    }
    attn_load_kv(sb + AT_BUF, khig, vhig, 0, tid);
    CP_COMMIT();
    __syncthreads();

    const int r8 = lane & 7;
    const int j8 = lane >> 3;
    const int aRow = wid * 16 + r8 + (j8 & 1) * 8;
    const int aC0  = j8 >> 1;
    uint32_t qh[4][4], ql[4][4];
#pragma unroll
    for (int kk = 0; kk < 4; kk++) {
        const uint32_t so = sw128((uint32_t)(aRow * 128 + (aC0 + 2 * kk) * 16));
        LDSM_X4(qh[kk][0], qh[kk][1], qh[kk][2], qh[kk][3], sb + AT_QHI + so);
        LDSM_X4(ql[kk][0], ql[kk][1], ql[kk][2], ql[kk][3], sb + AT_QLO + so);
    }

    float o[8][4];
#pragma unroll
    for (int nf = 0; nf < 8; nf++)
#pragma unroll
        for (int e = 0; e < 4; e++) o[nf][e] = 0.0f;
    float mrow1 = -CUDART_INF_F, mrow2 = -CUDART_INF_F;
    float lrow1 = 0.0f, lrow2 = 0.0f;

    const int qrow1 = qt * 128 + wid * 16 + (lane >> 2);
    const uint32_t* pk1 = g_pk + ((size_t)b * SEQL + qrow1) * (SEQL / 32);
    const uint32_t* pk2 = pk1 + 8 * (SEQL / 32);

    const int bRow = r8 + (j8 >> 1) * 8;
    const int bC   = j8 & 1;
    const int vRow = lane & 15;
    const int vCh  = lane >> 4;

    for (int it = 0; it < 16; it++) {
        const int cur = it & 1;
        if (it < 15) {
            attn_load_kv(sb + AT_BUF + (cur ^ 1) * AT_BUFSZ,
                         khig, vhig, (it + 1) * 64, tid);
            CP_COMMIT();
            asm volatile("cp.async.wait_group 1;" ::: "memory");
        } else {
            asm volatile("cp.async.wait_group 0;" ::: "memory");
        }
        __syncthreads();

        const uint32_t kb_base = sb + AT_BUF + cur * AT_BUFSZ;

        // ---- S = Q K^T over 64 keys (2-term) ----
        float s[8][4];
#pragma unroll
        for (int nf = 0; nf < 8; nf++)
#pragma unroll
            for (int e = 0; e < 4; e++) s[nf][e] = 0.0f;

#pragma unroll
        for (int kk = 0; kk < 4; kk++) {
            uint32_t kb[8][2];
#pragma unroll
            for (int nf2 = 0; nf2 < 4; nf2++) {
                uint32_t r0, r1, r2, r3;
                LDSM_X4(r0, r1, r2, r3, kb_base + 0 * AT_TILE +
                        sw128((uint32_t)((nf2 * 16 + bRow) * 128 + (bC + 2 * kk) * 16)));
                kb[2 * nf2][0] = r0; kb[2 * nf2][1] = r1;
                kb[2 * nf2 + 1][0] = r2; kb[2 * nf2 + 1][1] = r3;
            }
#pragma unroll
            for (int nf = 0; nf < 8; nf++) MMA_F16(s[nf], qh[kk], kb[nf]);
#pragma unroll
            for (int nf = 0; nf < 8; nf++) MMA_F16(s[nf], ql[kk], kb[nf]);
        }

        // ---- mask + scale (64 keys = 2 mask words per row) ----
        uint2 mwa = *(const uint2*)(pk1 + it * 2);
        uint2 mwb = *(const uint2*)(pk2 + it * 2);
        const uint32_t w1[2] = {mwa.x, mwa.y};
        const uint32_t w2[2] = {mwb.x, mwb.y};
#pragma unroll
        for (int nf = 0; nf < 8; nf++) {
            const uint32_t wa = w1[nf >> 2];
            const uint32_t wb = w2[nf >> 2];
            const int sh = (nf * 8 + (lane & 3) * 2) & 31;
            s[nf][0] = ((wa >> sh) & 1u)       ? s[nf][0] * 0.125f : -1e9f;
            s[nf][1] = ((wa >> (sh + 1)) & 1u) ? s[nf][1] * 0.125f : -1e9f;
            s[nf][2] = ((wb >> sh) & 1u)       ? s[nf][2] * 0.125f : -1e9f;
            s[nf][3] = ((wb >> (sh + 1)) & 1u) ? s[nf][3] * 0.125f : -1e9f;
        }

        // ---- online softmax ----
        float mx1 = -CUDART_INF_F, mx2 = -CUDART_INF_F;
#pragma unroll
        for (int nf = 0; nf < 8; nf++) {
            mx1 = fmaxf(mx1, fmaxf(s[nf][0], s[nf][1]));
            mx2 = fmaxf(mx2, fmaxf(s[nf][2], s[nf][3]));
        }
        mx1 = fmaxf(mx1, __shfl_xor_sync(0xffffffffu, mx1, 1));
        mx1 = fmaxf(mx1, __shfl_xor_sync(0xffffffffu, mx1, 2));
        mx2 = fmaxf(mx2, __shfl_xor_sync(0xffffffffu, mx2, 1));
        mx2 = fmaxf(mx2, __shfl_xor_sync(0xffffffffu, mx2, 2));

        const float mn1 = fmaxf(mrow1, mx1);
        const float mn2 = fmaxf(mrow2, mx2);
        const float c1 = __expf(mrow1 - mn1);
        const float c2 = __expf(mrow2 - mn2);
        mrow1 = mn1; mrow2 = mn2;

        float rs1 = 0.0f, rs2 = 0.0f;
#pragma unroll
        for (int nf = 0; nf < 8; nf++) {
            s[nf][0] = __expf(s[nf][0] - mn1); rs1 += s[nf][0];
            s[nf][1] = __expf(s[nf][1] - mn1); rs1 += s[nf][1];
            s[nf][2] = __expf(s[nf][2] - mn2); rs2 += s[nf][2];
            s[nf][3] = __expf(s[nf][3] - mn2); rs2 += s[nf][3];
        }
        rs1 += __shfl_xor_sync(0xffffffffu, rs1, 1);
        rs1 += __shfl_xor_sync(0xffffffffu, rs1, 2);
        rs2 += __shfl_xor_sync(0xffffffffu, rs2, 1);
        rs2 += __shfl_xor_sync(0xffffffffu, rs2, 2);
        lrow1 = lrow1 * c1 + rs1;
        lrow2 = lrow2 * c2 + rs2;

#pragma unroll
        for (int nf = 0; nf < 8; nf++) {
            o[nf][0] *= c1; o[nf][1] *= c1;
            o[nf][2] *= c2; o[nf][3] *= c2;
        }

        // ---- pack P hi/lo (fp16) ----
        uint32_t phi[8][2], plo[8][2];
#pragma unroll
        for (int nf = 0; nf < 8; nf++) {
            __half h0 = __float2half_rn(s[nf][0]);
            __half h1 = __float2half_rn(s[nf][1]);
            __half h2 = __float2half_rn(s[nf][2]);
            __half h3 = __float2half_rn(s[nf][3]);
            phi[nf][0] = pack_h2(h0, h1);
            phi[nf][1] = pack_h2(h2, h3);
            plo[nf][0] = pack_h2(
                __float2half_rn(s[nf][0] - __half2float(h0)),
                __float2half_rn(s[nf][1] - __half2float(h1)));
            plo[nf][1] = pack_h2(
                __float2half_rn(s[nf][2] - __half2float(h2)),
                __float2half_rn(s[nf][3] - __half2float(h3)));
        }

        // ---- O += P V (2-term); 4 k16 blocks over 64 keys ----
#pragma unroll
        for (int j = 0; j < 4; j++) {
            uint32_t pa_hi[4] = {phi[2 * j][0], phi[2 * j][1],
                                 phi[2 * j + 1][0], phi[2 * j + 1][1]};
            uint32_t pa_lo[4] = {plo[2 * j][0], plo[2 * j][1],
                                 plo[2 * j + 1][0], plo[2 * j + 1][1]};
            uint32_t vb[8][2];
#pragma unroll
            for (int nf2 = 0; nf2 < 4; nf2++) {
                uint32_t r0, r1, r2, r3;
                LDSM_X4T(r0, r1, r2, r3, kb_base + 1 * AT_TILE +
                         sw128((uint32_t)((j * 16 + vRow) * 128 + (nf2 * 2 + vCh) * 16)));
                vb[2 * nf2][0] = r0; vb[2 * nf2][1] = r1;
                vb[2 * nf2 + 1][0] = r2; vb[2 * nf2 + 1][1] = r3;
            }
#pragma unroll
            for (int nf = 0; nf < 8; nf++) MMA_F16(o[nf], pa_hi, vb[nf]);
#pragma unroll
            for (int nf = 0; nf < 8; nf++) MMA_F16(o[nf], pa_lo, vb[nf]);
        }

        __syncthreads();
    }

    const float inv1 = 1.0f / lrow1;
    const float inv2 = 1.0f / lrow2;
    const size_t rowg1 = (size_t)b * SEQL + qt * 128 + wid * 16 + (lane >> 2);
    const size_t rowg2 = rowg1 + 8;
#pragma unroll
    for (int nf = 0; nf < 8; nf++) {
        const int col = h * 64 + nf * 8 + (lane & 3) * 2;
        store_hilo2h(&g_xhi[rowg1 * D_MODEL + col], &g_xlo[rowg1 * D_MODEL + col],
                     o[nf][0] * inv1, o[nf][1] * inv1);
        store_hilo2h(&g_xhi[rowg2 * D_MODEL + col], &g_xlo[rowg2 * D_MODEL + col],
                     o[nf][2] * inv2, o[nf][3] * inv2);
    }
}

// ---------------------------------------------------------------------------
// Host launcher
// ---------------------------------------------------------------------------
extern "C" void kernel_launch(void* const* d_in, const int* in_sizes, int n_in,
                              void* d_out, int out_size)
{
    (void)in_sizes; (void)n_in; (void)out_size;

    const float* q    = (const float*)d_in[0];
    const float* k    = (const float*)d_in[1];
    const float* v    = (const float*)d_in[2];
    const int*   mask = (const int*)  d_in[3];
    const float* Wq   = (const float*)d_in[4];
    const float* bq   = (const float*)d_in[5];
    const float* Wk   = (const float*)d_in[6];
    const float* bk   = (const float*)d_in[7];
    const float* Wv   = (const float*)d_in[8];
    const float* bv   = (const float*)d_in[9];
    const float* Wo   = (const float*)d_in[10];
    const float* bo   = (const float*)d_in[11];
    float* out = (float*)d_out;

    void* p;
    cudaGetSymbolAddress(&p, g_qhi); __half* qhi = (__half*)p;
    cudaGetSymbolAddress(&p, g_qlo); __half* qlo = (__half*)p;
    cudaGetSymbolAddress(&p, g_khi); __half* khi = (__half*)p;
    cudaGetSymbolAddress(&p, g_vhi); __half* vhi = (__half*)p;
    cudaGetSymbolAddress(&p, g_xhi); __half* xhi = (__half*)p;
    cudaGetSymbolAddress(&p, g_xlo); __half* xlo = (__half*)p;
    cudaGetSymbolAddress(&p, g_whi); __half* whi = (__half*)p;

    const int SMEM2 = 3 * 24576;   // 73728
    const int SMEM1 = 3 * 16384;   // 49152
    cudaFuncSetAttribute(attn_mma_kernel,
                         cudaFuncAttributeMaxDynamicSharedMemorySize, AT_SMEM);
    cudaFuncSetAttribute(gemm_f16_kernel<1>,
                         cudaFuncAttributeMaxDynamicSharedMemorySize, SMEM2);
    cudaFuncSetAttribute(gemm_f16_kernel<0>,
                         cudaFuncAttributeMaxDynamicSharedMemorySize, SMEM1);

    const int n4 = MROWS * D_MODEL / 4;
    const dim3 ggemm(D_MODEL / 128, MROWS / 128);   // (8, 64)
    const dim3 gtr(D_MODEL / 32, D_MODEL / 32, 4);  // (32, 32, 4)
    const dim3 gsplit((n4 + 255) / 256, 3);

    pack_mask_kernel<<<MROWS / 8, 256>>>(mask);
    split_hilo3_kernel<<<gsplit, 256>>>(q, k, v, n4);
    split_transpose4_kernel<<<gtr, 256>>>(Wq, Wk, Wv, Wo);

    // Q projection: 1-term (softmax-dampened), output hi+lo for exact-ish S
    gemm_f16_kernel<0><<<ggemm, 256, SMEM1>>>(
        xhi + 0 * XSLICE, nullptr, whi + 0 * WSLICE,
        bq, nullptr, qhi, qlo, 1);
    // K projection: 1-term (softmax-dampened), hi only
    gemm_f16_kernel<0><<<ggemm, 256, SMEM1>>>(
        xhi + 1 * XSLICE, nullptr, whi + 1 * WSLICE,
        bk, nullptr, khi, nullptr, 1);
    // V projection: 2-term (direct path to output), hi only
    gemm_f16_kernel<1><<<ggemm, 256, SMEM2>>>(
        xhi + 2 * XSLICE, xlo + 2 * XSLICE, whi + 2 * WSLICE,
        bv, nullptr, vhi, nullptr, 1);

    // Attention (writes hi/lo concat into xhi/xlo slice 0)
    attn_mma_kernel<<<dim3(SEQL / 128, NHEAD, BSZ), 256, AT_SMEM>>>();

    // Output projection: 2-term (direct path), fp32 -> d_out
    gemm_f16_kernel<1><<<ggemm, 256, SMEM2>>>(
        xhi + 0 * XSLICE, xlo + 0 * XSLICE, whi + 3 * WSLICE,
        bo, out, nullptr, nullptr, 0);
}

// round 13
// speedup vs baseline: 5.0791x; 1.1349x over previous
#include <cuda_runtime.h>
#include <cuda_fp16.h>
#include <math_constants.h>
#include <cstdint>

// Problem constants
#define D_MODEL 1024
#define NHEAD   16
#define DK      64
#define BSZ     8
#define SEQL    1024
#define MROWS   (BSZ * SEQL)   // 8192

#define XSLICE ((size_t)MROWS * D_MODEL)
#define WSLICE ((size_t)D_MODEL * D_MODEL)

// ---------------------------------------------------------------------------
// Scratch (allocation-free: __device__ globals)
// Precision plan (error budget vs 1e-3):
//   Q,K proj + S + P: fp16 single-term (softmax-dampened paths)
//   V proj, O proj:   fp16 2-term (direct paths to output)
// ---------------------------------------------------------------------------
__device__ __align__(16) __half g_qhi[(size_t)BSZ * NHEAD * SEQL * DK];
__device__ __align__(16) __half g_khi[(size_t)BSZ * NHEAD * SEQL * DK];
__device__ __align__(16) __half g_vhi[(size_t)BSZ * NHEAD * SEQL * DK];
__device__ __align__(16) __half g_xhi[3 * XSLICE];  // q/k/v input splits; slice 0 reused by attn output
__device__ __align__(16) __half g_xlo[3 * XSLICE];
__device__ __align__(16) __half g_whi[4 * WSLICE];  // Wq/Wk/Wv/Wo transposed [N,K]
__device__ __align__(16) uint32_t g_pk[(size_t)BSZ * SEQL * (SEQL / 32)]; // packed mask

// ---------------------------------------------------------------------------
// PTX helpers (standard PTX only — tcgen05 is rejected by the sm_103 target)
// ---------------------------------------------------------------------------
__device__ __forceinline__ uint32_t smem_u32(const void* p) {
    uint32_t a;
    asm("{ .reg .u64 t; cvta.to.shared.u64 t, %1; cvt.u32.u64 %0, t; }"
        : "=r"(a) : "l"(p));
    return a;
}

#define LDSM_X4(r0, r1, r2, r3, addr) \
    asm volatile("ldmatrix.sync.aligned.m8n8.x4.shared.b16 {%0,%1,%2,%3}, [%4];" \
                 : "=r"(r0), "=r"(r1), "=r"(r2), "=r"(r3) : "r"(addr))

#define LDSM_X4T(r0, r1, r2, r3, addr) \
    asm volatile("ldmatrix.sync.aligned.m8n8.x4.trans.shared.b16 {%0,%1,%2,%3}, [%4];" \
                 : "=r"(r0), "=r"(r1), "=r"(r2), "=r"(r3) : "r"(addr))

#define MMA_F16(d, a, b) \
    asm("mma.sync.aligned.m16n8k16.row.col.f32.f16.f16.f32 " \
        "{%0,%1,%2,%3}, {%4,%5,%6,%7}, {%8,%9}, {%0,%1,%2,%3};" \
        : "+f"((d)[0]), "+f"((d)[1]), "+f"((d)[2]), "+f"((d)[3]) \
        : "r"((a)[0]), "r"((a)[1]), "r"((a)[2]), "r"((a)[3]), \
          "r"((b)[0]), "r"((b)[1]))

#define STS128(addr, v) \
    asm volatile("st.shared.v4.b32 [%0], {%1,%2,%3,%4};" \
                 :: "r"(addr), "r"((v).x), "r"((v).y), "r"((v).z), "r"((v).w) \
                 : "memory")

#define CP16(smem_addr, gptr) \
    asm volatile("cp.async.cg.shared.global [%0], [%1], 16;" \
                 :: "r"(smem_addr), "l"(gptr) : "memory")
#define CP_COMMIT() asm volatile("cp.async.commit_group;" ::: "memory")

// 64B-row swizzle (GEMM tiles)
__device__ __forceinline__ uint32_t swz(int row, int c) {
    return (uint32_t)((row << 6) + (((c ^ (row >> 1)) & 3) << 4));
}
// SW128 swizzle for 128B rows (attention tiles)
__device__ __forceinline__ uint32_t sw128(uint32_t off) {
    return off ^ ((off >> 3) & 0x70);
}

__device__ __forceinline__ uint32_t pack_h2(__half lo16, __half hi16) {
    return ((uint32_t)*(const uint16_t*)&hi16 << 16) | *(const uint16_t*)&lo16;
}

// split fp32 pair into fp16 hi / lo pairs and store as packed u32
__device__ __forceinline__ void store_hilo2h(__half* hi, __half* lo,
                                             float a, float b) {
    __half ha = __float2half_rn(a), hb = __float2half_rn(b);
    *(uint32_t*)hi = pack_h2(ha, hb);
    __half la = __float2half_rn(a - __half2float(ha));
    __half lb = __float2half_rn(b - __half2float(hb));
    *(uint32_t*)lo = pack_h2(la, lb);
}

__device__ __forceinline__ void store_hi2h(__half* hi, float a, float b) {
    *(uint32_t*)hi = pack_h2(__float2half_rn(a), __float2half_rn(b));
}

// ---------------------------------------------------------------------------
// fp32 -> (hi,lo) fp16 split for q,k,v in ONE launch (grid.y selects input)
// ---------------------------------------------------------------------------
__global__ void split_hilo3_kernel(const float* __restrict__ q,
                                   const float* __restrict__ k,
                                   const float* __restrict__ v, int n4)
{
    const int z = blockIdx.y;
    const float* x = (z == 0) ? q : (z == 1) ? k : v;
    __half* hi = g_xhi + (size_t)z * XSLICE;
    __half* lo = g_xlo + (size_t)z * XSLICE;

    int i = blockIdx.x * blockDim.x + threadIdx.x;
    if (i >= n4) return;
    float4 val = ((const float4*)x)[i];
    __half h[4], l[4];
    float f[4] = {val.x, val.y, val.z, val.w};
#pragma unroll
    for (int j = 0; j < 4; j++) {
        h[j] = __float2half_rn(f[j]);
        l[j] = __float2half_rn(f[j] - __half2float(h[j]));
    }
    ((uint2*)hi)[i] = *(uint2*)h;
    ((uint2*)lo)[i] = *(uint2*)l;
}

// ---------------------------------------------------------------------------
// All four W [K,N] fp32 -> Wt hi [N,K] fp16 in ONE launch (grid.z selects W)
// ---------------------------------------------------------------------------
__global__ void split_transpose4_kernel(const float* __restrict__ W0,
                                        const float* __restrict__ W1,
                                        const float* __restrict__ W2,
                                        const float* __restrict__ W3)
{
    const int z = blockIdx.z;
    const float* W = (z == 0) ? W0 : (z == 1) ? W1 : (z == 2) ? W2 : W3;
    __half* hi = g_whi + (size_t)z * WSLICE;

    __shared__ float t[32][33];
    const int kb = blockIdx.y * 32;
    const int nb = blockIdx.x * 32;
    const int tx = threadIdx.x & 31;
    const int ty = threadIdx.x >> 5;
#pragma unroll
    for (int j = 0; j < 4; j++)
        t[ty + 8 * j][tx] = W[(size_t)(kb + ty + 8 * j) * D_MODEL + nb + tx];
    __syncthreads();
#pragma unroll
    for (int j = 0; j < 4; j++) {
        float v = t[tx][ty + 8 * j];
        hi[(size_t)(nb + ty + 8 * j) * D_MODEL + kb + tx] = __float2half_rn(v);
    }
}

// ---------------------------------------------------------------------------
// Pack mask [B,S,S] int32 -> bitmask [B,S,S/32]
// ---------------------------------------------------------------------------
__global__ void pack_mask_kernel(const int* __restrict__ mask)
{
    const int warp = (blockIdx.x * blockDim.x + threadIdx.x) >> 5;  // 0..8191
    const int lane = threadIdx.x & 31;
    const int* src = mask + (size_t)warp * SEQL;
    uint32_t* dst = g_pk + (size_t)warp * (SEQL / 32);
#pragma unroll 4
    for (int w = 0; w < 32; w++) {
        int v = src[w * 32 + lane];
        uint32_t bits = __ballot_sync(0xffffffffu, v != 0);
        if (lane == 0) dst[w] = bits;
    }
}

// ---------------------------------------------------------------------------
// fp16 GEMM via mma.sync: C = X*W + bias, fp32 acc.
// TWO=1: C = Ahi*Bhi + Alo*Bhi (A exact to 2^-22).  TWO=0: C = Ahi*Bhi.
// 3-stage cp.async circular pipeline, one __syncthreads per 32-wide K chunk.
// CTA 128x128, warp tile 32x64. mode 0: fp32 out; mode 1: fp16 head-split.
// ---------------------------------------------------------------------------
template <int TWO>
__global__ __launch_bounds__(256, 2)
void gemm_f16_kernel(const __half* __restrict__ Ahi,
                     const __half* __restrict__ Alo,
                     const __half* __restrict__ Bhi,
                     const float* __restrict__ bias,
                     float* __restrict__ outf,
                     __half* __restrict__ ohi, int mode)
{
    constexpr uint32_t ST_AHI  = 0;
    constexpr uint32_t ST_ALO  = 8192;                 // valid only if TWO
    constexpr uint32_t ST_BHI  = TWO ? 16384 : 8192;
    constexpr uint32_t ST_SIZE = TWO ? 24576 : 16384;

    extern __shared__ __align__(1024) char smem[];
    const uint32_t smem_base = smem_u32(smem);

    const int tid   = threadIdx.x;
    const int wid   = tid >> 5;
    const int lane  = tid & 31;
    const int warpM = wid & 3;
    const int warpN = wid >> 2;
    const int mBase = blockIdx.y * 128;
    const int nBase = blockIdx.x * 128;

    const int j8 = lane >> 3;
    const int r8 = lane & 7;
    const int aR = warpM * 32 + r8 + (j8 & 1) * 8;
    const int aC = (j8 >> 1);
    const int bR = warpN * 64 + r8 + (j8 >> 1) * 8;
    const int bC = (j8 & 1);

    const int gRow0 = tid >> 2;   // 0..63
    const int gC    = tid & 3;    // 16B chunk within 64B row

    float acc[2][8][4];
#pragma unroll
    for (int mf = 0; mf < 2; mf++)
#pragma unroll
        for (int nf = 0; nf < 8; nf++)
#pragma unroll
            for (int e = 0; e < 4; e++) acc[mf][nf][e] = 0.0f;

    const __half* Apg = Ahi + (size_t)mBase * D_MODEL;
    const __half* Alg = TWO ? (Alo + (size_t)mBase * D_MODEL) : nullptr;
    const __half* Bpg = Bhi + (size_t)nBase * D_MODEL;

    auto load_chunk = [&](int k0, uint32_t stage) {
#pragma unroll
        for (int i = 0; i < 2; i++) {
            const int row = gRow0 + i * 64;
            const uint32_t off = swz(row, gC);
            const size_t goA = (size_t)row * D_MODEL + k0 + gC * 8;
            CP16(stage + ST_AHI + off, Apg + goA);
            if (TWO) CP16(stage + ST_ALO + off, Alg + goA);
            CP16(stage + ST_BHI + off, Bpg + goA);
        }
    };

    const int NCHUNK = D_MODEL / 32;  // 32

    load_chunk(0, smem_base + 0 * ST_SIZE);
    CP_COMMIT();
    load_chunk(32, smem_base + 1 * ST_SIZE);
    CP_COMMIT();

    for (int it = 0; it < NCHUNK; it++) {
        if (it + 1 < NCHUNK) {
            asm volatile("cp.async.wait_group 1;" ::: "memory");
        } else {
            asm volatile("cp.async.wait_group 0;" ::: "memory");
        }
        __syncthreads();

        if (it + 2 < NCHUNK) {
            load_chunk((it + 2) * 32, smem_base + ((it + 2) % 3) * ST_SIZE);
            CP_COMMIT();
        }

        const uint32_t st = smem_base + (it % 3) * ST_SIZE;

#pragma unroll
        for (int kk = 0; kk < 2; kk++) {
            uint32_t afh[2][4], afl[2][4];
#pragma unroll
            for (int mf = 0; mf < 2; mf++) {
                const int row = aR + mf * 16;
                const uint32_t off = swz(row, aC + 2 * kk);
                LDSM_X4(afh[mf][0], afh[mf][1], afh[mf][2], afh[mf][3],
                        st + ST_AHI + off);
                if (TWO)
                    LDSM_X4(afl[mf][0], afl[mf][1], afl[mf][2], afl[mf][3],
                            st + ST_ALO + off);
            }
#pragma unroll
            for (int nf2 = 0; nf2 < 4; nf2++) {
                const int row = bR + nf2 * 16;
                const uint32_t off = swz(row, bC + 2 * kk);
                uint32_t h0, h1, h2, h3;
                LDSM_X4(h0, h1, h2, h3, st + ST_BHI + off);
                uint32_t bh0[2] = {h0, h1}, bh1[2] = {h2, h3};
                MMA_F16(acc[0][2 * nf2],     afh[0], bh0);
                MMA_F16(acc[0][2 * nf2 + 1], afh[0], bh1);
                MMA_F16(acc[1][2 * nf2],     afh[1], bh0);
                MMA_F16(acc[1][2 * nf2 + 1], afh[1], bh1);
                if (TWO) {
                    MMA_F16(acc[0][2 * nf2],     afl[0], bh0);
                    MMA_F16(acc[0][2 * nf2 + 1], afl[0], bh1);
                    MMA_F16(acc[1][2 * nf2],     afl[1], bh0);
                    MMA_F16(acc[1][2 * nf2 + 1], afl[1], bh1);
                }
            }
        }
    }

#pragma unroll
    for (int mf = 0; mf < 2; mf++) {
#pragma unroll
        for (int nf = 0; nf < 8; nf++) {
            const int col = nBase + warpN * 64 + nf * 8 + (lane & 3) * 2;
            const float b0 = bias[col];
            const float b1 = bias[col + 1];
#pragma unroll
            for (int half = 0; half < 2; half++) {
                const int m = mBase + warpM * 32 + mf * 16 + (lane >> 2) + half * 8;
                const float vx = acc[mf][nf][half * 2 + 0] + b0;
                const float vy = acc[mf][nf][half * 2 + 1] + b1;
                if (mode) {
                    const int bb = m >> 10;
                    const int s  = m & 1023;
                    const int h  = col >> 6;
                    const int d  = col & 63;
                    const size_t idx = (((size_t)(bb * NHEAD + h) * SEQL + s) * DK) + d;
                    store_hi2h(&ohi[idx], vx, vy);
                } else {
                    float2 o2; o2.x = vx; o2.y = vy;
                    *(float2*)&outf[(size_t)m * D_MODEL + col] = o2;
                }
            }
        }
    }
}

// ---------------------------------------------------------------------------
// Tensor-core flash attention, fp16 single-term (softmax-dampened paths):
// S = Qhi*Khi ; O += Phi*Vhi.  Output written as hi/lo split (2-term O-proj).
// 64-key KV tiles; smem: Q hi 16KB + double-buffered K/V hi (16KB/stage)
// = 48KB -> 2 CTAs/SM.
// ---------------------------------------------------------------------------
#define AT_QHI  0
#define AT_BUF  16384
#define AT_TILE 8192
#define AT_BUFSZ 16384
#define AT_SMEM (AT_BUF + 2 * AT_BUFSZ)  // 49152

__device__ __forceinline__ void attn_load_kv(
    uint32_t dstBase,
    const __half* __restrict__ khi, const __half* __restrict__ vhi,
    int kt, int tid)
{
#pragma unroll
    for (int i = 0; i < 2; i++) {
        const int u = tid + i * 256;          // 0..511
        const int row = u >> 3;               // 0..63
        const int c = u & 7;
        const uint32_t so = sw128((uint32_t)(row * 128 + c * 16));
        const size_t go = (size_t)(kt + row) * DK + c * 8;
        CP16(dstBase + 0 * AT_TILE + so, khi + go);
        CP16(dstBase + 1 * AT_TILE + so, vhi + go);
    }
}

__global__ __launch_bounds__(256, 2) void attn_mma_kernel()
{
    extern __shared__ char sm[];
    const uint32_t sb = smem_u32(sm);
    const int tid  = threadIdx.x;
    const int wid  = tid >> 5;
    const int lane = tid & 31;
    const int qt = blockIdx.x;
    const int h  = blockIdx.y;
    const int b  = blockIdx.z;

    const size_t headOff = (size_t)(b * NHEAD + h) * SEQL * DK;
    const __half* qhig = g_qhi + headOff + (size_t)qt * 128 * DK;
    const __half* khig = g_khi + headOff;
    const __half* vhig = g_vhi + headOff;

    {
#pragma unroll
        for (int i = 0; i < 2; i++) {
            const int u = tid + i * 256;
            const int row = u >> 2;           // 0..127 (two 16B chunks/thread pass)
            const int c = u & 3;
            // Q tile: 128 rows x 128B; 1024 16B units; 512 threads-units/pass
            const int row2 = u >> 3;
            const int c2 = u & 7;
            (void)row; (void)c;
            const uint32_t so = sw128((uint32_t)(row2 * 128 + c2 * 16));
            const size_t go = (size_t)row2 * DK + c2 * 8;
            uint4 vh = *(const uint4*)(qhig + go);
            STS128(sb + AT_QHI + so, vh);
        }
        // remaining half of Q tile
#pragma unroll
        for (int i = 2; i < 4; i++) {
            const int u = tid + i * 256;
            const int row2 = u >> 3;
            const int c2 = u & 7;
            const uint32_t so = sw128((uint32_t)(row2 * 128 + c2 * 16));
            const size_t go = (size_t)row2 * DK + c2 * 8;
            uint4 vh = *(const uint4*)(qhig + go);
            STS128(sb + AT_QHI + so, vh);
        }
    }
    attn_load_kv(sb + AT_BUF, khig, vhig, 0, tid);
    CP_COMMIT();
    __syncthreads();

    const int r8 = lane & 7;
    const int j8 = lane >> 3;
    const int aRow = wid * 16 + r8 + (j8 & 1) * 8;
    const int aC0  = j8 >> 1;
    uint32_t qh[4][4];
#pragma unroll
    for (int kk = 0; kk < 4; kk++) {
        const uint32_t so = sw128((uint32_t)(aRow * 128 + (aC0 + 2 * kk) * 16));
        LDSM_X4(qh[kk][0], qh[kk][1], qh[kk][2], qh[kk][3], sb + AT_QHI + so);
    }

    float o[8][4];
#pragma unroll
    for (int nf = 0; nf < 8; nf++)
#pragma unroll
        for (int e = 0; e < 4; e++) o[nf][e] = 0.0f;
    float mrow1 = -CUDART_INF_F, mrow2 = -CUDART_INF_F;
    float lrow1 = 0.0f, lrow2 = 0.0f;

    const int qrow1 = qt * 128 + wid * 16 + (lane >> 2);
    const uint32_t* pk1 = g_pk + ((size_t)b * SEQL + qrow1) * (SEQL / 32);
    const uint32_t* pk2 = pk1 + 8 * (SEQL / 32);

    const int bRow = r8 + (j8 >> 1) * 8;
    const int bC   = j8 & 1;
    const int vRow = lane & 15;
    const int vCh  = lane >> 4;

    for (int it = 0; it < 16; it++) {
        const int cur = it & 1;
        if (it < 15) {
            attn_load_kv(sb + AT_BUF + (cur ^ 1) * AT_BUFSZ,
                         khig, vhig, (it + 1) * 64, tid);
            CP_COMMIT();
            asm volatile("cp.async.wait_group 1;" ::: "memory");
        } else {
            asm volatile("cp.async.wait_group 0;" ::: "memory");
        }
        __syncthreads();

        const uint32_t kb_base = sb + AT_BUF + cur * AT_BUFSZ;

        // ---- S = Qhi Khi^T over 64 keys (1-term) ----
        float s[8][4];
#pragma unroll
        for (int nf = 0; nf < 8; nf++)
#pragma unroll
            for (int e = 0; e < 4; e++) s[nf][e] = 0.0f;

#pragma unroll
        for (int kk = 0; kk < 4; kk++) {
            uint32_t kb[8][2];
#pragma unroll
            for (int nf2 = 0; nf2 < 4; nf2++) {
                uint32_t r0, r1, r2, r3;
                LDSM_X4(r0, r1, r2, r3, kb_base + 0 * AT_TILE +
                        sw128((uint32_t)((nf2 * 16 + bRow) * 128 + (bC + 2 * kk) * 16)));
                kb[2 * nf2][0] = r0; kb[2 * nf2][1] = r1;
                kb[2 * nf2 + 1][0] = r2; kb[2 * nf2 + 1][1] = r3;
            }
#pragma unroll
            for (int nf = 0; nf < 8; nf++) MMA_F16(s[nf], qh[kk], kb[nf]);
        }

        // ---- mask + scale (64 keys = 2 mask words per row) ----
        uint2 mwa = *(const uint2*)(pk1 + it * 2);
        uint2 mwb = *(const uint2*)(pk2 + it * 2);
        const uint32_t w1[2] = {mwa.x, mwa.y};
        const uint32_t w2[2] = {mwb.x, mwb.y};
#pragma unroll
        for (int nf = 0; nf < 8; nf++) {
            const uint32_t wa = w1[nf >> 2];
            const uint32_t wb = w2[nf >> 2];
            const int sh = (nf * 8 + (lane & 3) * 2) & 31;
            s[nf][0] = ((wa >> sh) & 1u)       ? s[nf][0] * 0.125f : -1e9f;
            s[nf][1] = ((wa >> (sh + 1)) & 1u) ? s[nf][1] * 0.125f : -1e9f;
            s[nf][2] = ((wb >> sh) & 1u)       ? s[nf][2] * 0.125f : -1e9f;
            s[nf][3] = ((wb >> (sh + 1)) & 1u) ? s[nf][3] * 0.125f : -1e9f;
        }

        // ---- online softmax ----
        float mx1 = -CUDART_INF_F, mx2 = -CUDART_INF_F;
#pragma unroll
        for (int nf = 0; nf < 8; nf++) {
            mx1 = fmaxf(mx1, fmaxf(s[nf][0], s[nf][1]));
            mx2 = fmaxf(mx2, fmaxf(s[nf][2], s[nf][3]));
        }
        mx1 = fmaxf(mx1, __shfl_xor_sync(0xffffffffu, mx1, 1));
        mx1 = fmaxf(mx1, __shfl_xor_sync(0xffffffffu, mx1, 2));
        mx2 = fmaxf(mx2, __shfl_xor_sync(0xffffffffu, mx2, 1));
        mx2 = fmaxf(mx2, __shfl_xor_sync(0xffffffffu, mx2, 2));

        const float mn1 = fmaxf(mrow1, mx1);
        const float mn2 = fmaxf(mrow2, mx2);
        const float c1 = __expf(mrow1 - mn1);
        const float c2 = __expf(mrow2 - mn2);
        mrow1 = mn1; mrow2 = mn2;

        float rs1 = 0.0f, rs2 = 0.0f;
#pragma unroll
        for (int nf = 0; nf < 8; nf++) {
            s[nf][0] = __expf(s[nf][0] - mn1); rs1 += s[nf][0];
            s[nf][1] = __expf(s[nf][1] - mn1); rs1 += s[nf][1];
            s[nf][2] = __expf(s[nf][2] - mn2); rs2 += s[nf][2];
            s[nf][3] = __expf(s[nf][3] - mn2); rs2 += s[nf][3];
        }
        rs1 += __shfl_xor_sync(0xffffffffu, rs1, 1);
        rs1 += __shfl_xor_sync(0xffffffffu, rs1, 2);
        rs2 += __shfl_xor_sync(0xffffffffu, rs2, 1);
        rs2 += __shfl_xor_sync(0xffffffffu, rs2, 2);
        lrow1 = lrow1 * c1 + rs1;
        lrow2 = lrow2 * c2 + rs2;

#pragma unroll
        for (int nf = 0; nf < 8; nf++) {
            o[nf][0] *= c1; o[nf][1] *= c1;
            o[nf][2] *= c2; o[nf][3] *= c2;
        }

        // ---- pack P (fp16, hi only) ----
        uint32_t phi[8][2];
#pragma unroll
        for (int nf = 0; nf < 8; nf++) {
            phi[nf][0] = pack_h2(__float2half_rn(s[nf][0]), __float2half_rn(s[nf][1]));
            phi[nf][1] = pack_h2(__float2half_rn(s[nf][2]), __float2half_rn(s[nf][3]));
        }

        // ---- O += P V (1-term); 4 k16 blocks over 64 keys ----
#pragma unroll
        for (int j = 0; j < 4; j++) {
            uint32_t pa_hi[4] = {phi[2 * j][0], phi[2 * j][1],
                                 phi[2 * j + 1][0], phi[2 * j + 1][1]};
            uint32_t vb[8][2];
#pragma unroll
            for (int nf2 = 0; nf2 < 4; nf2++) {
                uint32_t r0, r1, r2, r3;
                LDSM_X4T(r0, r1, r2, r3, kb_base + 1 * AT_TILE +
                         sw128((uint32_t)((j * 16 + vRow) * 128 + (nf2 * 2 + vCh) * 16)));
                vb[2 * nf2][0] = r0; vb[2 * nf2][1] = r1;
                vb[2 * nf2 + 1][0] = r2; vb[2 * nf2 + 1][1] = r3;
            }
#pragma unroll
            for (int nf = 0; nf < 8; nf++) MMA_F16(o[nf], pa_hi, vb[nf]);
        }

        __syncthreads();
    }

    const float inv1 = 1.0f / lrow1;
    const float inv2 = 1.0f / lrow2;
    const size_t rowg1 = (size_t)b * SEQL + qt * 128 + wid * 16 + (lane >> 2);
    const size_t rowg2 = rowg1 + 8;
#pragma unroll
    for (int nf = 0; nf < 8; nf++) {
        const int col = h * 64 + nf * 8 + (lane & 3) * 2;
        store_hilo2h(&g_xhi[rowg1 * D_MODEL + col], &g_xlo[rowg1 * D_MODEL + col],
                     o[nf][0] * inv1, o[nf][1] * inv1);
        store_hilo2h(&g_xhi[rowg2 * D_MODEL + col], &g_xlo[rowg2 * D_MODEL + col],
                     o[nf][2] * inv2, o[nf][3] * inv2);
    }
}

// ---------------------------------------------------------------------------
// Host launcher
// ---------------------------------------------------------------------------
extern "C" void kernel_launch(void* const* d_in, const int* in_sizes, int n_in,
                              void* d_out, int out_size)
{
    (void)in_sizes; (void)n_in; (void)out_size;

    const float* q    = (const float*)d_in[0];
    const float* k    = (const float*)d_in[1];
    const float* v    = (const float*)d_in[2];
    const int*   mask = (const int*)  d_in[3];
    const float* Wq   = (const float*)d_in[4];
    const float* bq   = (const float*)d_in[5];
    const float* Wk   = (const float*)d_in[6];
    const float* bk   = (const float*)d_in[7];
    const float* Wv   = (const float*)d_in[8];
    const float* bv   = (const float*)d_in[9];
    const float* Wo   = (const float*)d_in[10];
    const float* bo   = (const float*)d_in[11];
    float* out = (float*)d_out;

    void* p;
    cudaGetSymbolAddress(&p, g_qhi); __half* qhi = (__half*)p;
    cudaGetSymbolAddress(&p, g_khi); __half* khi = (__half*)p;
    cudaGetSymbolAddress(&p, g_vhi); __half* vhi = (__half*)p;
    cudaGetSymbolAddress(&p, g_xhi); __half* xhi = (__half*)p;
    cudaGetSymbolAddress(&p, g_xlo); __half* xlo = (__half*)p;
    cudaGetSymbolAddress(&p, g_whi); __half* whi = (__half*)p;

    const int SMEM2 = 3 * 24576;   // 73728
    const int SMEM1 = 3 * 16384;   // 49152
    cudaFuncSetAttribute(attn_mma_kernel,
                         cudaFuncAttributeMaxDynamicSharedMemorySize, AT_SMEM);
    cudaFuncSetAttribute(gemm_f16_kernel<1>,
                         cudaFuncAttributeMaxDynamicSharedMemorySize, SMEM2);
    cudaFuncSetAttribute(gemm_f16_kernel<0>,
                         cudaFuncAttributeMaxDynamicSharedMemorySize, SMEM1);

    const int n4 = MROWS * D_MODEL / 4;
    const dim3 ggemm(D_MODEL / 128, MROWS / 128);   // (8, 64)
    const dim3 gtr(D_MODEL / 32, D_MODEL / 32, 4);  // (32, 32, 4)
    const dim3 gsplit((n4 + 255) / 256, 3);

    pack_mask_kernel<<<MROWS / 8, 256>>>(mask);
    split_hilo3_kernel<<<gsplit, 256>>>(q, k, v, n4);
    split_transpose4_kernel<<<gtr, 256>>>(Wq, Wk, Wv, Wo);

    // Q projection: 1-term, hi only (S is single-term now)
    gemm_f16_kernel<0><<<ggemm, 256, SMEM1>>>(
        xhi + 0 * XSLICE, nullptr, whi + 0 * WSLICE,
        bq, nullptr, qhi, 1);
    // K projection: 1-term, hi only
    gemm_f16_kernel<0><<<ggemm, 256, SMEM1>>>(
        xhi + 1 * XSLICE, nullptr, whi + 1 * WSLICE,
        bk, nullptr, khi, 1);
    // V projection: 2-term (direct path to output), hi only
    gemm_f16_kernel<1><<<ggemm, 256, SMEM2>>>(
        xhi + 2 * XSLICE, xlo + 2 * XSLICE, whi + 2 * WSLICE,
        bv, nullptr, vhi, 1);

    // Attention (writes hi/lo concat into xhi/xlo slice 0)
    attn_mma_kernel<<<dim3(SEQL / 128, NHEAD, BSZ), 256, AT_SMEM>>>();

    // Output projection: 2-term (direct path), fp32 -> d_out
    gemm_f16_kernel<1><<<ggemm, 256, SMEM2>>>(
        xhi + 0 * XSLICE, xlo + 0 * XSLICE, whi + 3 * WSLICE,
        bo, out, nullptr, 0);
}